// round 4
// baseline (speedup 1.0000x reference)
#include <cuda_runtime.h>
#include <cuda_bf16.h>

// ---------------- problem constants ----------------
#define B 64
#define EPG 512
#define E_TOT (B * EPG)        // 32768
#define NODE_DIM 64
#define EDGE_DIM 32
#define HID 128
#define HEADS 8
#define DH 16
#define FEAT_DIM 160           // 2*64 + 32

// ---------------- scratch (device globals; no allocs allowed) ----------------
__device__ float g_h[E_TOT * HID];
__device__ float g_q[E_TOT * HID];
__device__ float g_k[E_TOT * HID];
__device__ float g_v[E_TOT * HID];
__device__ float g_a[E_TOT * HID];
__device__ float g_t[E_TOT * HID];
__device__ float g_feat[E_TOT * FEAT_DIM];
__device__ unsigned g_mask[B * EPG * 16];   // 512 bits per (graph,row)
__device__ float g_qpool[HID];
__device__ float g_pool[B * HID];
__device__ float g_pool2[B * HID];

// ---------------- gather edge features ----------------
__global__ void gather_feat_kernel(const float* __restrict__ x,
                                   const float* __restrict__ ea,
                                   const int* __restrict__ ei,
                                   float* __restrict__ feat) {
    int e = blockIdx.x;
    int c = threadIdx.x;            // 160 threads
    int s = ei[e];
    int d = ei[E_TOT + e];
    float val;
    if (c < 64)       val = x[(size_t)s * NODE_DIM + c];
    else if (c < 128) val = x[(size_t)d * NODE_DIM + (c - 64)];
    else              val = ea[(size_t)e * EDGE_DIM + (c - 128)];
    feat[(size_t)e * FEAT_DIM + c] = val;
}

// ---------------- adjacency bitmask (edges sharing a node) ----------------
__global__ void build_mask_kernel(const int* __restrict__ ei,
                                  unsigned* __restrict__ mask) {
    int b = blockIdx.x;
    __shared__ int ss[EPG];
    __shared__ int dd[EPG];
    for (int i = threadIdx.x; i < EPG; i += blockDim.x) {
        ss[i] = ei[b * EPG + i];
        dd[i] = ei[E_TOT + b * EPG + i];
    }
    __syncthreads();
    for (int i = threadIdx.x; i < EPG; i += blockDim.x) {
        int si = ss[i], di = dd[i];
        for (int w = 0; w < 16; w++) {
            unsigned bits = 0;
            #pragma unroll
            for (int jj = 0; jj < 32; jj++) {
                int j = (w << 5) + jj;
                int sj = ss[j], dj = dd[j];
                bool adj = (si == sj) | (si == dj) | (di == sj) | (di == dj) | (i == j);
                bits |= (unsigned)adj << jj;
            }
            mask[((size_t)b * EPG + i) * 16 + w] = bits;
        }
    }
}

// ---------------- tf32 helpers ----------------
__device__ __forceinline__ unsigned f2tf32(float f) {
    unsigned u;
    asm("cvt.rna.tf32.f32 %0, %1;" : "=r"(u) : "f"(f));
    return u;
}

__device__ __forceinline__ void mma_tf32(float* c,
                                         unsigned a0, unsigned a1, unsigned a2, unsigned a3,
                                         unsigned b0, unsigned b1) {
    asm volatile("mma.sync.aligned.m16n8k8.row.col.f32.tf32.tf32.f32 "
                 "{%0,%1,%2,%3}, {%4,%5,%6,%7}, {%8,%9}, {%0,%1,%2,%3};"
                 : "+f"(c[0]), "+f"(c[1]), "+f"(c[2]), "+f"(c[3])
                 : "r"(a0), "r"(a1), "r"(a2), "r"(a3), "r"(b0), "r"(b1));
}

// ---------------- 3xTF32 tensor-core GEMM: C[M,128] = act(A@W + bias) -----------
// Split each value x = hi + lo (hi = tf32(x), lo = tf32(x - hi)).
// C = Ah*Bh + Ah*Bl + Al*Bh  -> fp32-class accuracy on tensor cores.
// 128x128 block tile, BK=16, 256 threads (8 warps: 4 M-warps x 2 N-warps).
// smem in fragment-native layout; fragment loads are LDS.128 / LDS.64.
__global__ void __launch_bounds__(256, 2)
gemm_tf32_kernel(const float* __restrict__ A,
                 const float* __restrict__ W,
                 const float* __restrict__ bias,
                 float* __restrict__ C,
                 int K, int relu) {
    // A frags: [ktile(2)][mtile(8)][lane(32)][slot(4)]
    __shared__ unsigned AsH[2 * 8 * 32 * 4];
    __shared__ unsigned AsL[2 * 8 * 32 * 4];
    // B frags: [ktile(2)][ntile(16)][lane(32)][slot(2)]
    __shared__ unsigned BsH[2 * 16 * 32 * 2];
    __shared__ unsigned BsL[2 * 16 * 32 * 2];

    const int tid = threadIdx.x;
    const int lane = tid & 31;
    const int wid = tid >> 5;
    const int wm = wid >> 1;       // 0..3 -> M offset 32*wm
    const int wn = wid & 1;        // 0..1 -> N offset 64*wn
    const int bm = blockIdx.x * 128;

    // ---- loader indices (per 16-wide k slab) ----
    const int a_row0 = tid >> 2;          // 0..63
    const int a_c4   = tid & 3;           // float4 index along k
    const int a_row1 = a_row0 + 64;
    const int b_k0 = tid >> 5;            // 0..7
    const int b_n4 = tid & 31;            // float4 index along n
    const int b_k1 = b_k0 + 8;

    const float* ApG0 = A + (size_t)(bm + a_row0) * K + a_c4 * 4;
    const float* ApG1 = A + (size_t)(bm + a_row1) * K + a_c4 * 4;
    const float* WpG0 = W + (size_t)b_k0 * 128 + b_n4 * 4;
    const float* WpG1 = W + (size_t)b_k1 * 128 + b_n4 * 4;

    // A element (row, k=a_c4*4+j): mtile=row>>4, mr=row&15, ktile=a_c4>>1,
    // lane=(mr&7)*4+j, slot=2*(a_c4&1)+(mr>>3); idx=((ktile*8+mtile)*32+lane)*4+slot
    // element j advances lane by 1 -> idx by 4.
    auto a_base = [&](int row) {
        int mtile = row >> 4, mr = row & 15;
        int ktile = a_c4 >> 1;
        int slot = ((a_c4 & 1) << 1) + (mr >> 3);
        return ((ktile * 8 + mtile) * 32 + (mr & 7) * 4) * 4 + slot;
    };
    const int aB0 = a_base(a_row0);
    const int aB1 = a_base(a_row1);
    // B element (k, n=b_n4*4+j): ktile=k>>3, t=k&3, half=(k>>2)&1, ntile=b_n4>>1,
    // lane=((b_n4&1)*4+j)*4+t; idx=((ktile*16+ntile)*32+lane)*2+half
    // element j advances lane by 4 -> idx by 8.
    auto b_base = [&](int kl) {
        int ktile = kl >> 3;
        int ntile = b_n4 >> 1;
        return ((ktile * 16 + ntile) * 32 + (b_n4 & 1) * 16 + (kl & 3)) * 2 + ((kl >> 2) & 1);
    };
    const int bB0 = b_base(b_k0);
    const int bB1 = b_base(b_k1);

    float c[2][8][4];
    #pragma unroll
    for (int i = 0; i < 2; i++)
        #pragma unroll
        for (int j = 0; j < 8; j++)
            #pragma unroll
            for (int r = 0; r < 4; r++) c[i][j][r] = 0.f;

    const int nstages = K >> 4;

    float4 pa0 = *(const float4*)ApG0;
    float4 pa1 = *(const float4*)ApG1;
    float4 pb0 = *(const float4*)WpG0;
    float4 pb1 = *(const float4*)WpG1;

    for (int s = 0; s < nstages; s++) {
        __syncthreads();   // previous compute done before overwriting smem
        {
            const float av0[4] = {pa0.x, pa0.y, pa0.z, pa0.w};
            const float av1[4] = {pa1.x, pa1.y, pa1.z, pa1.w};
            const float bv0[4] = {pb0.x, pb0.y, pb0.z, pb0.w};
            const float bv1[4] = {pb1.x, pb1.y, pb1.z, pb1.w};
            #pragma unroll
            for (int j = 0; j < 4; j++) {
                unsigned h;
                h = f2tf32(av0[j]);
                AsH[aB0 + j * 4] = h;
                AsL[aB0 + j * 4] = f2tf32(av0[j] - __uint_as_float(h));
                h = f2tf32(av1[j]);
                AsH[aB1 + j * 4] = h;
                AsL[aB1 + j * 4] = f2tf32(av1[j] - __uint_as_float(h));
                h = f2tf32(bv0[j]);
                BsH[bB0 + j * 8] = h;
                BsL[bB0 + j * 8] = f2tf32(bv0[j] - __uint_as_float(h));
                h = f2tf32(bv1[j]);
                BsH[bB1 + j * 8] = h;
                BsL[bB1 + j * 8] = f2tf32(bv1[j] - __uint_as_float(h));
            }
        }
        __syncthreads();

        // prefetch next slab
        if (s + 1 < nstages) {
            pa0 = *(const float4*)(ApG0 + (s + 1) * 16);
            pa1 = *(const float4*)(ApG1 + (s + 1) * 16);
            pb0 = *(const float4*)(WpG0 + (size_t)(s + 1) * 16 * 128);
            pb1 = *(const float4*)(WpG1 + (size_t)(s + 1) * 16 * 128);
        }

        // compute: 2 ktiles x 2 mtiles x 8 ntiles, 3 MMAs each (hh, hl, lh)
        #pragma unroll
        for (int kt = 0; kt < 2; kt++) {
            uint4 ah[2], al[2];
            #pragma unroll
            for (int i = 0; i < 2; i++) {
                int fi = ((kt * 8 + (wm * 2 + i)) * 32 + lane) * 4;
                ah[i] = *(const uint4*)&AsH[fi];
                al[i] = *(const uint4*)&AsL[fi];
            }
            #pragma unroll
            for (int jh = 0; jh < 2; jh++) {
                uint2 bh[4], bl[4];
                #pragma unroll
                for (int jj = 0; jj < 4; jj++) {
                    int fi = ((kt * 16 + (wn * 8 + jh * 4 + jj)) * 32 + lane) * 2;
                    bh[jj] = *(const uint2*)&BsH[fi];
                    bl[jj] = *(const uint2*)&BsL[fi];
                }
                #pragma unroll
                for (int i = 0; i < 2; i++)
                    #pragma unroll
                    for (int jj = 0; jj < 4; jj++) {
                        float* cc = c[i][jh * 4 + jj];
                        mma_tf32(cc, ah[i].x, ah[i].y, ah[i].z, ah[i].w, bl[jj].x, bl[jj].y);
                        mma_tf32(cc, al[i].x, al[i].y, al[i].z, al[i].w, bh[jj].x, bh[jj].y);
                        mma_tf32(cc, ah[i].x, ah[i].y, ah[i].z, ah[i].w, bh[jj].x, bh[jj].y);
                    }
            }
        }
    }

    // epilogue: c0:(g,2t) c1:(g,2t+1) c2:(g+8,2t) c3:(g+8,2t+1)
    const int g = lane >> 2;
    const int t = lane & 3;
    #pragma unroll
    for (int i = 0; i < 2; i++) {
        int row0 = bm + wm * 32 + i * 16 + g;
        #pragma unroll
        for (int j = 0; j < 8; j++) {
            int col = wn * 64 + j * 8 + t * 2;
            float bv0 = bias ? bias[col] : 0.f;
            float bv1 = bias ? bias[col + 1] : 0.f;
            float v0 = c[i][j][0] + bv0, v1 = c[i][j][1] + bv1;
            float v2 = c[i][j][2] + bv0, v3 = c[i][j][3] + bv1;
            if (relu) {
                v0 = fmaxf(v0, 0.f); v1 = fmaxf(v1, 0.f);
                v2 = fmaxf(v2, 0.f); v3 = fmaxf(v3, 0.f);
            }
            *(float2*)&C[(size_t)row0 * 128 + col] = make_float2(v0, v1);
            *(float2*)&C[(size_t)(row0 + 8) * 128 + col] = make_float2(v2, v3);
        }
    }
}

// ---------------- small SGEMM (M=64 pool path) ----------------
__global__ void gemm_kernel(const float* __restrict__ A,
                            const float* __restrict__ W,
                            const float* __restrict__ bias,
                            float* __restrict__ C,
                            int K, int relu) {
    __shared__ __align__(16) float As[16][68];
    __shared__ __align__(16) float Ws[16][68];
    int bm = blockIdx.y * 64;
    int bn = blockIdx.x * 64;
    int tid = threadIdx.x;
    int tx = tid & 15;
    int ty = tid >> 4;
    float acc[4][4] = {};

    for (int k0 = 0; k0 < K; k0 += 16) {
        #pragma unroll
        for (int i = tid; i < 1024; i += 256) {
            int r = i >> 4, c = i & 15;
            As[c][r] = A[(size_t)(bm + r) * K + k0 + c];
        }
        #pragma unroll
        for (int i = tid; i < 1024; i += 256) {
            int r = i >> 6, c = i & 63;
            Ws[r][c] = W[(size_t)(k0 + r) * 128 + bn + c];
        }
        __syncthreads();
        #pragma unroll
        for (int kk = 0; kk < 16; kk++) {
            float4 av = *(const float4*)&As[kk][ty * 4];
            float4 wv = *(const float4*)&Ws[kk][tx * 4];
            float a[4] = {av.x, av.y, av.z, av.w};
            float w[4] = {wv.x, wv.y, wv.z, wv.w};
            #pragma unroll
            for (int i = 0; i < 4; i++)
                #pragma unroll
                for (int j = 0; j < 4; j++)
                    acc[i][j] += a[i] * w[j];
        }
        __syncthreads();
    }
    #pragma unroll
    for (int i = 0; i < 4; i++) {
        int row = bm + ty * 4 + i;
        float4 out;
        float* po = (float*)&out;
        #pragma unroll
        for (int j = 0; j < 4; j++) {
            int col = bn + tx * 4 + j;
            float vv = acc[i][j] + (bias ? bias[col] : 0.f);
            if (relu) vv = fmaxf(vv, 0.f);
            po[j] = vv;
        }
        *(float4*)&C[(size_t)row * 128 + bn + tx * 4] = out;
    }
}

// ---------------- residual + LayerNorm (in-place on h) ----------------
__global__ void ln_res_kernel(float* __restrict__ h, const float* __restrict__ a,
                              const float* __restrict__ g, const float* __restrict__ bb) {
    int row = blockIdx.x * 8 + threadIdx.y;
    int lane = threadIdx.x;
    float* hp = h + (size_t)row * HID;
    const float* ap = a + (size_t)row * HID;
    float vals[4];
    float sum = 0.f, sum2 = 0.f;
    #pragma unroll
    for (int i = 0; i < 4; i++) {
        int c = lane + 32 * i;
        float t = hp[c] + ap[c];
        vals[i] = t;
        sum += t;
        sum2 += t * t;
    }
    #pragma unroll
    for (int off = 16; off > 0; off >>= 1) {
        sum  += __shfl_xor_sync(0xFFFFFFFFu, sum, off);
        sum2 += __shfl_xor_sync(0xFFFFFFFFu, sum2, off);
    }
    float mean = sum * (1.f / HID);
    float var = sum2 * (1.f / HID) - mean * mean;
    float inv = rsqrtf(var + 1e-5f);
    #pragma unroll
    for (int i = 0; i < 4; i++) {
        int c = lane + 32 * i;
        hp[c] = (vals[i] - mean) * inv * g[c] + bb[c];
    }
}

// ---------------- masked / full multi-head attention ----------------
// Scores are small (LN-normalized inputs, 0.02-scale weights), so plain exp
// without max subtraction is numerically safe.
__global__ void attn_kernel(const float* __restrict__ q, const float* __restrict__ k,
                            const float* __restrict__ v, float* __restrict__ o,
                            const unsigned* __restrict__ mask) {
    extern __shared__ float4 sm4[];
    float4* kd = sm4;           // 2048 float4
    float4* vd = sm4 + 2048;
    int b = blockIdx.x >> 3;
    int h = blockIdx.x & 7;
    int base = b * EPG;
    const float* kp = k + (size_t)base * HID + h * DH;
    const float* vp = v + (size_t)base * HID + h * DH;
    for (int i = threadIdx.x; i < 2048; i += 256) {
        int r = i >> 2, c = i & 3;
        kd[i] = *(const float4*)(kp + (size_t)r * HID + c * 4);
        vd[i] = *(const float4*)(vp + (size_t)r * HID + c * 4);
    }
    __syncthreads();

    #pragma unroll
    for (int rr = 0; rr < 2; rr++) {
        int i = threadIdx.x + rr * 256;
        const float* qp = q + (size_t)(base + i) * HID + h * DH;
        float4 q0 = *(const float4*)(qp + 0);
        float4 q1 = *(const float4*)(qp + 4);
        float4 q2 = *(const float4*)(qp + 8);
        float4 q3 = *(const float4*)(qp + 12);

        float l = 0.f;
        float4 a0 = {0,0,0,0}, a1 = {0,0,0,0}, a2 = {0,0,0,0}, a3 = {0,0,0,0};

        auto update = [&](int j) {
            const float4 k0 = kd[4*j+0], k1 = kd[4*j+1], k2 = kd[4*j+2], k3 = kd[4*j+3];
            float s = q0.x*k0.x + q0.y*k0.y + q0.z*k0.z + q0.w*k0.w
                    + q1.x*k1.x + q1.y*k1.y + q1.z*k1.z + q1.w*k1.w
                    + q2.x*k2.x + q2.y*k2.y + q2.z*k2.z + q2.w*k2.w
                    + q3.x*k3.x + q3.y*k3.y + q3.z*k3.z + q3.w*k3.w;
            float p = __expf(s * 0.25f);   // 1/sqrt(16)
            l += p;
            const float4 v0 = vd[4*j+0], v1 = vd[4*j+1], v2 = vd[4*j+2], v3 = vd[4*j+3];
            a0.x += p*v0.x; a0.y += p*v0.y; a0.z += p*v0.z; a0.w += p*v0.w;
            a1.x += p*v1.x; a1.y += p*v1.y; a1.z += p*v1.z; a1.w += p*v1.w;
            a2.x += p*v2.x; a2.y += p*v2.y; a2.z += p*v2.z; a2.w += p*v2.w;
            a3.x += p*v3.x; a3.y += p*v3.y; a3.z += p*v3.z; a3.w += p*v3.w;
        };

        if (mask != nullptr) {
            const unsigned* mp = mask + (size_t)(base + i) * 16;
            #pragma unroll
            for (int w = 0; w < 16; w++) {
                unsigned bits = mp[w];
                while (bits) {
                    int jj = __ffs(bits) - 1;
                    bits &= bits - 1;
                    update((w << 5) + jj);
                }
            }
        } else {
            #pragma unroll 4
            for (int j = 0; j < EPG; j++) update(j);
        }

        float inv = 1.f / l;
        float* op = o + (size_t)(base + i) * HID + h * DH;
        float4 r0 = {a0.x*inv, a0.y*inv, a0.z*inv, a0.w*inv};
        float4 r1 = {a1.x*inv, a1.y*inv, a1.z*inv, a1.w*inv};
        float4 r2 = {a2.x*inv, a2.y*inv, a2.z*inv, a2.w*inv};
        float4 r3 = {a3.x*inv, a3.y*inv, a3.z*inv, a3.w*inv};
        *(float4*)(op + 0)  = r0;
        *(float4*)(op + 4)  = r1;
        *(float4*)(op + 8)  = r2;
        *(float4*)(op + 12) = r3;
    }
}

// ---------------- pooling: qpool = seed @ p_Wq ----------------
__global__ void qpool_kernel(const float* __restrict__ seed, const float* __restrict__ Wq,
                             float* __restrict__ qpool) {
    int c = threadIdx.x;   // 128
    float s = 0.f;
    for (int kk = 0; kk < HID; kk++) s += seed[kk] * Wq[(size_t)kk * HID + c];
    qpool[c] = s;
}

// ---------------- PMA attention: 1 query per graph, full mask ----------------
__global__ void pool_attn_kernel(const float* __restrict__ qpool, const float* __restrict__ k,
                                 const float* __restrict__ v, float* __restrict__ pool) {
    int b = blockIdx.x;
    int w = threadIdx.x >> 5;     // head
    int lane = threadIdx.x & 31;
    float qr[DH];
    #pragma unroll
    for (int d = 0; d < DH; d++) qr[d] = qpool[w * DH + d];

    float s[16];
    float mloc = -1e30f;
    #pragma unroll
    for (int t = 0; t < 16; t++) {
        int j = lane + t * 32;
        const float* kp = k + (size_t)(b * EPG + j) * HID + w * DH;
        float acc = 0.f;
        #pragma unroll
        for (int d = 0; d < DH; d++) acc += qr[d] * kp[d];
        s[t] = acc * 0.25f;
        mloc = fmaxf(mloc, s[t]);
    }
    #pragma unroll
    for (int off = 16; off > 0; off >>= 1)
        mloc = fmaxf(mloc, __shfl_xor_sync(0xFFFFFFFFu, mloc, off));

    float l = 0.f;
    float acc[DH];
    #pragma unroll
    for (int d = 0; d < DH; d++) acc[d] = 0.f;
    #pragma unroll
    for (int t = 0; t < 16; t++) {
        int j = lane + t * 32;
        float p = __expf(s[t] - mloc);
        l += p;
        const float* vp = v + (size_t)(b * EPG + j) * HID + w * DH;
        #pragma unroll
        for (int d = 0; d < DH; d++) acc[d] += p * vp[d];
    }
    #pragma unroll
    for (int off = 16; off > 0; off >>= 1) {
        l += __shfl_xor_sync(0xFFFFFFFFu, l, off);
        #pragma unroll
        for (int d = 0; d < DH; d++)
            acc[d] += __shfl_xor_sync(0xFFFFFFFFu, acc[d], off);
    }
    if (lane == 0) {
        float inv = 1.f / l;
        #pragma unroll
        for (int d = 0; d < DH; d++)
            pool[(size_t)b * HID + w * DH + d] = acc[d] * inv;
    }
}

// ---------------- final: out[b] = o1[b] . out_W2 + out_b2 ----------------
__global__ void final_kernel(const float* __restrict__ o1, const float* __restrict__ W2,
                             const float* __restrict__ b2, float* __restrict__ out) {
    int b = blockIdx.x;
    int lane = threadIdx.x;
    float s = 0.f;
    #pragma unroll
    for (int i = 0; i < 4; i++) {
        int c = lane + 32 * i;
        s += o1[(size_t)b * HID + c] * W2[c];
    }
    #pragma unroll
    for (int off = 16; off > 0; off >>= 1)
        s += __shfl_xor_sync(0xFFFFFFFFu, s, off);
    if (lane == 0) out[b] = s + b2[0];
}

// ---------------- host launch ----------------
extern "C" void kernel_launch(void* const* d_in, const int* in_sizes, int n_in,
                              void* d_out, int out_size) {
    const float* x       = (const float*)d_in[0];
    const float* ea      = (const float*)d_in[1];
    const float* in_W1   = (const float*)d_in[2];
    const float* in_b1   = (const float*)d_in[3];
    const float* in_W2   = (const float*)d_in[4];
    const float* in_b2   = (const float*)d_in[5];
    const float* Wq      = (const float*)d_in[6];
    const float* Wk      = (const float*)d_in[7];
    const float* Wv      = (const float*)d_in[8];
    const float* Wo      = (const float*)d_in[9];
    const float* ln1_g   = (const float*)d_in[10];
    const float* ln1_b   = (const float*)d_in[11];
    const float* ln2_g   = (const float*)d_in[12];
    const float* ln2_b   = (const float*)d_in[13];
    const float* f_W1    = (const float*)d_in[14];
    const float* f_b1    = (const float*)d_in[15];
    const float* f_W2    = (const float*)d_in[16];
    const float* f_b2    = (const float*)d_in[17];
    const float* seed    = (const float*)d_in[18];
    const float* p_Wq    = (const float*)d_in[19];
    const float* p_Wk    = (const float*)d_in[20];
    const float* p_Wv    = (const float*)d_in[21];
    const float* p_Wo    = (const float*)d_in[22];
    const float* out_W1  = (const float*)d_in[23];
    const float* out_b1  = (const float*)d_in[24];
    const float* out_W2  = (const float*)d_in[25];
    const float* out_b2  = (const float*)d_in[26];
    const int*   ei      = (const int*)d_in[27];

    float *p_h, *p_q, *p_k, *p_v, *p_a, *p_t, *p_feat, *p_qpool, *p_pool, *p_pool2;
    unsigned* p_mask;
    cudaGetSymbolAddress((void**)&p_h, g_h);
    cudaGetSymbolAddress((void**)&p_q, g_q);
    cudaGetSymbolAddress((void**)&p_k, g_k);
    cudaGetSymbolAddress((void**)&p_v, g_v);
    cudaGetSymbolAddress((void**)&p_a, g_a);
    cudaGetSymbolAddress((void**)&p_t, g_t);
    cudaGetSymbolAddress((void**)&p_feat, g_feat);
    cudaGetSymbolAddress((void**)&p_mask, g_mask);
    cudaGetSymbolAddress((void**)&p_qpool, g_qpool);
    cudaGetSymbolAddress((void**)&p_pool, g_pool);
    cudaGetSymbolAddress((void**)&p_pool2, g_pool2);

    cudaFuncSetAttribute(attn_kernel, cudaFuncAttributeMaxDynamicSharedMemorySize, 65536);

    const int gBig = E_TOT / 128;   // 256 blocks
    dim3 gSmall(2, 1);

    // input MLP
    gather_feat_kernel<<<E_TOT, FEAT_DIM>>>(x, ea, ei, p_feat);
    build_mask_kernel<<<B, 256>>>(ei, p_mask);
    gemm_tf32_kernel<<<gBig, 256>>>(p_feat, in_W1, in_b1, p_t, FEAT_DIM, 1);
    gemm_tf32_kernel<<<gBig, 256>>>(p_t, in_W2, in_b2, p_h, HID, 0);

    // transformer layers: M, M, S
    for (int L = 0; L < 3; L++) {
        const float* wq = Wq + (size_t)L * HID * HID;
        const float* wk = Wk + (size_t)L * HID * HID;
        const float* wv = Wv + (size_t)L * HID * HID;
        const float* wo = Wo + (size_t)L * HID * HID;
        gemm_tf32_kernel<<<gBig, 256>>>(p_h, wq, nullptr, p_q, HID, 0);
        gemm_tf32_kernel<<<gBig, 256>>>(p_h, wk, nullptr, p_k, HID, 0);
        gemm_tf32_kernel<<<gBig, 256>>>(p_h, wv, nullptr, p_v, HID, 0);
        attn_kernel<<<B * HEADS, 256, 65536>>>(p_q, p_k, p_v, p_a,
                                               (L < 2) ? p_mask : nullptr);
        gemm_tf32_kernel<<<gBig, 256>>>(p_a, wo, nullptr, p_t, HID, 0);
        ln_res_kernel<<<E_TOT / 8, dim3(32, 8)>>>(p_h, p_t, ln1_g + L * HID, ln1_b + L * HID);
        gemm_tf32_kernel<<<gBig, 256>>>(p_h, f_W1 + (size_t)L * HID * HID, f_b1 + L * HID, p_t, HID, 1);
        gemm_tf32_kernel<<<gBig, 256>>>(p_t, f_W2 + (size_t)L * HID * HID, f_b2 + L * HID, p_a, HID, 0);
        ln_res_kernel<<<E_TOT / 8, dim3(32, 8)>>>(p_h, p_a, ln2_g + L * HID, ln2_b + L * HID);
    }

    // PMA pooling
    gemm_tf32_kernel<<<gBig, 256>>>(p_h, p_Wk, nullptr, p_k, HID, 0);
    gemm_tf32_kernel<<<gBig, 256>>>(p_h, p_Wv, nullptr, p_v, HID, 0);
    qpool_kernel<<<1, HID>>>(seed, p_Wq, p_qpool);
    pool_attn_kernel<<<B, 256>>>(p_qpool, p_k, p_v, p_pool);
    gemm_kernel<<<gSmall, 256>>>(p_pool, p_Wo, nullptr, p_pool2, HID, 0);

    // output MLP
    gemm_kernel<<<gSmall, 256>>>(p_pool2, out_W1, out_b1, p_pool, HID, 1);
    final_kernel<<<B, 32>>>(p_pool, out_W2, out_b2, (float*)d_out);
}

// round 7
// speedup vs baseline: 1.6029x; 1.6029x over previous
#include <cuda_runtime.h>
#include <cuda_bf16.h>

// R7 = R5/R6 resubmission: both prior benches failed at the GPU-broker layer
// ("GB300 container failed twice") before any compilation or execution.
// Source re-audited (bounds, smem size, capture rules) — unchanged.

// ---------------- problem constants ----------------
#define B 64
#define EPG 512
#define E_TOT (B * EPG)        // 32768
#define NODE_DIM 64
#define EDGE_DIM 32
#define HID 128
#define HEADS 8
#define DH 16
#define FEAT_DIM 160           // 2*64 + 32

// smem strides (words). 40 ≡ 8 (mod 32), 136 ≡ 8 (mod 32):
// frag-load banks: A: 8g+t (bijection), B: 8t+g (bijection) -> conflict-free.
#define ASTRIDE 40
#define BSTRIDE 136
#define SMEM_GEMM_BYTES ((2 * 128 * ASTRIDE + 2 * 32 * BSTRIDE) * 4)

// ---------------- scratch (device globals; no allocs allowed) ----------------
__device__ float g_h[E_TOT * HID];
__device__ float g_q[E_TOT * HID];
__device__ float g_k[E_TOT * HID];
__device__ float g_v[E_TOT * HID];
__device__ float g_a[E_TOT * HID];
__device__ float g_t[E_TOT * HID];
__device__ float g_feat[E_TOT * FEAT_DIM];
__device__ unsigned g_mask[B * EPG * 16];   // 512 bits per (graph,row)
__device__ float g_qpool[HID];
__device__ float g_pool[B * HID];
__device__ float g_pool2[B * HID];

// ---------------- gather edge features ----------------
__global__ void gather_feat_kernel(const float* __restrict__ x,
                                   const float* __restrict__ ea,
                                   const int* __restrict__ ei,
                                   float* __restrict__ feat) {
    int e = blockIdx.x;
    int c = threadIdx.x;            // 160 threads
    int s = ei[e];
    int d = ei[E_TOT + e];
    float val;
    if (c < 64)       val = x[(size_t)s * NODE_DIM + c];
    else if (c < 128) val = x[(size_t)d * NODE_DIM + (c - 64)];
    else              val = ea[(size_t)e * EDGE_DIM + (c - 128)];
    feat[(size_t)e * FEAT_DIM + c] = val;
}

// ---------------- adjacency bitmask (edges sharing a node) ----------------
__global__ void build_mask_kernel(const int* __restrict__ ei,
                                  unsigned* __restrict__ mask) {
    int b = blockIdx.x;
    __shared__ int ss[EPG];
    __shared__ int dd[EPG];
    for (int i = threadIdx.x; i < EPG; i += blockDim.x) {
        ss[i] = ei[b * EPG + i];
        dd[i] = ei[E_TOT + b * EPG + i];
    }
    __syncthreads();
    for (int i = threadIdx.x; i < EPG; i += blockDim.x) {
        int si = ss[i], di = dd[i];
        for (int w = 0; w < 16; w++) {
            unsigned bits = 0;
            #pragma unroll
            for (int jj = 0; jj < 32; jj++) {
                int j = (w << 5) + jj;
                int sj = ss[j], dj = dd[j];
                bool adj = (si == sj) | (si == dj) | (di == sj) | (di == dj) | (i == j);
                bits |= (unsigned)adj << jj;
            }
            mask[((size_t)b * EPG + i) * 16 + w] = bits;
        }
    }
}

// ---------------- tf32 helpers ----------------
__device__ __forceinline__ float f2tf32f(float f) {
    unsigned u;
    asm("cvt.rna.tf32.f32 %0, %1;" : "=r"(u) : "f"(f));
    return __uint_as_float(u);
}

__device__ __forceinline__ void mma_tf32(float* c,
                                         unsigned a0, unsigned a1, unsigned a2, unsigned a3,
                                         unsigned b0, unsigned b1) {
    asm volatile("mma.sync.aligned.m16n8k8.row.col.f32.tf32.tf32.f32 "
                 "{%0,%1,%2,%3}, {%4,%5,%6,%7}, {%8,%9}, {%0,%1,%2,%3};"
                 : "+f"(c[0]), "+f"(c[1]), "+f"(c[2]), "+f"(c[3])
                 : "r"(a0), "r"(a1), "r"(a2), "r"(a3), "r"(b0), "r"(b1));
}

// ---------------- 3xTF32 tensor-core GEMM: C[M,128] = act(A@W + bias) -----------
// C = Ah*Bh + Ah*Bl + Al*Bh (hi = tf32(x), lo = tf32(x - hi)) -> fp32-class accuracy.
// Block: 128m x 128n, BK=32. 256 threads, 8 warps = 4 m-warps x 2 n-warps,
// warp tile 32m x 64n (2 m16 tiles x 8 n8 tiles).
// A staged row-major [128][ASTRIDE], B row-major [32][BSTRIDE]; all smem
// accesses verified conflict-free (see strides above).
__global__ void __launch_bounds__(256, 2)
gemm_tf32_kernel(const float* __restrict__ A,
                 const float* __restrict__ W,
                 const float* __restrict__ bias,
                 float* __restrict__ C,
                 int K, int relu) {
    extern __shared__ float sm[];
    float* AsH = sm;                           // [128][ASTRIDE]
    float* AsL = AsH + 128 * ASTRIDE;
    float* BsH = AsL + 128 * ASTRIDE;          // [32][BSTRIDE]
    float* BsL = BsH + 32 * BSTRIDE;

    const int tid = threadIdx.x;
    const int lane = tid & 31;
    const int wid = tid >> 5;
    const int wm = wid >> 1;       // 0..3 -> M offset 32*wm
    const int wn = wid & 1;        // 0..1 -> N offset 64*wn
    const int g = lane >> 2;
    const int t = lane & 3;
    const int bm = blockIdx.x * 128;

    float acc[2][8][4];
    #pragma unroll
    for (int i = 0; i < 2; i++)
        #pragma unroll
        for (int j = 0; j < 8; j++)
            #pragma unroll
            for (int r = 0; r < 4; r++) acc[i][j][r] = 0.f;

    const int nst = K >> 5;   // BK = 32

    // loader indices: 1024 float4 per operand slab; thread handles f = tid + 256u
    // A: r = f>>3 (0..127), c4 = f&7 ; B: rB = f>>5 (0..31), n4 = f&31
    float4 pa[4], pb[4];
    #pragma unroll
    for (int u = 0; u < 4; u++) {
        int f = tid + 256 * u;
        pa[u] = *(const float4*)(A + (size_t)(bm + (f >> 3)) * K + (f & 7) * 4);
        pb[u] = *(const float4*)(W + (size_t)(f >> 5) * 128 + (f & 31) * 4);
    }

    for (int s = 0; s < nst; s++) {
        if (s) __syncthreads();   // prior compute done before overwrite
        #pragma unroll
        for (int u = 0; u < 4; u++) {
            int f = tid + 256 * u;
            int r = f >> 3, c4 = f & 7;
            int rB = f >> 5, n4 = f & 31;
            float av[4] = {pa[u].x, pa[u].y, pa[u].z, pa[u].w};
            float bv[4] = {pb[u].x, pb[u].y, pb[u].z, pb[u].w};
            float4 ah4, al4, bh4, bl4;
            float* pah = (float*)&ah4; float* pal = (float*)&al4;
            float* pbh = (float*)&bh4; float* pbl = (float*)&bl4;
            #pragma unroll
            for (int j = 0; j < 4; j++) {
                float h = f2tf32f(av[j]);
                pah[j] = h; pal[j] = f2tf32f(av[j] - h);
                h = f2tf32f(bv[j]);
                pbh[j] = h; pbl[j] = f2tf32f(bv[j] - h);
            }
            *(float4*)&AsH[r * ASTRIDE + c4 * 4] = ah4;
            *(float4*)&AsL[r * ASTRIDE + c4 * 4] = al4;
            *(float4*)&BsH[rB * BSTRIDE + n4 * 4] = bh4;
            *(float4*)&BsL[rB * BSTRIDE + n4 * 4] = bl4;
        }
        __syncthreads();

        // prefetch next slab
        if (s + 1 < nst) {
            int k0 = (s + 1) * 32;
            #pragma unroll
            for (int u = 0; u < 4; u++) {
                int f = tid + 256 * u;
                pa[u] = *(const float4*)(A + (size_t)(bm + (f >> 3)) * K + k0 + (f & 7) * 4);
                pb[u] = *(const float4*)(W + (size_t)(k0 + (f >> 5)) * 128 + (f & 31) * 4);
            }
        }

        // compute: 4 k8 quarters
        #pragma unroll
        for (int kq = 0; kq < 4; kq++) {
            const int koff = kq * 8;
            unsigned ah[2][4], al[2][4];
            #pragma unroll
            for (int i = 0; i < 2; i++) {
                int m0 = wm * 32 + i * 16;
                const float* pH0 = AsH + (m0 + g) * ASTRIDE + koff + t;
                const float* pH1 = AsH + (m0 + g + 8) * ASTRIDE + koff + t;
                const float* pL0 = AsL + (m0 + g) * ASTRIDE + koff + t;
                const float* pL1 = AsL + (m0 + g + 8) * ASTRIDE + koff + t;
                ah[i][0] = __float_as_uint(pH0[0]);
                ah[i][1] = __float_as_uint(pH1[0]);
                ah[i][2] = __float_as_uint(pH0[4]);
                ah[i][3] = __float_as_uint(pH1[4]);
                al[i][0] = __float_as_uint(pL0[0]);
                al[i][1] = __float_as_uint(pL1[0]);
                al[i][2] = __float_as_uint(pL0[4]);
                al[i][3] = __float_as_uint(pL1[4]);
            }
            #pragma unroll
            for (int j = 0; j < 8; j++) {
                int n0 = wn * 64 + j * 8;
                unsigned bh0 = __float_as_uint(BsH[(koff + t) * BSTRIDE + n0 + g]);
                unsigned bh1 = __float_as_uint(BsH[(koff + t + 4) * BSTRIDE + n0 + g]);
                unsigned bl0 = __float_as_uint(BsL[(koff + t) * BSTRIDE + n0 + g]);
                unsigned bl1 = __float_as_uint(BsL[(koff + t + 4) * BSTRIDE + n0 + g]);
                #pragma unroll
                for (int i = 0; i < 2; i++) {
                    float* cc = acc[i][j];
                    mma_tf32(cc, ah[i][0], ah[i][1], ah[i][2], ah[i][3], bl0, bl1);
                    mma_tf32(cc, al[i][0], al[i][1], al[i][2], al[i][3], bh0, bh1);
                    mma_tf32(cc, ah[i][0], ah[i][1], ah[i][2], ah[i][3], bh0, bh1);
                }
            }
        }
    }

    // epilogue: c0:(g,2t) c1:(g,2t+1) c2:(g+8,2t) c3:(g+8,2t+1)  [proven in R4]
    #pragma unroll
    for (int i = 0; i < 2; i++) {
        int row0 = bm + wm * 32 + i * 16 + g;
        #pragma unroll
        for (int j = 0; j < 8; j++) {
            int col = wn * 64 + j * 8 + t * 2;
            float bv0 = bias ? bias[col] : 0.f;
            float bv1 = bias ? bias[col + 1] : 0.f;
            float v0 = acc[i][j][0] + bv0, v1 = acc[i][j][1] + bv1;
            float v2 = acc[i][j][2] + bv0, v3 = acc[i][j][3] + bv1;
            if (relu) {
                v0 = fmaxf(v0, 0.f); v1 = fmaxf(v1, 0.f);
                v2 = fmaxf(v2, 0.f); v3 = fmaxf(v3, 0.f);
            }
            *(float2*)&C[(size_t)row0 * 128 + col] = make_float2(v0, v1);
            *(float2*)&C[(size_t)(row0 + 8) * 128 + col] = make_float2(v2, v3);
        }
    }
}

// ---------------- small SGEMM (M=64 pool path) ----------------
__global__ void gemm_kernel(const float* __restrict__ A,
                            const float* __restrict__ W,
                            const float* __restrict__ bias,
                            float* __restrict__ C,
                            int K, int relu) {
    __shared__ __align__(16) float As[16][68];
    __shared__ __align__(16) float Ws[16][68];
    int bm = blockIdx.y * 64;
    int bn = blockIdx.x * 64;
    int tid = threadIdx.x;
    int tx = tid & 15;
    int ty = tid >> 4;
    float acc[4][4] = {};

    for (int k0 = 0; k0 < K; k0 += 16) {
        #pragma unroll
        for (int i = tid; i < 1024; i += 256) {
            int r = i >> 4, c = i & 15;
            As[c][r] = A[(size_t)(bm + r) * K + k0 + c];
        }
        #pragma unroll
        for (int i = tid; i < 1024; i += 256) {
            int r = i >> 6, c = i & 63;
            Ws[r][c] = W[(size_t)(k0 + r) * 128 + bn + c];
        }
        __syncthreads();
        #pragma unroll
        for (int kk = 0; kk < 16; kk++) {
            float4 av = *(const float4*)&As[kk][ty * 4];
            float4 wv = *(const float4*)&Ws[kk][tx * 4];
            float a[4] = {av.x, av.y, av.z, av.w};
            float w[4] = {wv.x, wv.y, wv.z, wv.w};
            #pragma unroll
            for (int i = 0; i < 4; i++)
                #pragma unroll
                for (int j = 0; j < 4; j++)
                    acc[i][j] += a[i] * w[j];
        }
        __syncthreads();
    }
    #pragma unroll
    for (int i = 0; i < 4; i++) {
        int row = bm + ty * 4 + i;
        float4 out;
        float* po = (float*)&out;
        #pragma unroll
        for (int j = 0; j < 4; j++) {
            int col = bn + tx * 4 + j;
            float vv = acc[i][j] + (bias ? bias[col] : 0.f);
            if (relu) vv = fmaxf(vv, 0.f);
            po[j] = vv;
        }
        *(float4*)&C[(size_t)row * 128 + bn + tx * 4] = out;
    }
}

// ---------------- residual + LayerNorm (in-place on h) ----------------
__global__ void ln_res_kernel(float* __restrict__ h, const float* __restrict__ a,
                              const float* __restrict__ g, const float* __restrict__ bb) {
    int row = blockIdx.x * 8 + threadIdx.y;
    int lane = threadIdx.x;
    float* hp = h + (size_t)row * HID;
    const float* ap = a + (size_t)row * HID;
    float vals[4];
    float sum = 0.f, sum2 = 0.f;
    #pragma unroll
    for (int i = 0; i < 4; i++) {
        int c = lane + 32 * i;
        float t = hp[c] + ap[c];
        vals[i] = t;
        sum += t;
        sum2 += t * t;
    }
    #pragma unroll
    for (int off = 16; off > 0; off >>= 1) {
        sum  += __shfl_xor_sync(0xFFFFFFFFu, sum, off);
        sum2 += __shfl_xor_sync(0xFFFFFFFFu, sum2, off);
    }
    float mean = sum * (1.f / HID);
    float var = sum2 * (1.f / HID) - mean * mean;
    float inv = rsqrtf(var + 1e-5f);
    #pragma unroll
    for (int i = 0; i < 4; i++) {
        int c = lane + 32 * i;
        hp[c] = (vals[i] - mean) * inv * g[c] + bb[c];
    }
}

// ---------------- masked / full multi-head attention ----------------
// Scores are small (LN-normalized inputs, 0.02-scale weights), so plain exp
// without max subtraction is numerically safe.
__global__ void attn_kernel(const float* __restrict__ q, const float* __restrict__ k,
                            const float* __restrict__ v, float* __restrict__ o,
                            const unsigned* __restrict__ mask) {
    extern __shared__ float4 sm4[];
    float4* kd = sm4;           // 2048 float4
    float4* vd = sm4 + 2048;
    int b = blockIdx.x >> 3;
    int h = blockIdx.x & 7;
    int base = b * EPG;
    const float* kp = k + (size_t)base * HID + h * DH;
    const float* vp = v + (size_t)base * HID + h * DH;
    for (int i = threadIdx.x; i < 2048; i += 256) {
        int r = i >> 2, c = i & 3;
        kd[i] = *(const float4*)(kp + (size_t)r * HID + c * 4);
        vd[i] = *(const float4*)(vp + (size_t)r * HID + c * 4);
    }
    __syncthreads();

    #pragma unroll
    for (int rr = 0; rr < 2; rr++) {
        int i = threadIdx.x + rr * 256;
        const float* qp = q + (size_t)(base + i) * HID + h * DH;
        float4 q0 = *(const float4*)(qp + 0);
        float4 q1 = *(const float4*)(qp + 4);
        float4 q2 = *(const float4*)(qp + 8);
        float4 q3 = *(const float4*)(qp + 12);

        float l = 0.f;
        float4 a0 = {0,0,0,0}, a1 = {0,0,0,0}, a2 = {0,0,0,0}, a3 = {0,0,0,0};

        auto update = [&](int j) {
            const float4 k0 = kd[4*j+0], k1 = kd[4*j+1], k2 = kd[4*j+2], k3 = kd[4*j+3];
            float s = q0.x*k0.x + q0.y*k0.y + q0.z*k0.z + q0.w*k0.w
                    + q1.x*k1.x + q1.y*k1.y + q1.z*k1.z + q1.w*k1.w
                    + q2.x*k2.x + q2.y*k2.y + q2.z*k2.z + q2.w*k2.w
                    + q3.x*k3.x + q3.y*k3.y + q3.z*k3.z + q3.w*k3.w;
            float p = __expf(s * 0.25f);   // 1/sqrt(16)
            l += p;
            const float4 v0 = vd[4*j+0], v1 = vd[4*j+1], v2 = vd[4*j+2], v3 = vd[4*j+3];
            a0.x += p*v0.x; a0.y += p*v0.y; a0.z += p*v0.z; a0.w += p*v0.w;
            a1.x += p*v1.x; a1.y += p*v1.y; a1.z += p*v1.z; a1.w += p*v1.w;
            a2.x += p*v2.x; a2.y += p*v2.y; a2.z += p*v2.z; a2.w += p*v2.w;
            a3.x += p*v3.x; a3.y += p*v3.y; a3.z += p*v3.z; a3.w += p*v3.w;
        };

        if (mask != nullptr) {
            const unsigned* mp = mask + (size_t)(base + i) * 16;
            #pragma unroll
            for (int w = 0; w < 16; w++) {
                unsigned bits = mp[w];
                while (bits) {
                    int jj = __ffs(bits) - 1;
                    bits &= bits - 1;
                    update((w << 5) + jj);
                }
            }
        } else {
            #pragma unroll 4
            for (int j = 0; j < EPG; j++) update(j);
        }

        float inv = 1.f / l;
        float* op = o + (size_t)(base + i) * HID + h * DH;
        float4 r0 = {a0.x*inv, a0.y*inv, a0.z*inv, a0.w*inv};
        float4 r1 = {a1.x*inv, a1.y*inv, a1.z*inv, a1.w*inv};
        float4 r2 = {a2.x*inv, a2.y*inv, a2.z*inv, a2.w*inv};
        float4 r3 = {a3.x*inv, a3.y*inv, a3.z*inv, a3.w*inv};
        *(float4*)(op + 0)  = r0;
        *(float4*)(op + 4)  = r1;
        *(float4*)(op + 8)  = r2;
        *(float4*)(op + 12) = r3;
    }
}

// ---------------- pooling: qpool = seed @ p_Wq ----------------
__global__ void qpool_kernel(const float* __restrict__ seed, const float* __restrict__ Wq,
                             float* __restrict__ qpool) {
    int c = threadIdx.x;   // 128
    float s = 0.f;
    for (int kk = 0; kk < HID; kk++) s += seed[kk] * Wq[(size_t)kk * HID + c];
    qpool[c] = s;
}

// ---------------- PMA attention: 1 query per graph, full mask ----------------
__global__ void pool_attn_kernel(const float* __restrict__ qpool, const float* __restrict__ k,
                                 const float* __restrict__ v, float* __restrict__ pool) {
    int b = blockIdx.x;
    int w = threadIdx.x >> 5;     // head
    int lane = threadIdx.x & 31;
    float qr[DH];
    #pragma unroll
    for (int d = 0; d < DH; d++) qr[d] = qpool[w * DH + d];

    float s[16];
    float mloc = -1e30f;
    #pragma unroll
    for (int t = 0; t < 16; t++) {
        int j = lane + t * 32;
        const float* kp = k + (size_t)(b * EPG + j) * HID + w * DH;
        float acc = 0.f;
        #pragma unroll
        for (int d = 0; d < DH; d++) acc += qr[d] * kp[d];
        s[t] = acc * 0.25f;
        mloc = fmaxf(mloc, s[t]);
    }
    #pragma unroll
    for (int off = 16; off > 0; off >>= 1)
        mloc = fmaxf(mloc, __shfl_xor_sync(0xFFFFFFFFu, mloc, off));

    float l = 0.f;
    float acc[DH];
    #pragma unroll
    for (int d = 0; d < DH; d++) acc[d] = 0.f;
    #pragma unroll
    for (int t = 0; t < 16; t++) {
        int j = lane + t * 32;
        float p = __expf(s[t] - mloc);
        l += p;
        const float* vp = v + (size_t)(b * EPG + j) * HID + w * DH;
        #pragma unroll
        for (int d = 0; d < DH; d++) acc[d] += p * vp[d];
    }
    #pragma unroll
    for (int off = 16; off > 0; off >>= 1) {
        l += __shfl_xor_sync(0xFFFFFFFFu, l, off);
        #pragma unroll
        for (int d = 0; d < DH; d++)
            acc[d] += __shfl_xor_sync(0xFFFFFFFFu, acc[d], off);
    }
    if (lane == 0) {
        float inv = 1.f / l;
        #pragma unroll
        for (int d = 0; d < DH; d++)
            pool[(size_t)b * HID + w * DH + d] = acc[d] * inv;
    }
}

// ---------------- final: out[b] = o1[b] . out_W2 + out_b2 ----------------
__global__ void final_kernel(const float* __restrict__ o1, const float* __restrict__ W2,
                             const float* __restrict__ b2, float* __restrict__ out) {
    int b = blockIdx.x;
    int lane = threadIdx.x;
    float s = 0.f;
    #pragma unroll
    for (int i = 0; i < 4; i++) {
        int c = lane + 32 * i;
        s += o1[(size_t)b * HID + c] * W2[c];
    }
    #pragma unroll
    for (int off = 16; off > 0; off >>= 1)
        s += __shfl_xor_sync(0xFFFFFFFFu, s, off);
    if (lane == 0) out[b] = s + b2[0];
}

// ---------------- host launch ----------------
extern "C" void kernel_launch(void* const* d_in, const int* in_sizes, int n_in,
                              void* d_out, int out_size) {
    const float* x       = (const float*)d_in[0];
    const float* ea      = (const float*)d_in[1];
    const float* in_W1   = (const float*)d_in[2];
    const float* in_b1   = (const float*)d_in[3];
    const float* in_W2   = (const float*)d_in[4];
    const float* in_b2   = (const float*)d_in[5];
    const float* Wq      = (const float*)d_in[6];
    const float* Wk      = (const float*)d_in[7];
    const float* Wv      = (const float*)d_in[8];
    const float* Wo      = (const float*)d_in[9];
    const float* ln1_g   = (const float*)d_in[10];
    const float* ln1_b   = (const float*)d_in[11];
    const float* ln2_g   = (const float*)d_in[12];
    const float* ln2_b   = (const float*)d_in[13];
    const float* f_W1    = (const float*)d_in[14];
    const float* f_b1    = (const float*)d_in[15];
    const float* f_W2    = (const float*)d_in[16];
    const float* f_b2    = (const float*)d_in[17];
    const float* seed    = (const float*)d_in[18];
    const float* p_Wq    = (const float*)d_in[19];
    const float* p_Wk    = (const float*)d_in[20];
    const float* p_Wv    = (const float*)d_in[21];
    const float* p_Wo    = (const float*)d_in[22];
    const float* out_W1  = (const float*)d_in[23];
    const float* out_b1  = (const float*)d_in[24];
    const float* out_W2  = (const float*)d_in[25];
    const float* out_b2  = (const float*)d_in[26];
    const int*   ei      = (const int*)d_in[27];

    float *p_h, *p_q, *p_k, *p_v, *p_a, *p_t, *p_feat, *p_qpool, *p_pool, *p_pool2;
    unsigned* p_mask;
    cudaGetSymbolAddress((void**)&p_h, g_h);
    cudaGetSymbolAddress((void**)&p_q, g_q);
    cudaGetSymbolAddress((void**)&p_k, g_k);
    cudaGetSymbolAddress((void**)&p_v, g_v);
    cudaGetSymbolAddress((void**)&p_a, g_a);
    cudaGetSymbolAddress((void**)&p_t, g_t);
    cudaGetSymbolAddress((void**)&p_feat, g_feat);
    cudaGetSymbolAddress((void**)&p_mask, g_mask);
    cudaGetSymbolAddress((void**)&p_qpool, g_qpool);
    cudaGetSymbolAddress((void**)&p_pool, g_pool);
    cudaGetSymbolAddress((void**)&p_pool2, g_pool2);

    cudaFuncSetAttribute(attn_kernel, cudaFuncAttributeMaxDynamicSharedMemorySize, 65536);
    cudaFuncSetAttribute(gemm_tf32_kernel, cudaFuncAttributeMaxDynamicSharedMemorySize,
                         SMEM_GEMM_BYTES);

    const int gBig = E_TOT / 128;   // 256 blocks
    dim3 gSmall(2, 1);

    // input MLP
    gather_feat_kernel<<<E_TOT, FEAT_DIM>>>(x, ea, ei, p_feat);
    build_mask_kernel<<<B, 256>>>(ei, p_mask);
    gemm_tf32_kernel<<<gBig, 256, SMEM_GEMM_BYTES>>>(p_feat, in_W1, in_b1, p_t, FEAT_DIM, 1);
    gemm_tf32_kernel<<<gBig, 256, SMEM_GEMM_BYTES>>>(p_t, in_W2, in_b2, p_h, HID, 0);

    // transformer layers: M, M, S
    for (int L = 0; L < 3; L++) {
        const float* wq = Wq + (size_t)L * HID * HID;
        const float* wk = Wk + (size_t)L * HID * HID;
        const float* wv = Wv + (size_t)L * HID * HID;
        const float* wo = Wo + (size_t)L * HID * HID;
        gemm_tf32_kernel<<<gBig, 256, SMEM_GEMM_BYTES>>>(p_h, wq, nullptr, p_q, HID, 0);
        gemm_tf32_kernel<<<gBig, 256, SMEM_GEMM_BYTES>>>(p_h, wk, nullptr, p_k, HID, 0);
        gemm_tf32_kernel<<<gBig, 256, SMEM_GEMM_BYTES>>>(p_h, wv, nullptr, p_v, HID, 0);
        attn_kernel<<<B * HEADS, 256, 65536>>>(p_q, p_k, p_v, p_a,
                                               (L < 2) ? p_mask : nullptr);
        gemm_tf32_kernel<<<gBig, 256, SMEM_GEMM_BYTES>>>(p_a, wo, nullptr, p_t, HID, 0);
        ln_res_kernel<<<E_TOT / 8, dim3(32, 8)>>>(p_h, p_t, ln1_g + L * HID, ln1_b + L * HID);
        gemm_tf32_kernel<<<gBig, 256, SMEM_GEMM_BYTES>>>(p_h, f_W1 + (size_t)L * HID * HID,
                                                         f_b1 + L * HID, p_t, HID, 1);
        gemm_tf32_kernel<<<gBig, 256, SMEM_GEMM_BYTES>>>(p_t, f_W2 + (size_t)L * HID * HID,
                                                         f_b2 + L * HID, p_a, HID, 0);
        ln_res_kernel<<<E_TOT / 8, dim3(32, 8)>>>(p_h, p_a, ln2_g + L * HID, ln2_b + L * HID);
    }

    // PMA pooling
    gemm_tf32_kernel<<<gBig, 256, SMEM_GEMM_BYTES>>>(p_h, p_Wk, nullptr, p_k, HID, 0);
    gemm_tf32_kernel<<<gBig, 256, SMEM_GEMM_BYTES>>>(p_h, p_Wv, nullptr, p_v, HID, 0);
    qpool_kernel<<<1, HID>>>(seed, p_Wq, p_qpool);
    pool_attn_kernel<<<B, 256>>>(p_qpool, p_k, p_v, p_pool);
    gemm_kernel<<<gSmall, 256>>>(p_pool, p_Wo, nullptr, p_pool2, HID, 0);

    // output MLP
    gemm_kernel<<<gSmall, 256>>>(p_pool2, out_W1, out_b1, p_pool, HID, 1);
    final_kernel<<<B, 32>>>(p_pool, out_W2, out_b2, (float*)d_out);
}

// round 8
// speedup vs baseline: 1.7985x; 1.1220x over previous
#include <cuda_runtime.h>
#include <cuda_bf16.h>

// ---------------- problem constants ----------------
#define B 64
#define EPG 512
#define E_TOT (B * EPG)        // 32768
#define NODE_DIM 64
#define EDGE_DIM 32
#define HID 128
#define HEADS 8
#define DH 16
#define FEAT_DIM 160           // 2*64 + 32

// smem strides (words). 40 ≡ 8 (mod 32), 136 ≡ 8 (mod 32):
// frag-load banks: A: 8g+t (bijection), B: 8t+g (bijection) -> conflict-free.
#define ASTRIDE 40
#define BSTRIDE 136
// double-buffered RAW fp32 staging (hi/lo split happens in registers)
#define SMEM_GEMM_BYTES ((2 * 128 * ASTRIDE + 2 * 32 * BSTRIDE) * 4)   // 75776

// ---------------- scratch (device globals; no allocs allowed) ----------------
__device__ float g_h[E_TOT * HID];
__device__ float g_q[E_TOT * HID];
__device__ float g_k[E_TOT * HID];
__device__ float g_v[E_TOT * HID];
__device__ float g_a[E_TOT * HID];
__device__ float g_t[E_TOT * HID];
__device__ float g_feat[E_TOT * FEAT_DIM];
__device__ unsigned g_mask[B * EPG * 16];   // 512 bits per (graph,row)
__device__ float g_qpool[HID];
__device__ float g_pool[B * HID];
__device__ float g_pool2[B * HID];

// ---------------- gather edge features ----------------
__global__ void gather_feat_kernel(const float* __restrict__ x,
                                   const float* __restrict__ ea,
                                   const int* __restrict__ ei,
                                   float* __restrict__ feat) {
    int e = blockIdx.x;
    int c = threadIdx.x;            // 160 threads
    int s = ei[e];
    int d = ei[E_TOT + e];
    float val;
    if (c < 64)       val = x[(size_t)s * NODE_DIM + c];
    else if (c < 128) val = x[(size_t)d * NODE_DIM + (c - 64)];
    else              val = ea[(size_t)e * EDGE_DIM + (c - 128)];
    feat[(size_t)e * FEAT_DIM + c] = val;
}

// ---------------- adjacency bitmask (edges sharing a node) ----------------
__global__ void build_mask_kernel(const int* __restrict__ ei,
                                  unsigned* __restrict__ mask) {
    int b = blockIdx.x;
    __shared__ int ss[EPG];
    __shared__ int dd[EPG];
    for (int i = threadIdx.x; i < EPG; i += blockDim.x) {
        ss[i] = ei[b * EPG + i];
        dd[i] = ei[E_TOT + b * EPG + i];
    }
    __syncthreads();
    for (int i = threadIdx.x; i < EPG; i += blockDim.x) {
        int si = ss[i], di = dd[i];
        for (int w = 0; w < 16; w++) {
            unsigned bits = 0;
            #pragma unroll
            for (int jj = 0; jj < 32; jj++) {
                int j = (w << 5) + jj;
                int sj = ss[j], dj = dd[j];
                bool adj = (si == sj) | (si == dj) | (di == sj) | (di == dj) | (i == j);
                bits |= (unsigned)adj << jj;
            }
            mask[((size_t)b * EPG + i) * 16 + w] = bits;
        }
    }
}

// ---------------- tf32 / cp.async helpers ----------------
__device__ __forceinline__ unsigned f2tf32u(float f) {
    unsigned u;
    asm("cvt.rna.tf32.f32 %0, %1;" : "=r"(u) : "f"(f));
    return u;
}

__device__ __forceinline__ void split_tf32(float x, unsigned& hi, unsigned& lo) {
    hi = f2tf32u(x);
    lo = f2tf32u(x - __uint_as_float(hi));
}

__device__ __forceinline__ void cp_async16(unsigned smem_addr, const void* gptr) {
    asm volatile("cp.async.cg.shared.global [%0], [%1], 16;\n"
                 :: "r"(smem_addr), "l"(gptr));
}

__device__ __forceinline__ void mma_tf32(float* c,
                                         unsigned a0, unsigned a1, unsigned a2, unsigned a3,
                                         unsigned b0, unsigned b1) {
    asm volatile("mma.sync.aligned.m16n8k8.row.col.f32.tf32.tf32.f32 "
                 "{%0,%1,%2,%3}, {%4,%5,%6,%7}, {%8,%9}, {%0,%1,%2,%3};"
                 : "+f"(c[0]), "+f"(c[1]), "+f"(c[2]), "+f"(c[3])
                 : "r"(a0), "r"(a1), "r"(a2), "r"(a3), "r"(b0), "r"(b1));
}

// ---------------- 3xTF32 tensor-core GEMM: C[M,128] = act(A@W + bias) -----------
// C = Ah*Bh + Ah*Bl + Al*Bh (split in REGISTERS; smem stages raw fp32 via cp.async,
// double-buffered). Block: 128m x 128n, BK=32, 256 threads, 8 warps (4m x 2n).
// grid.y in {1,2,3} selects W/C (fused QKV / PMA-KV launches share A).
__global__ void __launch_bounds__(256, 2)
gemm_tf32_kernel(const float* __restrict__ A,
                 const float* __restrict__ W0, const float* __restrict__ W1,
                 const float* __restrict__ W2,
                 float* __restrict__ C0, float* __restrict__ C1, float* __restrict__ C2,
                 const float* __restrict__ bias, int K, int relu) {
    const float* W = (blockIdx.y == 0) ? W0 : (blockIdx.y == 1 ? W1 : W2);
    float* C       = (blockIdx.y == 0) ? C0 : (blockIdx.y == 1 ? C1 : C2);

    extern __shared__ float sm[];
    float* Abuf[2] = { sm, sm + 128 * ASTRIDE };
    float* Bbuf[2] = { sm + 2 * 128 * ASTRIDE, sm + 2 * 128 * ASTRIDE + 32 * BSTRIDE };

    const int tid = threadIdx.x;
    const int lane = tid & 31;
    const int wid = tid >> 5;
    const int wm = wid >> 1;       // 0..3 -> M offset 32*wm
    const int wn = wid & 1;        // 0..1 -> N offset 64*wn
    const int g = lane >> 2;
    const int t = lane & 3;
    const int bm = blockIdx.x * 128;

    float acc[2][8][4];
    #pragma unroll
    for (int i = 0; i < 2; i++)
        #pragma unroll
        for (int j = 0; j < 8; j++)
            #pragma unroll
            for (int r = 0; r < 4; r++) acc[i][j][r] = 0.f;

    const int nst = K >> 5;   // BK = 32 (K = 128 or 160)

    // per-thread loader geometry (1024 float4 per operand slab)
    const int a_r  = tid >> 3;          // handled rows: a_r + 32u is wrong; f = tid+256u:
    // f>>3 for u: rows tid>>3 + 32u ; c4 = tid&7 (constant across u since 256%8==0)
    const int a_c4 = tid & 7;
    const int b_n4 = tid & 31;          // constant across u (256%32==0)
    // smem base addrs (u32) for cp.async
    const unsigned sA0 = (unsigned)__cvta_generic_to_shared(Abuf[0]);
    const unsigned sA1 = (unsigned)__cvta_generic_to_shared(Abuf[1]);
    const unsigned sB0 = (unsigned)__cvta_generic_to_shared(Bbuf[0]);
    const unsigned sB1 = (unsigned)__cvta_generic_to_shared(Bbuf[1]);

    auto load_stage = [&](int buf, int s) {
        const int k0 = s * 32;
        const unsigned sA = buf ? sA1 : sA0;
        const unsigned sB = buf ? sB1 : sB0;
        #pragma unroll
        for (int u = 0; u < 4; u++) {
            int rA = (tid >> 3) + 32 * u;
            cp_async16(sA + (unsigned)((rA * ASTRIDE + a_c4 * 4) << 2),
                       A + (size_t)(bm + rA) * K + k0 + a_c4 * 4);
            int rB = (tid >> 5) + 8 * u;
            cp_async16(sB + (unsigned)((rB * BSTRIDE + b_n4 * 4) << 2),
                       W + (size_t)(k0 + rB) * 128 + b_n4 * 4);
        }
        asm volatile("cp.async.commit_group;\n" ::: "memory");
    };

    // prologue: fill both buffers
    load_stage(0, 0);
    if (nst > 1) load_stage(1, 1);

    for (int s = 0; s < nst; s++) {
        if (s + 1 < nst)
            asm volatile("cp.async.wait_group 1;\n" ::: "memory");
        else
            asm volatile("cp.async.wait_group 0;\n" ::: "memory");
        __syncthreads();

        const float* As = Abuf[s & 1];
        const float* Bs = Bbuf[s & 1];

        #pragma unroll
        for (int kq = 0; kq < 4; kq++) {
            const int koff = kq * 8;
            unsigned ah[2][4], al[2][4];
            #pragma unroll
            for (int i = 0; i < 2; i++) {
                int m0 = wm * 32 + i * 16;
                const float* p0 = As + (m0 + g) * ASTRIDE + koff + t;
                const float* p1 = As + (m0 + g + 8) * ASTRIDE + koff + t;
                split_tf32(p0[0], ah[i][0], al[i][0]);
                split_tf32(p1[0], ah[i][1], al[i][1]);
                split_tf32(p0[4], ah[i][2], al[i][2]);
                split_tf32(p1[4], ah[i][3], al[i][3]);
            }
            #pragma unroll
            for (int j = 0; j < 8; j++) {
                int n0 = wn * 64 + j * 8;
                unsigned bh0, bl0, bh1, bl1;
                split_tf32(Bs[(koff + t) * BSTRIDE + n0 + g], bh0, bl0);
                split_tf32(Bs[(koff + t + 4) * BSTRIDE + n0 + g], bh1, bl1);
                #pragma unroll
                for (int i = 0; i < 2; i++) {
                    float* cc = acc[i][j];
                    mma_tf32(cc, ah[i][0], ah[i][1], ah[i][2], ah[i][3], bl0, bl1);
                    mma_tf32(cc, al[i][0], al[i][1], al[i][2], al[i][3], bh0, bh1);
                    mma_tf32(cc, ah[i][0], ah[i][1], ah[i][2], ah[i][3], bh0, bh1);
                }
            }
        }
        __syncthreads();   // all warps done with buf (s&1) before it's reloaded
        if (s + 2 < nst) load_stage(s & 1, s + 2);
    }

    // epilogue: c0:(g,2t) c1:(g,2t+1) c2:(g+8,2t) c3:(g+8,2t+1)
    #pragma unroll
    for (int i = 0; i < 2; i++) {
        int row0 = bm + wm * 32 + i * 16 + g;
        #pragma unroll
        for (int j = 0; j < 8; j++) {
            int col = wn * 64 + j * 8 + t * 2;
            float bv0 = bias ? bias[col] : 0.f;
            float bv1 = bias ? bias[col + 1] : 0.f;
            float v0 = acc[i][j][0] + bv0, v1 = acc[i][j][1] + bv1;
            float v2 = acc[i][j][2] + bv0, v3 = acc[i][j][3] + bv1;
            if (relu) {
                v0 = fmaxf(v0, 0.f); v1 = fmaxf(v1, 0.f);
                v2 = fmaxf(v2, 0.f); v3 = fmaxf(v3, 0.f);
            }
            *(float2*)&C[(size_t)row0 * 128 + col] = make_float2(v0, v1);
            *(float2*)&C[(size_t)(row0 + 8) * 128 + col] = make_float2(v2, v3);
        }
    }
}

// ---------------- small SGEMM (M=64 pool path) ----------------
__global__ void gemm_kernel(const float* __restrict__ A,
                            const float* __restrict__ W,
                            const float* __restrict__ bias,
                            float* __restrict__ C,
                            int K, int relu) {
    __shared__ __align__(16) float As[16][68];
    __shared__ __align__(16) float Ws[16][68];
    int bm = blockIdx.y * 64;
    int bn = blockIdx.x * 64;
    int tid = threadIdx.x;
    int tx = tid & 15;
    int ty = tid >> 4;
    float acc[4][4] = {};

    for (int k0 = 0; k0 < K; k0 += 16) {
        #pragma unroll
        for (int i = tid; i < 1024; i += 256) {
            int r = i >> 4, c = i & 15;
            As[c][r] = A[(size_t)(bm + r) * K + k0 + c];
        }
        #pragma unroll
        for (int i = tid; i < 1024; i += 256) {
            int r = i >> 6, c = i & 63;
            Ws[r][c] = W[(size_t)(k0 + r) * 128 + bn + c];
        }
        __syncthreads();
        #pragma unroll
        for (int kk = 0; kk < 16; kk++) {
            float4 av = *(const float4*)&As[kk][ty * 4];
            float4 wv = *(const float4*)&Ws[kk][tx * 4];
            float a[4] = {av.x, av.y, av.z, av.w};
            float w[4] = {wv.x, wv.y, wv.z, wv.w};
            #pragma unroll
            for (int i = 0; i < 4; i++)
                #pragma unroll
                for (int j = 0; j < 4; j++)
                    acc[i][j] += a[i] * w[j];
        }
        __syncthreads();
    }
    #pragma unroll
    for (int i = 0; i < 4; i++) {
        int row = bm + ty * 4 + i;
        float4 out;
        float* po = (float*)&out;
        #pragma unroll
        for (int j = 0; j < 4; j++) {
            int col = bn + tx * 4 + j;
            float vv = acc[i][j] + (bias ? bias[col] : 0.f);
            if (relu) vv = fmaxf(vv, 0.f);
            po[j] = vv;
        }
        *(float4*)&C[(size_t)row * 128 + bn + tx * 4] = out;
    }
}

// ---------------- residual + LayerNorm (in-place on h) ----------------
__global__ void ln_res_kernel(float* __restrict__ h, const float* __restrict__ a,
                              const float* __restrict__ g, const float* __restrict__ bb) {
    int row = blockIdx.x * 8 + threadIdx.y;
    int lane = threadIdx.x;
    float* hp = h + (size_t)row * HID;
    const float* ap = a + (size_t)row * HID;
    float vals[4];
    float sum = 0.f, sum2 = 0.f;
    #pragma unroll
    for (int i = 0; i < 4; i++) {
        int c = lane + 32 * i;
        float t = hp[c] + ap[c];
        vals[i] = t;
        sum += t;
        sum2 += t * t;
    }
    #pragma unroll
    for (int off = 16; off > 0; off >>= 1) {
        sum  += __shfl_xor_sync(0xFFFFFFFFu, sum, off);
        sum2 += __shfl_xor_sync(0xFFFFFFFFu, sum2, off);
    }
    float mean = sum * (1.f / HID);
    float var = sum2 * (1.f / HID) - mean * mean;
    float inv = rsqrtf(var + 1e-5f);
    #pragma unroll
    for (int i = 0; i < 4; i++) {
        int c = lane + 32 * i;
        hp[c] = (vals[i] - mean) * inv * g[c] + bb[c];
    }
}

// ---------------- masked / full multi-head attention ----------------
// Scores are small (LN-normalized inputs, 0.02-scale weights), so plain exp
// without max subtraction is numerically safe.
__global__ void attn_kernel(const float* __restrict__ q, const float* __restrict__ k,
                            const float* __restrict__ v, float* __restrict__ o,
                            const unsigned* __restrict__ mask) {
    extern __shared__ float4 sm4[];
    float4* kd = sm4;           // 2048 float4
    float4* vd = sm4 + 2048;
    int b = blockIdx.x >> 3;
    int h = blockIdx.x & 7;
    int base = b * EPG;
    const float* kp = k + (size_t)base * HID + h * DH;
    const float* vp = v + (size_t)base * HID + h * DH;
    for (int i = threadIdx.x; i < 2048; i += 256) {
        int r = i >> 2, c = i & 3;
        kd[i] = *(const float4*)(kp + (size_t)r * HID + c * 4);
        vd[i] = *(const float4*)(vp + (size_t)r * HID + c * 4);
    }
    __syncthreads();

    if (mask != nullptr) {
        // sparse path: rows have distinct masks -> per-row key iteration
        #pragma unroll
        for (int rr = 0; rr < 2; rr++) {
            int i = threadIdx.x + rr * 256;
            const float* qp = q + (size_t)(base + i) * HID + h * DH;
            float4 q0 = *(const float4*)(qp + 0);
            float4 q1 = *(const float4*)(qp + 4);
            float4 q2 = *(const float4*)(qp + 8);
            float4 q3 = *(const float4*)(qp + 12);

            float l = 0.f;
            float4 a0 = {0,0,0,0}, a1 = {0,0,0,0}, a2 = {0,0,0,0}, a3 = {0,0,0,0};

            const unsigned* mp = mask + (size_t)(base + i) * 16;
            #pragma unroll
            for (int w = 0; w < 16; w++) {
                unsigned bits = mp[w];
                while (bits) {
                    int jj = __ffs(bits) - 1;
                    bits &= bits - 1;
                    int j = (w << 5) + jj;
                    const float4 k0 = kd[4*j+0], k1 = kd[4*j+1], k2 = kd[4*j+2], k3 = kd[4*j+3];
                    float s = q0.x*k0.x + q0.y*k0.y + q0.z*k0.z + q0.w*k0.w
                            + q1.x*k1.x + q1.y*k1.y + q1.z*k1.z + q1.w*k1.w
                            + q2.x*k2.x + q2.y*k2.y + q2.z*k2.z + q2.w*k2.w
                            + q3.x*k3.x + q3.y*k3.y + q3.z*k3.z + q3.w*k3.w;
                    float p = __expf(s * 0.25f);   // 1/sqrt(16)
                    l += p;
                    const float4 v0 = vd[4*j+0], v1 = vd[4*j+1], v2 = vd[4*j+2], v3 = vd[4*j+3];
                    a0.x += p*v0.x; a0.y += p*v0.y; a0.z += p*v0.z; a0.w += p*v0.w;
                    a1.x += p*v1.x; a1.y += p*v1.y; a1.z += p*v1.z; a1.w += p*v1.w;
                    a2.x += p*v2.x; a2.y += p*v2.y; a2.z += p*v2.z; a2.w += p*v2.w;
                    a3.x += p*v3.x; a3.y += p*v3.y; a3.z += p*v3.z; a3.w += p*v3.w;
                }
            }

            float inv = 1.f / l;
            float* op = o + (size_t)(base + i) * HID + h * DH;
            *(float4*)(op + 0)  = make_float4(a0.x*inv, a0.y*inv, a0.z*inv, a0.w*inv);
            *(float4*)(op + 4)  = make_float4(a1.x*inv, a1.y*inv, a1.z*inv, a1.w*inv);
            *(float4*)(op + 8)  = make_float4(a2.x*inv, a2.y*inv, a2.z*inv, a2.w*inv);
            *(float4*)(op + 12) = make_float4(a3.x*inv, a3.y*inv, a3.z*inv, a3.w*inv);
        }
    } else {
        // dense path: both rows share every K/V read
        float4 qa[2][4];
        #pragma unroll
        for (int rr = 0; rr < 2; rr++) {
            const float* qp = q + (size_t)(base + threadIdx.x + rr * 256) * HID + h * DH;
            qa[rr][0] = *(const float4*)(qp + 0);
            qa[rr][1] = *(const float4*)(qp + 4);
            qa[rr][2] = *(const float4*)(qp + 8);
            qa[rr][3] = *(const float4*)(qp + 12);
        }
        float l[2] = {0.f, 0.f};
        float4 ac[2][4];
        #pragma unroll
        for (int rr = 0; rr < 2; rr++)
            #pragma unroll
            for (int c = 0; c < 4; c++) ac[rr][c] = make_float4(0.f, 0.f, 0.f, 0.f);

        #pragma unroll 2
        for (int j = 0; j < EPG; j++) {
            const float4 k0 = kd[4*j+0], k1 = kd[4*j+1], k2 = kd[4*j+2], k3 = kd[4*j+3];
            const float4 v0 = vd[4*j+0], v1 = vd[4*j+1], v2 = vd[4*j+2], v3 = vd[4*j+3];
            #pragma unroll
            for (int rr = 0; rr < 2; rr++) {
                float s = qa[rr][0].x*k0.x + qa[rr][0].y*k0.y + qa[rr][0].z*k0.z + qa[rr][0].w*k0.w
                        + qa[rr][1].x*k1.x + qa[rr][1].y*k1.y + qa[rr][1].z*k1.z + qa[rr][1].w*k1.w
                        + qa[rr][2].x*k2.x + qa[rr][2].y*k2.y + qa[rr][2].z*k2.z + qa[rr][2].w*k2.w
                        + qa[rr][3].x*k3.x + qa[rr][3].y*k3.y + qa[rr][3].z*k3.z + qa[rr][3].w*k3.w;
                float p = __expf(s * 0.25f);
                l[rr] += p;
                ac[rr][0].x += p*v0.x; ac[rr][0].y += p*v0.y; ac[rr][0].z += p*v0.z; ac[rr][0].w += p*v0.w;
                ac[rr][1].x += p*v1.x; ac[rr][1].y += p*v1.y; ac[rr][1].z += p*v1.z; ac[rr][1].w += p*v1.w;
                ac[rr][2].x += p*v2.x; ac[rr][2].y += p*v2.y; ac[rr][2].z += p*v2.z; ac[rr][2].w += p*v2.w;
                ac[rr][3].x += p*v3.x; ac[rr][3].y += p*v3.y; ac[rr][3].z += p*v3.z; ac[rr][3].w += p*v3.w;
            }
        }
        #pragma unroll
        for (int rr = 0; rr < 2; rr++) {
            float inv = 1.f / l[rr];
            float* op = o + (size_t)(base + threadIdx.x + rr * 256) * HID + h * DH;
            #pragma unroll
            for (int c = 0; c < 4; c++)
                *(float4*)(op + 4 * c) = make_float4(ac[rr][c].x*inv, ac[rr][c].y*inv,
                                                     ac[rr][c].z*inv, ac[rr][c].w*inv);
        }
    }
}

// ---------------- pooling: qpool = seed @ p_Wq ----------------
__global__ void qpool_kernel(const float* __restrict__ seed, const float* __restrict__ Wq,
                             float* __restrict__ qpool) {
    int c = threadIdx.x;   // 128
    float s = 0.f;
    for (int kk = 0; kk < HID; kk++) s += seed[kk] * Wq[(size_t)kk * HID + c];
    qpool[c] = s;
}

// ---------------- PMA attention: 1 query per graph, full mask ----------------
__global__ void pool_attn_kernel(const float* __restrict__ qpool, const float* __restrict__ k,
                                 const float* __restrict__ v, float* __restrict__ pool) {
    int b = blockIdx.x;
    int w = threadIdx.x >> 5;     // head
    int lane = threadIdx.x & 31;
    float qr[DH];
    #pragma unroll
    for (int d = 0; d < DH; d++) qr[d] = qpool[w * DH + d];

    float s[16];
    float mloc = -1e30f;
    #pragma unroll
    for (int t = 0; t < 16; t++) {
        int j = lane + t * 32;
        const float* kp = k + (size_t)(b * EPG + j) * HID + w * DH;
        float acc = 0.f;
        #pragma unroll
        for (int d = 0; d < DH; d++) acc += qr[d] * kp[d];
        s[t] = acc * 0.25f;
        mloc = fmaxf(mloc, s[t]);
    }
    #pragma unroll
    for (int off = 16; off > 0; off >>= 1)
        mloc = fmaxf(mloc, __shfl_xor_sync(0xFFFFFFFFu, mloc, off));

    float l = 0.f;
    float acc[DH];
    #pragma unroll
    for (int d = 0; d < DH; d++) acc[d] = 0.f;
    #pragma unroll
    for (int t = 0; t < 16; t++) {
        int j = lane + t * 32;
        float p = __expf(s[t] - mloc);
        l += p;
        const float* vp = v + (size_t)(b * EPG + j) * HID + w * DH;
        #pragma unroll
        for (int d = 0; d < DH; d++) acc[d] += p * vp[d];
    }
    #pragma unroll
    for (int off = 16; off > 0; off >>= 1) {
        l += __shfl_xor_sync(0xFFFFFFFFu, l, off);
        #pragma unroll
        for (int d = 0; d < DH; d++)
            acc[d] += __shfl_xor_sync(0xFFFFFFFFu, acc[d], off);
    }
    if (lane == 0) {
        float inv = 1.f / l;
        #pragma unroll
        for (int d = 0; d < DH; d++)
            pool[(size_t)b * HID + w * DH + d] = acc[d] * inv;
    }
}

// ---------------- final: out[b] = o1[b] . out_W2 + out_b2 ----------------
__global__ void final_kernel(const float* __restrict__ o1, const float* __restrict__ W2,
                             const float* __restrict__ b2, float* __restrict__ out) {
    int b = blockIdx.x;
    int lane = threadIdx.x;
    float s = 0.f;
    #pragma unroll
    for (int i = 0; i < 4; i++) {
        int c = lane + 32 * i;
        s += o1[(size_t)b * HID + c] * W2[c];
    }
    #pragma unroll
    for (int off = 16; off > 0; off >>= 1)
        s += __shfl_xor_sync(0xFFFFFFFFu, s, off);
    if (lane == 0) out[b] = s + b2[0];
}

// ---------------- host launch ----------------
extern "C" void kernel_launch(void* const* d_in, const int* in_sizes, int n_in,
                              void* d_out, int out_size) {
    const float* x       = (const float*)d_in[0];
    const float* ea      = (const float*)d_in[1];
    const float* in_W1   = (const float*)d_in[2];
    const float* in_b1   = (const float*)d_in[3];
    const float* in_W2   = (const float*)d_in[4];
    const float* in_b2   = (const float*)d_in[5];
    const float* Wq      = (const float*)d_in[6];
    const float* Wk      = (const float*)d_in[7];
    const float* Wv      = (const float*)d_in[8];
    const float* Wo      = (const float*)d_in[9];
    const float* ln1_g   = (const float*)d_in[10];
    const float* ln1_b   = (const float*)d_in[11];
    const float* ln2_g   = (const float*)d_in[12];
    const float* ln2_b   = (const float*)d_in[13];
    const float* f_W1    = (const float*)d_in[14];
    const float* f_b1    = (const float*)d_in[15];
    const float* f_W2    = (const float*)d_in[16];
    const float* f_b2    = (const float*)d_in[17];
    const float* seed    = (const float*)d_in[18];
    const float* p_Wq    = (const float*)d_in[19];
    const float* p_Wk    = (const float*)d_in[20];
    const float* p_Wv    = (const float*)d_in[21];
    const float* p_Wo    = (const float*)d_in[22];
    const float* out_W1  = (const float*)d_in[23];
    const float* out_b1  = (const float*)d_in[24];
    const float* out_W2  = (const float*)d_in[25];
    const float* out_b2  = (const float*)d_in[26];
    const int*   ei      = (const int*)d_in[27];

    float *p_h, *p_q, *p_k, *p_v, *p_a, *p_t, *p_feat, *p_qpool, *p_pool, *p_pool2;
    unsigned* p_mask;
    cudaGetSymbolAddress((void**)&p_h, g_h);
    cudaGetSymbolAddress((void**)&p_q, g_q);
    cudaGetSymbolAddress((void**)&p_k, g_k);
    cudaGetSymbolAddress((void**)&p_v, g_v);
    cudaGetSymbolAddress((void**)&p_a, g_a);
    cudaGetSymbolAddress((void**)&p_t, g_t);
    cudaGetSymbolAddress((void**)&p_feat, g_feat);
    cudaGetSymbolAddress((void**)&p_mask, g_mask);
    cudaGetSymbolAddress((void**)&p_qpool, g_qpool);
    cudaGetSymbolAddress((void**)&p_pool, g_pool);
    cudaGetSymbolAddress((void**)&p_pool2, g_pool2);

    cudaFuncSetAttribute(attn_kernel, cudaFuncAttributeMaxDynamicSharedMemorySize, 65536);
    cudaFuncSetAttribute(gemm_tf32_kernel, cudaFuncAttributeMaxDynamicSharedMemorySize,
                         SMEM_GEMM_BYTES);

    const dim3 g1(E_TOT / 128, 1);   // single-W
    const dim3 g2(E_TOT / 128, 2);   // fused 2-W
    const dim3 g3(E_TOT / 128, 3);   // fused 3-W
    dim3 gSmall(2, 1);

    // input MLP
    gather_feat_kernel<<<E_TOT, FEAT_DIM>>>(x, ea, ei, p_feat);
    build_mask_kernel<<<B, 256>>>(ei, p_mask);
    gemm_tf32_kernel<<<g1, 256, SMEM_GEMM_BYTES>>>(p_feat, in_W1, in_W1, in_W1,
                                                   p_t, p_t, p_t, in_b1, FEAT_DIM, 1);
    gemm_tf32_kernel<<<g1, 256, SMEM_GEMM_BYTES>>>(p_t, in_W2, in_W2, in_W2,
                                                   p_h, p_h, p_h, in_b2, HID, 0);

    // transformer layers: M, M, S
    for (int L = 0; L < 3; L++) {
        const float* wq = Wq + (size_t)L * HID * HID;
        const float* wk = Wk + (size_t)L * HID * HID;
        const float* wv = Wv + (size_t)L * HID * HID;
        const float* wo = Wo + (size_t)L * HID * HID;
        gemm_tf32_kernel<<<g3, 256, SMEM_GEMM_BYTES>>>(p_h, wq, wk, wv,
                                                       p_q, p_k, p_v, nullptr, HID, 0);
        attn_kernel<<<B * HEADS, 256, 65536>>>(p_q, p_k, p_v, p_a,
                                               (L < 2) ? p_mask : nullptr);
        gemm_tf32_kernel<<<g1, 256, SMEM_GEMM_BYTES>>>(p_a, wo, wo, wo,
                                                       p_t, p_t, p_t, nullptr, HID, 0);
        ln_res_kernel<<<E_TOT / 8, dim3(32, 8)>>>(p_h, p_t, ln1_g + L * HID, ln1_b + L * HID);
        gemm_tf32_kernel<<<g1, 256, SMEM_GEMM_BYTES>>>(p_h,
            f_W1 + (size_t)L * HID * HID, f_W1 + (size_t)L * HID * HID,
            f_W1 + (size_t)L * HID * HID, p_t, p_t, p_t, f_b1 + L * HID, HID, 1);
        gemm_tf32_kernel<<<g1, 256, SMEM_GEMM_BYTES>>>(p_t,
            f_W2 + (size_t)L * HID * HID, f_W2 + (size_t)L * HID * HID,
            f_W2 + (size_t)L * HID * HID, p_a, p_a, p_a, f_b2 + L * HID, HID, 0);
        ln_res_kernel<<<E_TOT / 8, dim3(32, 8)>>>(p_h, p_a, ln2_g + L * HID, ln2_b + L * HID);
    }

    // PMA pooling (fused K/V projection)
    gemm_tf32_kernel<<<g2, 256, SMEM_GEMM_BYTES>>>(p_h, p_Wk, p_Wv, p_Wv,
                                                   p_k, p_v, p_v, nullptr, HID, 0);
    qpool_kernel<<<1, HID>>>(seed, p_Wq, p_qpool);
    pool_attn_kernel<<<B, 256>>>(p_qpool, p_k, p_v, p_pool);
    gemm_kernel<<<gSmall, 256>>>(p_pool, p_Wo, nullptr, p_pool2, HID, 0);

    // output MLP
    gemm_kernel<<<gSmall, 256>>>(p_pool2, out_W1, out_b1, p_pool, HID, 1);
    final_kernel<<<B, 32>>>(p_pool, out_W2, out_b2, (float*)d_out);
}

// round 9
// speedup vs baseline: 1.8394x; 1.0227x over previous
#include <cuda_runtime.h>
#include <cuda_bf16.h>

// ---------------- problem constants ----------------
#define B 64
#define EPG 512
#define E_TOT (B * EPG)        // 32768
#define NODE_DIM 64
#define EDGE_DIM 32
#define HID 128
#define HEADS 8
#define DH 16
#define FEAT_DIM 160           // 2*64 + 32

// smem strides (words). 40 ≡ 8 (mod 32), 136 ≡ 8 (mod 32):
// frag-load banks: A: 8g+t (bijection), B: 8t+g (bijection) -> conflict-free.
#define ASTRIDE 40
#define BSTRIDE 136
// A raw double-buffered + B hi/lo double-buffered
#define SMEM_GEMM_BYTES ((2 * 128 * ASTRIDE + 4 * 32 * BSTRIDE) * 4)   // 110592

// pre-split weight scratch offsets (floats)
#define O_INW1 0
#define O_INW2 20480
#define O_WQ   36864
#define O_WK   86016
#define O_WV   135168
#define O_WO   184320
#define O_FW1  233472
#define O_FW2  282624
#define O_PWK  331776
#define O_PWV  348160
#define W_TOTAL 364544

// ---------------- scratch (device globals; no allocs allowed) ----------------
__device__ float g_h[E_TOT * HID];
__device__ float g_q[E_TOT * HID];
__device__ float g_k[E_TOT * HID];
__device__ float g_v[E_TOT * HID];
__device__ float g_a[E_TOT * HID];
__device__ float g_t[E_TOT * HID];
__device__ float g_feat[E_TOT * FEAT_DIM];
__device__ unsigned g_mask[B * EPG * 16];   // 512 bits per (graph,row)
__device__ float g_whi[W_TOTAL];
__device__ float g_wlo[W_TOTAL];
__device__ float g_qpool[HID];
__device__ float g_pool[B * HID];
__device__ float g_pool2[B * HID];

// ---------------- tf32 / cp.async helpers ----------------
__device__ __forceinline__ unsigned f2tf32u(float f) {
    unsigned u;
    asm("cvt.rna.tf32.f32 %0, %1;" : "=r"(u) : "f"(f));
    return u;
}

__device__ __forceinline__ void split_tf32(float x, unsigned& hi, unsigned& lo) {
    hi = f2tf32u(x);
    lo = f2tf32u(x - __uint_as_float(hi));
}

__device__ __forceinline__ void cp_async16(unsigned smem_addr, const void* gptr) {
    asm volatile("cp.async.cg.shared.global [%0], [%1], 16;\n"
                 :: "r"(smem_addr), "l"(gptr));
}

__device__ __forceinline__ void mma_tf32(float* c,
                                         unsigned a0, unsigned a1, unsigned a2, unsigned a3,
                                         unsigned b0, unsigned b1) {
    asm volatile("mma.sync.aligned.m16n8k8.row.col.f32.tf32.tf32.f32 "
                 "{%0,%1,%2,%3}, {%4,%5,%6,%7}, {%8,%9}, {%0,%1,%2,%3};"
                 : "+f"(c[0]), "+f"(c[1]), "+f"(c[2]), "+f"(c[3])
                 : "r"(a0), "r"(a1), "r"(a2), "r"(a3), "r"(b0), "r"(b1));
}

// ---------------- one-shot weight pre-split: w -> (tf32 hi, tf32 lo) ----------------
__global__ void split_w_kernel(const float* __restrict__ w0, const float* __restrict__ w1,
                               const float* __restrict__ w2, const float* __restrict__ w3,
                               const float* __restrict__ w4, const float* __restrict__ w5,
                               const float* __restrict__ w6, const float* __restrict__ w7,
                               const float* __restrict__ w8, const float* __restrict__ w9,
                               float* __restrict__ hi, float* __restrict__ lo) {
    int idx = blockIdx.x * 256 + threadIdx.x;
    float v;
    if      (idx < O_INW2) v = w0[idx - O_INW1];
    else if (idx < O_WQ)   v = w1[idx - O_INW2];
    else if (idx < O_WK)   v = w2[idx - O_WQ];
    else if (idx < O_WV)   v = w3[idx - O_WK];
    else if (idx < O_WO)   v = w4[idx - O_WV];
    else if (idx < O_FW1)  v = w5[idx - O_WO];
    else if (idx < O_FW2)  v = w6[idx - O_FW1];
    else if (idx < O_PWK)  v = w7[idx - O_FW2];
    else if (idx < O_PWV)  v = w8[idx - O_PWK];
    else                   v = w9[idx - O_PWV];
    unsigned h = f2tf32u(v);
    hi[idx] = __uint_as_float(h);
    lo[idx] = __uint_as_float(f2tf32u(v - __uint_as_float(h)));
}

// ---------------- gather edge features ----------------
__global__ void gather_feat_kernel(const float* __restrict__ x,
                                   const float* __restrict__ ea,
                                   const int* __restrict__ ei,
                                   float* __restrict__ feat) {
    int e = blockIdx.x;
    int c = threadIdx.x;            // 160 threads
    int s = ei[e];
    int d = ei[E_TOT + e];
    float val;
    if (c < 64)       val = x[(size_t)s * NODE_DIM + c];
    else if (c < 128) val = x[(size_t)d * NODE_DIM + (c - 64)];
    else              val = ea[(size_t)e * EDGE_DIM + (c - 128)];
    feat[(size_t)e * FEAT_DIM + c] = val;
}

// ---------------- adjacency bitmask (edges sharing a node) ----------------
__global__ void build_mask_kernel(const int* __restrict__ ei,
                                  unsigned* __restrict__ mask) {
    int b = blockIdx.x;
    __shared__ int ss[EPG];
    __shared__ int dd[EPG];
    for (int i = threadIdx.x; i < EPG; i += blockDim.x) {
        ss[i] = ei[b * EPG + i];
        dd[i] = ei[E_TOT + b * EPG + i];
    }
    __syncthreads();
    for (int i = threadIdx.x; i < EPG; i += blockDim.x) {
        int si = ss[i], di = dd[i];
        for (int w = 0; w < 16; w++) {
            unsigned bits = 0;
            #pragma unroll
            for (int jj = 0; jj < 32; jj++) {
                int j = (w << 5) + jj;
                int sj = ss[j], dj = dd[j];
                bool adj = (si == sj) | (si == dj) | (di == sj) | (di == dj) | (i == j);
                bits |= (unsigned)adj << jj;
            }
            mask[((size_t)b * EPG + i) * 16 + w] = bits;
        }
    }
}

// ---------------- 3xTF32 tensor-core GEMM: C[M,128] = act(A@W + bias) -----------
// C = Ah*Bh + Ah*Bl + Al*Bh. W is PRE-SPLIT in global (Whi/Wlo) -> no B-split ALU.
// A staged raw via cp.async, split in registers (amortized over 8 n-tiles).
// Block: 128m x 128n, BK=32, 256 threads, 8 warps (4m x 2n), double-buffered.
// grid.y in {1,2,3} selects W/C (fused QKV / PMA-KV launches share A).
__global__ void __launch_bounds__(256, 2)
gemm_tf32_kernel(const float* __restrict__ A,
                 const float* __restrict__ Whi0, const float* __restrict__ Whi1,
                 const float* __restrict__ Whi2,
                 const float* __restrict__ Wlo0, const float* __restrict__ Wlo1,
                 const float* __restrict__ Wlo2,
                 float* __restrict__ C0, float* __restrict__ C1, float* __restrict__ C2,
                 const float* __restrict__ bias, int K, int relu) {
    const float* WH = (blockIdx.y == 0) ? Whi0 : (blockIdx.y == 1 ? Whi1 : Whi2);
    const float* WL = (blockIdx.y == 0) ? Wlo0 : (blockIdx.y == 1 ? Wlo1 : Wlo2);
    float* C        = (blockIdx.y == 0) ? C0   : (blockIdx.y == 1 ? C1   : C2);

    extern __shared__ float sm[];
    float* Abuf[2]  = { sm, sm + 128 * ASTRIDE };
    float* BHbuf[2] = { sm + 2 * 128 * ASTRIDE,
                        sm + 2 * 128 * ASTRIDE + 32 * BSTRIDE };
    float* BLbuf[2] = { sm + 2 * 128 * ASTRIDE + 2 * 32 * BSTRIDE,
                        sm + 2 * 128 * ASTRIDE + 3 * 32 * BSTRIDE };

    const int tid = threadIdx.x;
    const int lane = tid & 31;
    const int wid = tid >> 5;
    const int wm = wid >> 1;       // 0..3 -> M offset 32*wm
    const int wn = wid & 1;        // 0..1 -> N offset 64*wn
    const int g = lane >> 2;
    const int t = lane & 3;
    const int bm = blockIdx.x * 128;

    float acc[2][8][4];
    #pragma unroll
    for (int i = 0; i < 2; i++)
        #pragma unroll
        for (int j = 0; j < 8; j++)
            #pragma unroll
            for (int r = 0; r < 4; r++) acc[i][j][r] = 0.f;

    const int nst = K >> 5;   // BK = 32 (K = 128 or 160)

    const int a_c4 = tid & 7;           // constant across u (256%8==0)
    const int b_n4 = tid & 31;          // constant across u (256%32==0)
    const unsigned sA[2]  = { (unsigned)__cvta_generic_to_shared(Abuf[0]),
                              (unsigned)__cvta_generic_to_shared(Abuf[1]) };
    const unsigned sBH[2] = { (unsigned)__cvta_generic_to_shared(BHbuf[0]),
                              (unsigned)__cvta_generic_to_shared(BHbuf[1]) };
    const unsigned sBL[2] = { (unsigned)__cvta_generic_to_shared(BLbuf[0]),
                              (unsigned)__cvta_generic_to_shared(BLbuf[1]) };

    auto load_stage = [&](int buf, int s) {
        const int k0 = s * 32;
        #pragma unroll
        for (int u = 0; u < 4; u++) {
            int rA = (tid >> 3) + 32 * u;
            cp_async16(sA[buf] + (unsigned)((rA * ASTRIDE + a_c4 * 4) << 2),
                       A + (size_t)(bm + rA) * K + k0 + a_c4 * 4);
            int rB = (tid >> 5) + 8 * u;
            unsigned boff = (unsigned)((rB * BSTRIDE + b_n4 * 4) << 2);
            const size_t gw = (size_t)(k0 + rB) * 128 + b_n4 * 4;
            cp_async16(sBH[buf] + boff, WH + gw);
            cp_async16(sBL[buf] + boff, WL + gw);
        }
        asm volatile("cp.async.commit_group;\n" ::: "memory");
    };

    // prologue: fill both buffers
    load_stage(0, 0);
    if (nst > 1) load_stage(1, 1);

    for (int s = 0; s < nst; s++) {
        if (s + 1 < nst)
            asm volatile("cp.async.wait_group 1;\n" ::: "memory");
        else
            asm volatile("cp.async.wait_group 0;\n" ::: "memory");
        __syncthreads();

        const float* As = Abuf[s & 1];
        const float* BsH = BHbuf[s & 1];
        const float* BsL = BLbuf[s & 1];

        #pragma unroll
        for (int kq = 0; kq < 4; kq++) {
            const int koff = kq * 8;
            unsigned ah[2][4], al[2][4];
            #pragma unroll
            for (int i = 0; i < 2; i++) {
                int m0 = wm * 32 + i * 16;
                const float* p0 = As + (m0 + g) * ASTRIDE + koff + t;
                const float* p1 = As + (m0 + g + 8) * ASTRIDE + koff + t;
                split_tf32(p0[0], ah[i][0], al[i][0]);
                split_tf32(p1[0], ah[i][1], al[i][1]);
                split_tf32(p0[4], ah[i][2], al[i][2]);
                split_tf32(p1[4], ah[i][3], al[i][3]);
            }
            #pragma unroll
            for (int j = 0; j < 8; j++) {
                int n0 = wn * 64 + j * 8;
                unsigned bh0 = __float_as_uint(BsH[(koff + t) * BSTRIDE + n0 + g]);
                unsigned bh1 = __float_as_uint(BsH[(koff + t + 4) * BSTRIDE + n0 + g]);
                unsigned bl0 = __float_as_uint(BsL[(koff + t) * BSTRIDE + n0 + g]);
                unsigned bl1 = __float_as_uint(BsL[(koff + t + 4) * BSTRIDE + n0 + g]);
                #pragma unroll
                for (int i = 0; i < 2; i++) {
                    float* cc = acc[i][j];
                    mma_tf32(cc, ah[i][0], ah[i][1], ah[i][2], ah[i][3], bl0, bl1);
                    mma_tf32(cc, al[i][0], al[i][1], al[i][2], al[i][3], bh0, bh1);
                    mma_tf32(cc, ah[i][0], ah[i][1], ah[i][2], ah[i][3], bh0, bh1);
                }
            }
        }
        __syncthreads();   // all warps done with buf (s&1) before it's reloaded
        if (s + 2 < nst) load_stage(s & 1, s + 2);
    }

    // epilogue: c0:(g,2t) c1:(g,2t+1) c2:(g+8,2t) c3:(g+8,2t+1)
    #pragma unroll
    for (int i = 0; i < 2; i++) {
        int row0 = bm + wm * 32 + i * 16 + g;
        #pragma unroll
        for (int j = 0; j < 8; j++) {
            int col = wn * 64 + j * 8 + t * 2;
            float bv0 = bias ? bias[col] : 0.f;
            float bv1 = bias ? bias[col + 1] : 0.f;
            float v0 = acc[i][j][0] + bv0, v1 = acc[i][j][1] + bv1;
            float v2 = acc[i][j][2] + bv0, v3 = acc[i][j][3] + bv1;
            if (relu) {
                v0 = fmaxf(v0, 0.f); v1 = fmaxf(v1, 0.f);
                v2 = fmaxf(v2, 0.f); v3 = fmaxf(v3, 0.f);
            }
            *(float2*)&C[(size_t)row0 * 128 + col] = make_float2(v0, v1);
            *(float2*)&C[(size_t)(row0 + 8) * 128 + col] = make_float2(v2, v3);
        }
    }
}

// ---------------- small SGEMM (M=64 pool path) ----------------
__global__ void gemm_kernel(const float* __restrict__ A,
                            const float* __restrict__ W,
                            const float* __restrict__ bias,
                            float* __restrict__ C,
                            int K, int relu) {
    __shared__ __align__(16) float As[16][68];
    __shared__ __align__(16) float Ws[16][68];
    int bm = blockIdx.y * 64;
    int bn = blockIdx.x * 64;
    int tid = threadIdx.x;
    int tx = tid & 15;
    int ty = tid >> 4;
    float acc[4][4] = {};

    for (int k0 = 0; k0 < K; k0 += 16) {
        #pragma unroll
        for (int i = tid; i < 1024; i += 256) {
            int r = i >> 4, c = i & 15;
            As[c][r] = A[(size_t)(bm + r) * K + k0 + c];
        }
        #pragma unroll
        for (int i = tid; i < 1024; i += 256) {
            int r = i >> 6, c = i & 63;
            Ws[r][c] = W[(size_t)(k0 + r) * 128 + bn + c];
        }
        __syncthreads();
        #pragma unroll
        for (int kk = 0; kk < 16; kk++) {
            float4 av = *(const float4*)&As[kk][ty * 4];
            float4 wv = *(const float4*)&Ws[kk][tx * 4];
            float a[4] = {av.x, av.y, av.z, av.w};
            float w[4] = {wv.x, wv.y, wv.z, wv.w};
            #pragma unroll
            for (int i = 0; i < 4; i++)
                #pragma unroll
                for (int j = 0; j < 4; j++)
                    acc[i][j] += a[i] * w[j];
        }
        __syncthreads();
    }
    #pragma unroll
    for (int i = 0; i < 4; i++) {
        int row = bm + ty * 4 + i;
        float4 out;
        float* po = (float*)&out;
        #pragma unroll
        for (int j = 0; j < 4; j++) {
            int col = bn + tx * 4 + j;
            float vv = acc[i][j] + (bias ? bias[col] : 0.f);
            if (relu) vv = fmaxf(vv, 0.f);
            po[j] = vv;
        }
        *(float4*)&C[(size_t)row * 128 + bn + tx * 4] = out;
    }
}

// ---------------- residual + LayerNorm (in-place on h), float4 ----------------
__global__ void ln_res_kernel(float* __restrict__ h, const float* __restrict__ a,
                              const float* __restrict__ g, const float* __restrict__ bb) {
    int row = blockIdx.x * 8 + threadIdx.y;
    int lane = threadIdx.x;
    float* hp = h + (size_t)row * HID + lane * 4;
    const float* ap = a + (size_t)row * HID + lane * 4;
    float4 hv = *(const float4*)hp;
    float4 av = *(const float4*)ap;
    float v0 = hv.x + av.x, v1 = hv.y + av.y, v2 = hv.z + av.z, v3 = hv.w + av.w;
    float sum = v0 + v1 + v2 + v3;
    float sum2 = v0 * v0 + v1 * v1 + v2 * v2 + v3 * v3;
    #pragma unroll
    for (int off = 16; off > 0; off >>= 1) {
        sum  += __shfl_xor_sync(0xFFFFFFFFu, sum, off);
        sum2 += __shfl_xor_sync(0xFFFFFFFFu, sum2, off);
    }
    float mean = sum * (1.f / HID);
    float var = sum2 * (1.f / HID) - mean * mean;
    float inv = rsqrtf(var + 1e-5f);
    float4 gv = *(const float4*)(g + lane * 4);
    float4 bv = *(const float4*)(bb + lane * 4);
    float4 out;
    out.x = (v0 - mean) * inv * gv.x + bv.x;
    out.y = (v1 - mean) * inv * gv.y + bv.y;
    out.z = (v2 - mean) * inv * gv.z + bv.z;
    out.w = (v3 - mean) * inv * gv.w + bv.w;
    *(float4*)hp = out;
}

// ---------------- masked / full multi-head attention ----------------
// Scores are small (LN-normalized inputs, 0.02-scale weights), so plain exp
// without max subtraction is numerically safe.
__global__ void attn_kernel(const float* __restrict__ q, const float* __restrict__ k,
                            const float* __restrict__ v, float* __restrict__ o,
                            const unsigned* __restrict__ mask) {
    extern __shared__ float4 sm4[];
    float4* kd = sm4;           // 2048 float4
    float4* vd = sm4 + 2048;
    int b = blockIdx.x >> 3;
    int h = blockIdx.x & 7;
    int base = b * EPG;
    const float* kp = k + (size_t)base * HID + h * DH;
    const float* vp = v + (size_t)base * HID + h * DH;
    for (int i = threadIdx.x; i < 2048; i += 256) {
        int r = i >> 2, c = i & 3;
        kd[i] = *(const float4*)(kp + (size_t)r * HID + c * 4);
        vd[i] = *(const float4*)(vp + (size_t)r * HID + c * 4);
    }
    __syncthreads();

    if (mask != nullptr) {
        #pragma unroll
        for (int rr = 0; rr < 2; rr++) {
            int i = threadIdx.x + rr * 256;
            const float* qp = q + (size_t)(base + i) * HID + h * DH;
            float4 q0 = *(const float4*)(qp + 0);
            float4 q1 = *(const float4*)(qp + 4);
            float4 q2 = *(const float4*)(qp + 8);
            float4 q3 = *(const float4*)(qp + 12);

            float l = 0.f;
            float4 a0 = {0,0,0,0}, a1 = {0,0,0,0}, a2 = {0,0,0,0}, a3 = {0,0,0,0};

            const unsigned* mp = mask + (size_t)(base + i) * 16;
            #pragma unroll
            for (int w = 0; w < 16; w++) {
                unsigned bits = mp[w];
                while (bits) {
                    int jj = __ffs(bits) - 1;
                    bits &= bits - 1;
                    int j = (w << 5) + jj;
                    const float4 k0 = kd[4*j+0], k1 = kd[4*j+1], k2 = kd[4*j+2], k3 = kd[4*j+3];
                    float s = q0.x*k0.x + q0.y*k0.y + q0.z*k0.z + q0.w*k0.w
                            + q1.x*k1.x + q1.y*k1.y + q1.z*k1.z + q1.w*k1.w
                            + q2.x*k2.x + q2.y*k2.y + q2.z*k2.z + q2.w*k2.w
                            + q3.x*k3.x + q3.y*k3.y + q3.z*k3.z + q3.w*k3.w;
                    float p = __expf(s * 0.25f);   // 1/sqrt(16)
                    l += p;
                    const float4 v0 = vd[4*j+0], v1 = vd[4*j+1], v2 = vd[4*j+2], v3 = vd[4*j+3];
                    a0.x += p*v0.x; a0.y += p*v0.y; a0.z += p*v0.z; a0.w += p*v0.w;
                    a1.x += p*v1.x; a1.y += p*v1.y; a1.z += p*v1.z; a1.w += p*v1.w;
                    a2.x += p*v2.x; a2.y += p*v2.y; a2.z += p*v2.z; a2.w += p*v2.w;
                    a3.x += p*v3.x; a3.y += p*v3.y; a3.z += p*v3.z; a3.w += p*v3.w;
                }
            }

            float inv = 1.f / l;
            float* op = o + (size_t)(base + i) * HID + h * DH;
            *(float4*)(op + 0)  = make_float4(a0.x*inv, a0.y*inv, a0.z*inv, a0.w*inv);
            *(float4*)(op + 4)  = make_float4(a1.x*inv, a1.y*inv, a1.z*inv, a1.w*inv);
            *(float4*)(op + 8)  = make_float4(a2.x*inv, a2.y*inv, a2.z*inv, a2.w*inv);
            *(float4*)(op + 12) = make_float4(a3.x*inv, a3.y*inv, a3.z*inv, a3.w*inv);
        }
    } else {
        // dense path: both rows share every K/V read
        float4 qa[2][4];
        #pragma unroll
        for (int rr = 0; rr < 2; rr++) {
            const float* qp = q + (size_t)(base + threadIdx.x + rr * 256) * HID + h * DH;
            qa[rr][0] = *(const float4*)(qp + 0);
            qa[rr][1] = *(const float4*)(qp + 4);
            qa[rr][2] = *(const float4*)(qp + 8);
            qa[rr][3] = *(const float4*)(qp + 12);
        }
        float l[2] = {0.f, 0.f};
        float4 ac[2][4];
        #pragma unroll
        for (int rr = 0; rr < 2; rr++)
            #pragma unroll
            for (int c = 0; c < 4; c++) ac[rr][c] = make_float4(0.f, 0.f, 0.f, 0.f);

        #pragma unroll 2
        for (int j = 0; j < EPG; j++) {
            const float4 k0 = kd[4*j+0], k1 = kd[4*j+1], k2 = kd[4*j+2], k3 = kd[4*j+3];
            const float4 v0 = vd[4*j+0], v1 = vd[4*j+1], v2 = vd[4*j+2], v3 = vd[4*j+3];
            #pragma unroll
            for (int rr = 0; rr < 2; rr++) {
                float s = qa[rr][0].x*k0.x + qa[rr][0].y*k0.y + qa[rr][0].z*k0.z + qa[rr][0].w*k0.w
                        + qa[rr][1].x*k1.x + qa[rr][1].y*k1.y + qa[rr][1].z*k1.z + qa[rr][1].w*k1.w
                        + qa[rr][2].x*k2.x + qa[rr][2].y*k2.y + qa[rr][2].z*k2.z + qa[rr][2].w*k2.w
                        + qa[rr][3].x*k3.x + qa[rr][3].y*k3.y + qa[rr][3].z*k3.z + qa[rr][3].w*k3.w;
                float p = __expf(s * 0.25f);
                l[rr] += p;
                ac[rr][0].x += p*v0.x; ac[rr][0].y += p*v0.y; ac[rr][0].z += p*v0.z; ac[rr][0].w += p*v0.w;
                ac[rr][1].x += p*v1.x; ac[rr][1].y += p*v1.y; ac[rr][1].z += p*v1.z; ac[rr][1].w += p*v1.w;
                ac[rr][2].x += p*v2.x; ac[rr][2].y += p*v2.y; ac[rr][2].z += p*v2.z; ac[rr][2].w += p*v2.w;
                ac[rr][3].x += p*v3.x; ac[rr][3].y += p*v3.y; ac[rr][3].z += p*v3.z; ac[rr][3].w += p*v3.w;
            }
        }
        #pragma unroll
        for (int rr = 0; rr < 2; rr++) {
            float inv = 1.f / l[rr];
            float* op = o + (size_t)(base + threadIdx.x + rr * 256) * HID + h * DH;
            #pragma unroll
            for (int c = 0; c < 4; c++)
                *(float4*)(op + 4 * c) = make_float4(ac[rr][c].x*inv, ac[rr][c].y*inv,
                                                     ac[rr][c].z*inv, ac[rr][c].w*inv);
        }
    }
}

// ---------------- pooling: qpool = seed @ p_Wq ----------------
__global__ void qpool_kernel(const float* __restrict__ seed, const float* __restrict__ Wq,
                             float* __restrict__ qpool) {
    int c = threadIdx.x;   // 128
    float s = 0.f;
    for (int kk = 0; kk < HID; kk++) s += seed[kk] * Wq[(size_t)kk * HID + c];
    qpool[c] = s;
}

// ---------------- PMA attention: 1 query per graph, full mask ----------------
__global__ void pool_attn_kernel(const float* __restrict__ qpool, const float* __restrict__ k,
                                 const float* __restrict__ v, float* __restrict__ pool) {
    int b = blockIdx.x;
    int w = threadIdx.x >> 5;     // head
    int lane = threadIdx.x & 31;
    float qr[DH];
    #pragma unroll
    for (int d = 0; d < DH; d++) qr[d] = qpool[w * DH + d];

    float s[16];
    float mloc = -1e30f;
    #pragma unroll
    for (int t = 0; t < 16; t++) {
        int j = lane + t * 32;
        const float* kp = k + (size_t)(b * EPG + j) * HID + w * DH;
        float acc = 0.f;
        #pragma unroll
        for (int d = 0; d < DH; d++) acc += qr[d] * kp[d];
        s[t] = acc * 0.25f;
        mloc = fmaxf(mloc, s[t]);
    }
    #pragma unroll
    for (int off = 16; off > 0; off >>= 1)
        mloc = fmaxf(mloc, __shfl_xor_sync(0xFFFFFFFFu, mloc, off));

    float l = 0.f;
    float acc[DH];
    #pragma unroll
    for (int d = 0; d < DH; d++) acc[d] = 0.f;
    #pragma unroll
    for (int t = 0; t < 16; t++) {
        int j = lane + t * 32;
        float p = __expf(s[t] - mloc);
        l += p;
        const float* vp = v + (size_t)(b * EPG + j) * HID + w * DH;
        #pragma unroll
        for (int d = 0; d < DH; d++) acc[d] += p * vp[d];
    }
    #pragma unroll
    for (int off = 16; off > 0; off >>= 1) {
        l += __shfl_xor_sync(0xFFFFFFFFu, l, off);
        #pragma unroll
        for (int d = 0; d < DH; d++)
            acc[d] += __shfl_xor_sync(0xFFFFFFFFu, acc[d], off);
    }
    if (lane == 0) {
        float inv = 1.f / l;
        #pragma unroll
        for (int d = 0; d < DH; d++)
            pool[(size_t)b * HID + w * DH + d] = acc[d] * inv;
    }
}

// ---------------- final: out[b] = o1[b] . out_W2 + out_b2 ----------------
__global__ void final_kernel(const float* __restrict__ o1, const float* __restrict__ W2,
                             const float* __restrict__ b2, float* __restrict__ out) {
    int b = blockIdx.x;
    int lane = threadIdx.x;
    float s = 0.f;
    #pragma unroll
    for (int i = 0; i < 4; i++) {
        int c = lane + 32 * i;
        s += o1[(size_t)b * HID + c] * W2[c];
    }
    #pragma unroll
    for (int off = 16; off > 0; off >>= 1)
        s += __shfl_xor_sync(0xFFFFFFFFu, s, off);
    if (lane == 0) out[b] = s + b2[0];
}

// ---------------- host launch ----------------
extern "C" void kernel_launch(void* const* d_in, const int* in_sizes, int n_in,
                              void* d_out, int out_size) {
    const float* x       = (const float*)d_in[0];
    const float* ea      = (const float*)d_in[1];
    const float* in_W1   = (const float*)d_in[2];
    const float* in_b1   = (const float*)d_in[3];
    const float* in_W2   = (const float*)d_in[4];
    const float* in_b2   = (const float*)d_in[5];
    const float* Wq      = (const float*)d_in[6];
    const float* Wk      = (const float*)d_in[7];
    const float* Wv      = (const float*)d_in[8];
    const float* Wo      = (const float*)d_in[9];
    const float* ln1_g   = (const float*)d_in[10];
    const float* ln1_b   = (const float*)d_in[11];
    const float* ln2_g   = (const float*)d_in[12];
    const float* ln2_b   = (const float*)d_in[13];
    const float* f_W1    = (const float*)d_in[14];
    const float* f_b1    = (const float*)d_in[15];
    const float* f_W2    = (const float*)d_in[16];
    const float* f_b2    = (const float*)d_in[17];
    const float* seed    = (const float*)d_in[18];
    const float* p_Wq    = (const float*)d_in[19];
    const float* p_Wk    = (const float*)d_in[20];
    const float* p_Wv    = (const float*)d_in[21];
    const float* p_Wo    = (const float*)d_in[22];
    const float* out_W1  = (const float*)d_in[23];
    const float* out_b1  = (const float*)d_in[24];
    const float* out_W2  = (const float*)d_in[25];
    const float* out_b2  = (const float*)d_in[26];
    const int*   ei      = (const int*)d_in[27];

    float *p_h, *p_q, *p_k, *p_v, *p_a, *p_t, *p_feat, *p_qpool, *p_pool, *p_pool2;
    float *p_whi, *p_wlo;
    unsigned* p_mask;
    cudaGetSymbolAddress((void**)&p_h, g_h);
    cudaGetSymbolAddress((void**)&p_q, g_q);
    cudaGetSymbolAddress((void**)&p_k, g_k);
    cudaGetSymbolAddress((void**)&p_v, g_v);
    cudaGetSymbolAddress((void**)&p_a, g_a);
    cudaGetSymbolAddress((void**)&p_t, g_t);
    cudaGetSymbolAddress((void**)&p_feat, g_feat);
    cudaGetSymbolAddress((void**)&p_mask, g_mask);
    cudaGetSymbolAddress((void**)&p_whi, g_whi);
    cudaGetSymbolAddress((void**)&p_wlo, g_wlo);
    cudaGetSymbolAddress((void**)&p_qpool, g_qpool);
    cudaGetSymbolAddress((void**)&p_pool, g_pool);
    cudaGetSymbolAddress((void**)&p_pool2, g_pool2);

    cudaFuncSetAttribute(attn_kernel, cudaFuncAttributeMaxDynamicSharedMemorySize, 65536);
    cudaFuncSetAttribute(gemm_tf32_kernel, cudaFuncAttributeMaxDynamicSharedMemorySize,
                         SMEM_GEMM_BYTES);

    const dim3 g1(E_TOT / 128, 1);
    const dim3 g2(E_TOT / 128, 2);
    const dim3 g3(E_TOT / 128, 3);
    dim3 gSmall(2, 1);

    // weight pre-split + inputs
    split_w_kernel<<<W_TOTAL / 256, 256>>>(in_W1, in_W2, Wq, Wk, Wv, Wo,
                                           f_W1, f_W2, p_Wk, p_Wv, p_whi, p_wlo);
    gather_feat_kernel<<<E_TOT, FEAT_DIM>>>(x, ea, ei, p_feat);
    build_mask_kernel<<<B, 256>>>(ei, p_mask);

    #define GEMM1(Ap, OFF, Cp, bias, K, relu) \
        gemm_tf32_kernel<<<g1, 256, SMEM_GEMM_BYTES>>>(Ap, \
            p_whi + (OFF), p_whi + (OFF), p_whi + (OFF), \
            p_wlo + (OFF), p_wlo + (OFF), p_wlo + (OFF), \
            Cp, Cp, Cp, bias, K, relu)

    // input MLP
    GEMM1(p_feat, O_INW1, p_t, in_b1, FEAT_DIM, 1);
    GEMM1(p_t, O_INW2, p_h, in_b2, HID, 0);

    // transformer layers: M, M, S
    for (int L = 0; L < 3; L++) {
        const size_t wo = (size_t)L * HID * HID;
        gemm_tf32_kernel<<<g3, 256, SMEM_GEMM_BYTES>>>(p_h,
            p_whi + O_WQ + wo, p_whi + O_WK + wo, p_whi + O_WV + wo,
            p_wlo + O_WQ + wo, p_wlo + O_WK + wo, p_wlo + O_WV + wo,
            p_q, p_k, p_v, nullptr, HID, 0);
        attn_kernel<<<B * HEADS, 256, 65536>>>(p_q, p_k, p_v, p_a,
                                               (L < 2) ? p_mask : nullptr);
        GEMM1(p_a, O_WO + wo, p_t, nullptr, HID, 0);
        ln_res_kernel<<<E_TOT / 8, dim3(32, 8)>>>(p_h, p_t, ln1_g + L * HID, ln1_b + L * HID);
        GEMM1(p_h, O_FW1 + wo, p_t, f_b1 + L * HID, HID, 1);
        GEMM1(p_t, O_FW2 + wo, p_a, f_b2 + L * HID, HID, 0);
        ln_res_kernel<<<E_TOT / 8, dim3(32, 8)>>>(p_h, p_a, ln2_g + L * HID, ln2_b + L * HID);
    }

    // PMA pooling (fused K/V projection)
    gemm_tf32_kernel<<<g2, 256, SMEM_GEMM_BYTES>>>(p_h,
        p_whi + O_PWK, p_whi + O_PWV, p_whi + O_PWV,
        p_wlo + O_PWK, p_wlo + O_PWV, p_wlo + O_PWV,
        p_k, p_v, p_v, nullptr, HID, 0);
    qpool_kernel<<<1, HID>>>(seed, p_Wq, p_qpool);
    pool_attn_kernel<<<B, 256>>>(p_qpool, p_k, p_v, p_pool);
    gemm_kernel<<<gSmall, 256>>>(p_pool, p_Wo, nullptr, p_pool2, HID, 0);

    // output MLP
    gemm_kernel<<<gSmall, 256>>>(p_pool2, out_W1, out_b1, p_pool, HID, 1);
    final_kernel<<<B, 32>>>(p_pool, out_W2, out_b2, (float*)d_out);
    #undef GEMM1
}

// round 10
// speedup vs baseline: 1.9201x; 1.0439x over previous
#include <cuda_runtime.h>
#include <cuda_bf16.h>

// ---------------- problem constants ----------------
#define B 64
#define EPG 512
#define E_TOT (B * EPG)        // 32768
#define NODE_DIM 64
#define EDGE_DIM 32
#define HID 128
#define HEADS 8
#define DH 16
#define FEAT_DIM 160           // 2*64 + 32

// GEMM smem strides (words). 40 ≡ 8 (mod 32), 136 ≡ 8 (mod 32): conflict-free.
#define ASTRIDE 40
#define BSTRIDE 136
#define SMEM_GEMM_BYTES ((2 * 128 * ASTRIDE + 4 * 32 * BSTRIDE) * 4)   // 110592

// dense-attention smem strides (words) — all bank-verified conflict-free:
// K frag: (20g+t) mod 32 bijective; V frag: (24t+g) mod 32 bijective;
// P frag: (4g+t) mod 32 bijective.
#define KSTR 20
#define VSTR 24
#define PSTR 36
#define SMEM_DATTN ((512 * KSTR + 512 * VSTR + 8 * 64 * PSTR) * 4)     // 163840

// pre-split weight scratch offsets (floats)
#define O_INW1 0
#define O_INW2 20480
#define O_WQ   36864
#define O_WK   86016
#define O_WV   135168
#define O_WO   184320
#define O_FW1  233472
#define O_FW2  282624
#define O_PWK  331776
#define O_PWV  348160
#define W_TOTAL 364544

// ---------------- scratch (device globals; no allocs allowed) ----------------
__device__ float g_h[E_TOT * HID];
__device__ float g_q[E_TOT * HID];
__device__ float g_k[E_TOT * HID];
__device__ float g_v[E_TOT * HID];
__device__ float g_a[E_TOT * HID];
__device__ float g_t[E_TOT * HID];
__device__ float g_feat[E_TOT * FEAT_DIM];
__device__ unsigned g_mask[B * EPG * 16];   // 512 bits per (graph,row)
__device__ float g_whi[W_TOTAL];
__device__ float g_wlo[W_TOTAL];
__device__ float g_qpool[HID];
__device__ float g_pool[B * HID];
__device__ float g_pool2[B * HID];

// ---------------- tf32 / cp.async helpers ----------------
__device__ __forceinline__ unsigned f2tf32u(float f) {
    unsigned u;
    asm("cvt.rna.tf32.f32 %0, %1;" : "=r"(u) : "f"(f));
    return u;
}

__device__ __forceinline__ void split_tf32(float x, unsigned& hi, unsigned& lo) {
    hi = f2tf32u(x);
    lo = f2tf32u(x - __uint_as_float(hi));
}

__device__ __forceinline__ void cp_async16(unsigned smem_addr, const void* gptr) {
    asm volatile("cp.async.cg.shared.global [%0], [%1], 16;\n"
                 :: "r"(smem_addr), "l"(gptr));
}

__device__ __forceinline__ void mma_tf32(float* c,
                                         unsigned a0, unsigned a1, unsigned a2, unsigned a3,
                                         unsigned b0, unsigned b1) {
    asm volatile("mma.sync.aligned.m16n8k8.row.col.f32.tf32.tf32.f32 "
                 "{%0,%1,%2,%3}, {%4,%5,%6,%7}, {%8,%9}, {%0,%1,%2,%3};"
                 : "+f"(c[0]), "+f"(c[1]), "+f"(c[2]), "+f"(c[3])
                 : "r"(a0), "r"(a1), "r"(a2), "r"(a3), "r"(b0), "r"(b1));
}

// ---------------- one-shot weight pre-split: w -> (tf32 hi, tf32 lo) ----------------
__global__ void split_w_kernel(const float* __restrict__ w0, const float* __restrict__ w1,
                               const float* __restrict__ w2, const float* __restrict__ w3,
                               const float* __restrict__ w4, const float* __restrict__ w5,
                               const float* __restrict__ w6, const float* __restrict__ w7,
                               const float* __restrict__ w8, const float* __restrict__ w9,
                               float* __restrict__ hi, float* __restrict__ lo) {
    int idx = blockIdx.x * 256 + threadIdx.x;
    float v;
    if      (idx < O_INW2) v = w0[idx - O_INW1];
    else if (idx < O_WQ)   v = w1[idx - O_INW2];
    else if (idx < O_WK)   v = w2[idx - O_WQ];
    else if (idx < O_WV)   v = w3[idx - O_WK];
    else if (idx < O_WO)   v = w4[idx - O_WV];
    else if (idx < O_FW1)  v = w5[idx - O_WO];
    else if (idx < O_FW2)  v = w6[idx - O_FW1];
    else if (idx < O_PWK)  v = w7[idx - O_FW2];
    else if (idx < O_PWV)  v = w8[idx - O_PWK];
    else                   v = w9[idx - O_PWV];
    unsigned h = f2tf32u(v);
    hi[idx] = __uint_as_float(h);
    lo[idx] = __uint_as_float(f2tf32u(v - __uint_as_float(h)));
}

// ---------------- gather edge features ----------------
__global__ void gather_feat_kernel(const float* __restrict__ x,
                                   const float* __restrict__ ea,
                                   const int* __restrict__ ei,
                                   float* __restrict__ feat) {
    int e = blockIdx.x;
    int c = threadIdx.x;            // 160 threads
    int s = ei[e];
    int d = ei[E_TOT + e];
    float val;
    if (c < 64)       val = x[(size_t)s * NODE_DIM + c];
    else if (c < 128) val = x[(size_t)d * NODE_DIM + (c - 64)];
    else              val = ea[(size_t)e * EDGE_DIM + (c - 128)];
    feat[(size_t)e * FEAT_DIM + c] = val;
}

// ---------------- adjacency bitmask (edges sharing a node) ----------------
__global__ void build_mask_kernel(const int* __restrict__ ei,
                                  unsigned* __restrict__ mask) {
    int b = blockIdx.x;
    __shared__ int ss[EPG];
    __shared__ int dd[EPG];
    for (int i = threadIdx.x; i < EPG; i += blockDim.x) {
        ss[i] = ei[b * EPG + i];
        dd[i] = ei[E_TOT + b * EPG + i];
    }
    __syncthreads();
    for (int i = threadIdx.x; i < EPG; i += blockDim.x) {
        int si = ss[i], di = dd[i];
        for (int w = 0; w < 16; w++) {
            unsigned bits = 0;
            #pragma unroll
            for (int jj = 0; jj < 32; jj++) {
                int j = (w << 5) + jj;
                int sj = ss[j], dj = dd[j];
                bool adj = (si == sj) | (si == dj) | (di == sj) | (di == dj) | (i == j);
                bits |= (unsigned)adj << jj;
            }
            mask[((size_t)b * EPG + i) * 16 + w] = bits;
        }
    }
}

// ---------------- 3xTF32 tensor-core GEMM (unchanged from R9) -----------
__global__ void __launch_bounds__(256, 2)
gemm_tf32_kernel(const float* __restrict__ A,
                 const float* __restrict__ Whi0, const float* __restrict__ Whi1,
                 const float* __restrict__ Whi2,
                 const float* __restrict__ Wlo0, const float* __restrict__ Wlo1,
                 const float* __restrict__ Wlo2,
                 float* __restrict__ C0, float* __restrict__ C1, float* __restrict__ C2,
                 const float* __restrict__ bias, int K, int relu) {
    const float* WH = (blockIdx.y == 0) ? Whi0 : (blockIdx.y == 1 ? Whi1 : Whi2);
    const float* WL = (blockIdx.y == 0) ? Wlo0 : (blockIdx.y == 1 ? Wlo1 : Wlo2);
    float* C        = (blockIdx.y == 0) ? C0   : (blockIdx.y == 1 ? C1   : C2);

    extern __shared__ float sm[];
    float* Abuf[2]  = { sm, sm + 128 * ASTRIDE };
    float* BHbuf[2] = { sm + 2 * 128 * ASTRIDE,
                        sm + 2 * 128 * ASTRIDE + 32 * BSTRIDE };
    float* BLbuf[2] = { sm + 2 * 128 * ASTRIDE + 2 * 32 * BSTRIDE,
                        sm + 2 * 128 * ASTRIDE + 3 * 32 * BSTRIDE };

    const int tid = threadIdx.x;
    const int lane = tid & 31;
    const int wid = tid >> 5;
    const int wm = wid >> 1;
    const int wn = wid & 1;
    const int g = lane >> 2;
    const int t = lane & 3;
    const int bm = blockIdx.x * 128;

    float acc[2][8][4];
    #pragma unroll
    for (int i = 0; i < 2; i++)
        #pragma unroll
        for (int j = 0; j < 8; j++)
            #pragma unroll
            for (int r = 0; r < 4; r++) acc[i][j][r] = 0.f;

    const int nst = K >> 5;

    const int a_c4 = tid & 7;
    const int b_n4 = tid & 31;
    const unsigned sA[2]  = { (unsigned)__cvta_generic_to_shared(Abuf[0]),
                              (unsigned)__cvta_generic_to_shared(Abuf[1]) };
    const unsigned sBH[2] = { (unsigned)__cvta_generic_to_shared(BHbuf[0]),
                              (unsigned)__cvta_generic_to_shared(BHbuf[1]) };
    const unsigned sBL[2] = { (unsigned)__cvta_generic_to_shared(BLbuf[0]),
                              (unsigned)__cvta_generic_to_shared(BLbuf[1]) };

    auto load_stage = [&](int buf, int s) {
        const int k0 = s * 32;
        #pragma unroll
        for (int u = 0; u < 4; u++) {
            int rA = (tid >> 3) + 32 * u;
            cp_async16(sA[buf] + (unsigned)((rA * ASTRIDE + a_c4 * 4) << 2),
                       A + (size_t)(bm + rA) * K + k0 + a_c4 * 4);
            int rB = (tid >> 5) + 8 * u;
            unsigned boff = (unsigned)((rB * BSTRIDE + b_n4 * 4) << 2);
            const size_t gw = (size_t)(k0 + rB) * 128 + b_n4 * 4;
            cp_async16(sBH[buf] + boff, WH + gw);
            cp_async16(sBL[buf] + boff, WL + gw);
        }
        asm volatile("cp.async.commit_group;\n" ::: "memory");
    };

    load_stage(0, 0);
    if (nst > 1) load_stage(1, 1);

    for (int s = 0; s < nst; s++) {
        if (s + 1 < nst)
            asm volatile("cp.async.wait_group 1;\n" ::: "memory");
        else
            asm volatile("cp.async.wait_group 0;\n" ::: "memory");
        __syncthreads();

        const float* As = Abuf[s & 1];
        const float* BsH = BHbuf[s & 1];
        const float* BsL = BLbuf[s & 1];

        #pragma unroll
        for (int kq = 0; kq < 4; kq++) {
            const int koff = kq * 8;
            unsigned ah[2][4], al[2][4];
            #pragma unroll
            for (int i = 0; i < 2; i++) {
                int m0 = wm * 32 + i * 16;
                const float* p0 = As + (m0 + g) * ASTRIDE + koff + t;
                const float* p1 = As + (m0 + g + 8) * ASTRIDE + koff + t;
                split_tf32(p0[0], ah[i][0], al[i][0]);
                split_tf32(p1[0], ah[i][1], al[i][1]);
                split_tf32(p0[4], ah[i][2], al[i][2]);
                split_tf32(p1[4], ah[i][3], al[i][3]);
            }
            #pragma unroll
            for (int j = 0; j < 8; j++) {
                int n0 = wn * 64 + j * 8;
                unsigned bh0 = __float_as_uint(BsH[(koff + t) * BSTRIDE + n0 + g]);
                unsigned bh1 = __float_as_uint(BsH[(koff + t + 4) * BSTRIDE + n0 + g]);
                unsigned bl0 = __float_as_uint(BsL[(koff + t) * BSTRIDE + n0 + g]);
                unsigned bl1 = __float_as_uint(BsL[(koff + t + 4) * BSTRIDE + n0 + g]);
                #pragma unroll
                for (int i = 0; i < 2; i++) {
                    float* cc = acc[i][j];
                    mma_tf32(cc, ah[i][0], ah[i][1], ah[i][2], ah[i][3], bl0, bl1);
                    mma_tf32(cc, al[i][0], al[i][1], al[i][2], al[i][3], bh0, bh1);
                    mma_tf32(cc, ah[i][0], ah[i][1], ah[i][2], ah[i][3], bh0, bh1);
                }
            }
        }
        __syncthreads();
        if (s + 2 < nst) load_stage(s & 1, s + 2);
    }

    #pragma unroll
    for (int i = 0; i < 2; i++) {
        int row0 = bm + wm * 32 + i * 16 + g;
        #pragma unroll
        for (int j = 0; j < 8; j++) {
            int col = wn * 64 + j * 8 + t * 2;
            float bv0 = bias ? bias[col] : 0.f;
            float bv1 = bias ? bias[col + 1] : 0.f;
            float v0 = acc[i][j][0] + bv0, v1 = acc[i][j][1] + bv1;
            float v2 = acc[i][j][2] + bv0, v3 = acc[i][j][3] + bv1;
            if (relu) {
                v0 = fmaxf(v0, 0.f); v1 = fmaxf(v1, 0.f);
                v2 = fmaxf(v2, 0.f); v3 = fmaxf(v3, 0.f);
            }
            *(float2*)&C[(size_t)row0 * 128 + col] = make_float2(v0, v1);
            *(float2*)&C[(size_t)(row0 + 8) * 128 + col] = make_float2(v2, v3);
        }
    }
}

// ---------------- dense (S-layer) attention on tensor cores ----------------
// One block per (graph, head): 8 warps, warp owns 64 q-rows.
// QK^T = 3xTF32 (accurate scores); softmax without max (scores provably small;
// l accumulated from the SAME tf32-truncated p used in the numerator, so the
// result is the exact softmax of slightly-perturbed probabilities).
// P@V = single tf32 mma (error ~1e-5, gate is 1e-3).
__global__ void __launch_bounds__(256, 1)
dense_attn_tc_kernel(const float* __restrict__ q, const float* __restrict__ k,
                     const float* __restrict__ v, float* __restrict__ o) {
    extern __shared__ float sm[];
    float* Ks = sm;                      // [512][KSTR]
    float* Vs = Ks + 512 * KSTR;         // [512][VSTR]
    float* Ps = Vs + 512 * VSTR;         // [8][64][PSTR]
    const int b = blockIdx.x >> 3, h = blockIdx.x & 7;
    const int base = b * EPG;
    const int tid = threadIdx.x, lane = tid & 31, wid = tid >> 5;
    const int g = lane >> 2, t = lane & 3;
    float* Pw = Ps + wid * 64 * PSTR;

    // stage K, V (raw fp32)
    for (int i = tid; i < 2048; i += 256) {
        int r = i >> 2, c4 = (i & 3) * 4;
        float4 kv = *(const float4*)(k + (size_t)(base + r) * HID + h * DH + c4);
        float4 vv = *(const float4*)(v + (size_t)(base + r) * HID + h * DH + c4);
        Ks[r * KSTR + c4 + 0] = kv.x; Ks[r * KSTR + c4 + 1] = kv.y;
        Ks[r * KSTR + c4 + 2] = kv.z; Ks[r * KSTR + c4 + 3] = kv.w;
        Vs[r * VSTR + c4 + 0] = vv.x; Vs[r * VSTR + c4 + 1] = vv.y;
        Vs[r * VSTR + c4 + 2] = vv.z; Vs[r * VSTR + c4 + 3] = vv.w;
    }

    // Q fragments (register-resident, hi/lo split). a0=(g,t) a1=(g+8,t) a2=(g,t+4) a3=(g+8,t+4)
    unsigned qh[4][2][4], ql[4][2][4];
    #pragma unroll
    for (int mi = 0; mi < 4; mi++) {
        const size_t r0 = (size_t)(base + wid * 64 + mi * 16 + g) * HID + h * DH;
        const size_t r1 = r0 + (size_t)8 * HID;
        #pragma unroll
        for (int ko = 0; ko < 2; ko++) {
            split_tf32(q[r0 + ko * 8 + t],     qh[mi][ko][0], ql[mi][ko][0]);
            split_tf32(q[r1 + ko * 8 + t],     qh[mi][ko][1], ql[mi][ko][1]);
            split_tf32(q[r0 + ko * 8 + t + 4], qh[mi][ko][2], ql[mi][ko][2]);
            split_tf32(q[r1 + ko * 8 + t + 4], qh[mi][ko][3], ql[mi][ko][3]);
        }
    }
    __syncthreads();

    float oacc[4][2][4] = {};
    float lrow[8] = {};

    for (int kc = 0; kc < 16; kc++) {
        const int j0 = kc * 32;
        float sacc[4][4][4] = {};
        // S = Q @ K^T, 3xTF32. B-frag: b0 = K[j0+nj*8+g][ko*8+t], b1 = col+4.
        #pragma unroll
        for (int ko = 0; ko < 2; ko++) {
            #pragma unroll
            for (int nj = 0; nj < 4; nj++) {
                const float* kp = Ks + (j0 + nj * 8 + g) * KSTR + ko * 8 + t;
                unsigned bh0, bl0, bh1, bl1;
                split_tf32(kp[0], bh0, bl0);
                split_tf32(kp[4], bh1, bl1);
                #pragma unroll
                for (int mi = 0; mi < 4; mi++) {
                    float* cc = sacc[mi][nj];
                    mma_tf32(cc, qh[mi][ko][0], qh[mi][ko][1], qh[mi][ko][2], qh[mi][ko][3], bl0, bl1);
                    mma_tf32(cc, ql[mi][ko][0], ql[mi][ko][1], ql[mi][ko][2], ql[mi][ko][3], bh0, bh1);
                    mma_tf32(cc, qh[mi][ko][0], qh[mi][ko][1], qh[mi][ko][2], qh[mi][ko][3], bh0, bh1);
                }
            }
        }
        // exp, accumulate l from truncated p, store P (tf32) to warp buffer.
        // C layout: c0=(g,2t) c1=(g,2t+1) c2=(g+8,2t) c3=(g+8,2t+1)
        #pragma unroll
        for (int mi = 0; mi < 4; mi++) {
            #pragma unroll
            for (int nj = 0; nj < 4; nj++) {
                float p0 = __uint_as_float(f2tf32u(__expf(sacc[mi][nj][0] * 0.25f)));
                float p1 = __uint_as_float(f2tf32u(__expf(sacc[mi][nj][1] * 0.25f)));
                float p2 = __uint_as_float(f2tf32u(__expf(sacc[mi][nj][2] * 0.25f)));
                float p3 = __uint_as_float(f2tf32u(__expf(sacc[mi][nj][3] * 0.25f)));
                lrow[mi * 2 + 0] += p0 + p1;
                lrow[mi * 2 + 1] += p2 + p3;
                *(float2*)(Pw + (mi * 16 + g) * PSTR + nj * 8 + 2 * t) = make_float2(p0, p1);
                *(float2*)(Pw + (mi * 16 + g + 8) * PSTR + nj * 8 + 2 * t) = make_float2(p2, p3);
            }
        }
        __syncwarp();
        // O += P @ V (single tf32). A-frag from Pw; B-frag: b0 = V[j0+k2*8+t][nd*8+g].
        #pragma unroll
        for (int k2 = 0; k2 < 4; k2++) {
            unsigned pa[4][4];
            #pragma unroll
            for (int mi = 0; mi < 4; mi++) {
                const float* p0 = Pw + (mi * 16 + g) * PSTR + k2 * 8 + t;
                const float* p1 = Pw + (mi * 16 + g + 8) * PSTR + k2 * 8 + t;
                pa[mi][0] = __float_as_uint(p0[0]);
                pa[mi][1] = __float_as_uint(p1[0]);
                pa[mi][2] = __float_as_uint(p0[4]);
                pa[mi][3] = __float_as_uint(p1[4]);
            }
            #pragma unroll
            for (int nd = 0; nd < 2; nd++) {
                unsigned vb0 = f2tf32u(Vs[(j0 + k2 * 8 + t) * VSTR + nd * 8 + g]);
                unsigned vb1 = f2tf32u(Vs[(j0 + k2 * 8 + t + 4) * VSTR + nd * 8 + g]);
                #pragma unroll
                for (int mi = 0; mi < 4; mi++)
                    mma_tf32(oacc[mi][nd], pa[mi][0], pa[mi][1], pa[mi][2], pa[mi][3], vb0, vb1);
            }
        }
        __syncwarp();   // Pw reused next chunk
    }

    // reduce l over the quad (t = lane bits 0..1)
    #pragma unroll
    for (int i = 0; i < 8; i++) {
        lrow[i] += __shfl_xor_sync(0xFFFFFFFFu, lrow[i], 1);
        lrow[i] += __shfl_xor_sync(0xFFFFFFFFu, lrow[i], 2);
    }
    // write O
    #pragma unroll
    for (int mi = 0; mi < 4; mi++) {
        float inv0 = 1.f / lrow[mi * 2 + 0];
        float inv1 = 1.f / lrow[mi * 2 + 1];
        size_t r0 = (size_t)(base + wid * 64 + mi * 16 + g) * HID + h * DH;
        size_t r1 = r0 + (size_t)8 * HID;
        #pragma unroll
        for (int nd = 0; nd < 2; nd++) {
            *(float2*)(o + r0 + nd * 8 + 2 * t) =
                make_float2(oacc[mi][nd][0] * inv0, oacc[mi][nd][1] * inv0);
            *(float2*)(o + r1 + nd * 8 + 2 * t) =
                make_float2(oacc[mi][nd][2] * inv1, oacc[mi][nd][3] * inv1);
        }
    }
}

// ---------------- small SGEMM (M=64 pool path) ----------------
__global__ void gemm_kernel(const float* __restrict__ A,
                            const float* __restrict__ W,
                            const float* __restrict__ bias,
                            float* __restrict__ C,
                            int K, int relu) {
    __shared__ __align__(16) float As[16][68];
    __shared__ __align__(16) float Ws[16][68];
    int bm = blockIdx.y * 64;
    int bn = blockIdx.x * 64;
    int tid = threadIdx.x;
    int tx = tid & 15;
    int ty = tid >> 4;
    float acc[4][4] = {};

    for (int k0 = 0; k0 < K; k0 += 16) {
        #pragma unroll
        for (int i = tid; i < 1024; i += 256) {
            int r = i >> 4, c = i & 15;
            As[c][r] = A[(size_t)(bm + r) * K + k0 + c];
        }
        #pragma unroll
        for (int i = tid; i < 1024; i += 256) {
            int r = i >> 6, c = i & 63;
            Ws[r][c] = W[(size_t)(k0 + r) * 128 + bn + c];
        }
        __syncthreads();
        #pragma unroll
        for (int kk = 0; kk < 16; kk++) {
            float4 av = *(const float4*)&As[kk][ty * 4];
            float4 wv = *(const float4*)&Ws[kk][tx * 4];
            float a[4] = {av.x, av.y, av.z, av.w};
            float w[4] = {wv.x, wv.y, wv.z, wv.w};
            #pragma unroll
            for (int i = 0; i < 4; i++)
                #pragma unroll
                for (int j = 0; j < 4; j++)
                    acc[i][j] += a[i] * w[j];
        }
        __syncthreads();
    }
    #pragma unroll
    for (int i = 0; i < 4; i++) {
        int row = bm + ty * 4 + i;
        float4 out;
        float* po = (float*)&out;
        #pragma unroll
        for (int j = 0; j < 4; j++) {
            int col = bn + tx * 4 + j;
            float vv = acc[i][j] + (bias ? bias[col] : 0.f);
            if (relu) vv = fmaxf(vv, 0.f);
            po[j] = vv;
        }
        *(float4*)&C[(size_t)row * 128 + bn + tx * 4] = out;
    }
}

// ---------------- residual + LayerNorm (in-place on h), float4 ----------------
__global__ void ln_res_kernel(float* __restrict__ h, const float* __restrict__ a,
                              const float* __restrict__ g, const float* __restrict__ bb) {
    int row = blockIdx.x * 8 + threadIdx.y;
    int lane = threadIdx.x;
    float* hp = h + (size_t)row * HID + lane * 4;
    const float* ap = a + (size_t)row * HID + lane * 4;
    float4 hv = *(const float4*)hp;
    float4 av = *(const float4*)ap;
    float v0 = hv.x + av.x, v1 = hv.y + av.y, v2 = hv.z + av.z, v3 = hv.w + av.w;
    float sum = v0 + v1 + v2 + v3;
    float sum2 = v0 * v0 + v1 * v1 + v2 * v2 + v3 * v3;
    #pragma unroll
    for (int off = 16; off > 0; off >>= 1) {
        sum  += __shfl_xor_sync(0xFFFFFFFFu, sum, off);
        sum2 += __shfl_xor_sync(0xFFFFFFFFu, sum2, off);
    }
    float mean = sum * (1.f / HID);
    float var = sum2 * (1.f / HID) - mean * mean;
    float inv = rsqrtf(var + 1e-5f);
    float4 gv = *(const float4*)(g + lane * 4);
    float4 bv = *(const float4*)(bb + lane * 4);
    float4 out;
    out.x = (v0 - mean) * inv * gv.x + bv.x;
    out.y = (v1 - mean) * inv * gv.y + bv.y;
    out.z = (v2 - mean) * inv * gv.z + bv.z;
    out.w = (v3 - mean) * inv * gv.w + bv.w;
    *(float4*)hp = out;
}

// ---------------- masked multi-head attention (M layers) ----------------
__global__ void attn_kernel(const float* __restrict__ q, const float* __restrict__ k,
                            const float* __restrict__ v, float* __restrict__ o,
                            const unsigned* __restrict__ mask) {
    extern __shared__ float4 sm4[];
    float4* kd = sm4;           // 2048 float4
    float4* vd = sm4 + 2048;
    int b = blockIdx.x >> 3;
    int h = blockIdx.x & 7;
    int base = b * EPG;
    const float* kp = k + (size_t)base * HID + h * DH;
    const float* vp = v + (size_t)base * HID + h * DH;
    for (int i = threadIdx.x; i < 2048; i += 256) {
        int r = i >> 2, c = i & 3;
        kd[i] = *(const float4*)(kp + (size_t)r * HID + c * 4);
        vd[i] = *(const float4*)(vp + (size_t)r * HID + c * 4);
    }
    __syncthreads();

    #pragma unroll
    for (int rr = 0; rr < 2; rr++) {
        int i = threadIdx.x + rr * 256;
        const float* qp = q + (size_t)(base + i) * HID + h * DH;
        float4 q0 = *(const float4*)(qp + 0);
        float4 q1 = *(const float4*)(qp + 4);
        float4 q2 = *(const float4*)(qp + 8);
        float4 q3 = *(const float4*)(qp + 12);

        float l = 0.f;
        float4 a0 = {0,0,0,0}, a1 = {0,0,0,0}, a2 = {0,0,0,0}, a3 = {0,0,0,0};

        const unsigned* mp = mask + (size_t)(base + i) * 16;
        #pragma unroll
        for (int w = 0; w < 16; w++) {
            unsigned bits = mp[w];
            while (bits) {
                int jj = __ffs(bits) - 1;
                bits &= bits - 1;
                int j = (w << 5) + jj;
                const float4 k0 = kd[4*j+0], k1 = kd[4*j+1], k2 = kd[4*j+2], k3 = kd[4*j+3];
                float s = q0.x*k0.x + q0.y*k0.y + q0.z*k0.z + q0.w*k0.w
                        + q1.x*k1.x + q1.y*k1.y + q1.z*k1.z + q1.w*k1.w
                        + q2.x*k2.x + q2.y*k2.y + q2.z*k2.z + q2.w*k2.w
                        + q3.x*k3.x + q3.y*k3.y + q3.z*k3.z + q3.w*k3.w;
                float p = __expf(s * 0.25f);   // 1/sqrt(16)
                l += p;
                const float4 v0 = vd[4*j+0], v1 = vd[4*j+1], v2 = vd[4*j+2], v3 = vd[4*j+3];
                a0.x += p*v0.x; a0.y += p*v0.y; a0.z += p*v0.z; a0.w += p*v0.w;
                a1.x += p*v1.x; a1.y += p*v1.y; a1.z += p*v1.z; a1.w += p*v1.w;
                a2.x += p*v2.x; a2.y += p*v2.y; a2.z += p*v2.z; a2.w += p*v2.w;
                a3.x += p*v3.x; a3.y += p*v3.y; a3.z += p*v3.z; a3.w += p*v3.w;
            }
        }

        float inv = 1.f / l;
        float* op = o + (size_t)(base + i) * HID + h * DH;
        *(float4*)(op + 0)  = make_float4(a0.x*inv, a0.y*inv, a0.z*inv, a0.w*inv);
        *(float4*)(op + 4)  = make_float4(a1.x*inv, a1.y*inv, a1.z*inv, a1.w*inv);
        *(float4*)(op + 8)  = make_float4(a2.x*inv, a2.y*inv, a2.z*inv, a2.w*inv);
        *(float4*)(op + 12) = make_float4(a3.x*inv, a3.y*inv, a3.z*inv, a3.w*inv);
    }
}

// ---------------- pooling: qpool = seed @ p_Wq ----------------
__global__ void qpool_kernel(const float* __restrict__ seed, const float* __restrict__ Wq,
                             float* __restrict__ qpool) {
    int c = threadIdx.x;   // 128
    float s = 0.f;
    for (int kk = 0; kk < HID; kk++) s += seed[kk] * Wq[(size_t)kk * HID + c];
    qpool[c] = s;
}

// ---------------- PMA attention: 1 query per graph, full mask ----------------
__global__ void pool_attn_kernel(const float* __restrict__ qpool, const float* __restrict__ k,
                                 const float* __restrict__ v, float* __restrict__ pool) {
    int b = blockIdx.x;
    int w = threadIdx.x >> 5;     // head
    int lane = threadIdx.x & 31;
    float qr[DH];
    #pragma unroll
    for (int d = 0; d < DH; d++) qr[d] = qpool[w * DH + d];

    float s[16];
    float mloc = -1e30f;
    #pragma unroll
    for (int t = 0; t < 16; t++) {
        int j = lane + t * 32;
        const float* kp = k + (size_t)(b * EPG + j) * HID + w * DH;
        float acc = 0.f;
        #pragma unroll
        for (int d = 0; d < DH; d++) acc += qr[d] * kp[d];
        s[t] = acc * 0.25f;
        mloc = fmaxf(mloc, s[t]);
    }
    #pragma unroll
    for (int off = 16; off > 0; off >>= 1)
        mloc = fmaxf(mloc, __shfl_xor_sync(0xFFFFFFFFu, mloc, off));

    float l = 0.f;
    float acc[DH];
    #pragma unroll
    for (int d = 0; d < DH; d++) acc[d] = 0.f;
    #pragma unroll
    for (int t = 0; t < 16; t++) {
        int j = lane + t * 32;
        float p = __expf(s[t] - mloc);
        l += p;
        const float* vp = v + (size_t)(b * EPG + j) * HID + w * DH;
        #pragma unroll
        for (int d = 0; d < DH; d++) acc[d] += p * vp[d];
    }
    #pragma unroll
    for (int off = 16; off > 0; off >>= 1) {
        l += __shfl_xor_sync(0xFFFFFFFFu, l, off);
        #pragma unroll
        for (int d = 0; d < DH; d++)
            acc[d] += __shfl_xor_sync(0xFFFFFFFFu, acc[d], off);
    }
    if (lane == 0) {
        float inv = 1.f / l;
        #pragma unroll
        for (int d = 0; d < DH; d++)
            pool[(size_t)b * HID + w * DH + d] = acc[d] * inv;
    }
}

// ---------------- final: out[b] = o1[b] . out_W2 + out_b2 ----------------
__global__ void final_kernel(const float* __restrict__ o1, const float* __restrict__ W2,
                             const float* __restrict__ b2, float* __restrict__ out) {
    int b = blockIdx.x;
    int lane = threadIdx.x;
    float s = 0.f;
    #pragma unroll
    for (int i = 0; i < 4; i++) {
        int c = lane + 32 * i;
        s += o1[(size_t)b * HID + c] * W2[c];
    }
    #pragma unroll
    for (int off = 16; off > 0; off >>= 1)
        s += __shfl_xor_sync(0xFFFFFFFFu, s, off);
    if (lane == 0) out[b] = s + b2[0];
}

// ---------------- host launch ----------------
extern "C" void kernel_launch(void* const* d_in, const int* in_sizes, int n_in,
                              void* d_out, int out_size) {
    const float* x       = (const float*)d_in[0];
    const float* ea      = (const float*)d_in[1];
    const float* in_W1   = (const float*)d_in[2];
    const float* in_b1   = (const float*)d_in[3];
    const float* in_W2   = (const float*)d_in[4];
    const float* in_b2   = (const float*)d_in[5];
    const float* Wq      = (const float*)d_in[6];
    const float* Wk      = (const float*)d_in[7];
    const float* Wv      = (const float*)d_in[8];
    const float* Wo      = (const float*)d_in[9];
    const float* ln1_g   = (const float*)d_in[10];
    const float* ln1_b   = (const float*)d_in[11];
    const float* ln2_g   = (const float*)d_in[12];
    const float* ln2_b   = (const float*)d_in[13];
    const float* f_W1    = (const float*)d_in[14];
    const float* f_b1    = (const float*)d_in[15];
    const float* f_W2    = (const float*)d_in[16];
    const float* f_b2    = (const float*)d_in[17];
    const float* seed    = (const float*)d_in[18];
    const float* p_Wq    = (const float*)d_in[19];
    const float* p_Wk    = (const float*)d_in[20];
    const float* p_Wv    = (const float*)d_in[21];
    const float* p_Wo    = (const float*)d_in[22];
    const float* out_W1  = (const float*)d_in[23];
    const float* out_b1  = (const float*)d_in[24];
    const float* out_W2  = (const float*)d_in[25];
    const float* out_b2  = (const float*)d_in[26];
    const int*   ei      = (const int*)d_in[27];

    float *p_h, *p_q, *p_k, *p_v, *p_a, *p_t, *p_feat, *p_qpool, *p_pool, *p_pool2;
    float *p_whi, *p_wlo;
    unsigned* p_mask;
    cudaGetSymbolAddress((void**)&p_h, g_h);
    cudaGetSymbolAddress((void**)&p_q, g_q);
    cudaGetSymbolAddress((void**)&p_k, g_k);
    cudaGetSymbolAddress((void**)&p_v, g_v);
    cudaGetSymbolAddress((void**)&p_a, g_a);
    cudaGetSymbolAddress((void**)&p_t, g_t);
    cudaGetSymbolAddress((void**)&p_feat, g_feat);
    cudaGetSymbolAddress((void**)&p_mask, g_mask);
    cudaGetSymbolAddress((void**)&p_whi, g_whi);
    cudaGetSymbolAddress((void**)&p_wlo, g_wlo);
    cudaGetSymbolAddress((void**)&p_qpool, g_qpool);
    cudaGetSymbolAddress((void**)&p_pool, g_pool);
    cudaGetSymbolAddress((void**)&p_pool2, g_pool2);

    cudaFuncSetAttribute(attn_kernel, cudaFuncAttributeMaxDynamicSharedMemorySize, 65536);
    cudaFuncSetAttribute(gemm_tf32_kernel, cudaFuncAttributeMaxDynamicSharedMemorySize,
                         SMEM_GEMM_BYTES);
    cudaFuncSetAttribute(dense_attn_tc_kernel, cudaFuncAttributeMaxDynamicSharedMemorySize,
                         SMEM_DATTN);

    const dim3 g1(E_TOT / 128, 1);
    const dim3 g2(E_TOT / 128, 2);
    const dim3 g3(E_TOT / 128, 3);
    dim3 gSmall(2, 1);

    // weight pre-split + inputs
    split_w_kernel<<<W_TOTAL / 256, 256>>>(in_W1, in_W2, Wq, Wk, Wv, Wo,
                                           f_W1, f_W2, p_Wk, p_Wv, p_whi, p_wlo);
    gather_feat_kernel<<<E_TOT, FEAT_DIM>>>(x, ea, ei, p_feat);
    build_mask_kernel<<<B, 256>>>(ei, p_mask);

    #define GEMM1(Ap, OFF, Cp, bias, K, relu) \
        gemm_tf32_kernel<<<g1, 256, SMEM_GEMM_BYTES>>>(Ap, \
            p_whi + (OFF), p_whi + (OFF), p_whi + (OFF), \
            p_wlo + (OFF), p_wlo + (OFF), p_wlo + (OFF), \
            Cp, Cp, Cp, bias, K, relu)

    // input MLP
    GEMM1(p_feat, O_INW1, p_t, in_b1, FEAT_DIM, 1);
    GEMM1(p_t, O_INW2, p_h, in_b2, HID, 0);

    // transformer layers: M, M, S
    for (int L = 0; L < 3; L++) {
        const size_t wo = (size_t)L * HID * HID;
        gemm_tf32_kernel<<<g3, 256, SMEM_GEMM_BYTES>>>(p_h,
            p_whi + O_WQ + wo, p_whi + O_WK + wo, p_whi + O_WV + wo,
            p_wlo + O_WQ + wo, p_wlo + O_WK + wo, p_wlo + O_WV + wo,
            p_q, p_k, p_v, nullptr, HID, 0);
        if (L < 2)
            attn_kernel<<<B * HEADS, 256, 65536>>>(p_q, p_k, p_v, p_a, p_mask);
        else
            dense_attn_tc_kernel<<<B * HEADS, 256, SMEM_DATTN>>>(p_q, p_k, p_v, p_a);
        GEMM1(p_a, O_WO + wo, p_t, nullptr, HID, 0);
        ln_res_kernel<<<E_TOT / 8, dim3(32, 8)>>>(p_h, p_t, ln1_g + L * HID, ln1_b + L * HID);
        GEMM1(p_h, O_FW1 + wo, p_t, f_b1 + L * HID, HID, 1);
        GEMM1(p_t, O_FW2 + wo, p_a, f_b2 + L * HID, HID, 0);
        ln_res_kernel<<<E_TOT / 8, dim3(32, 8)>>>(p_h, p_a, ln2_g + L * HID, ln2_b + L * HID);
    }

    // PMA pooling (fused K/V projection)
    gemm_tf32_kernel<<<g2, 256, SMEM_GEMM_BYTES>>>(p_h,
        p_whi + O_PWK, p_whi + O_PWV, p_whi + O_PWV,
        p_wlo + O_PWK, p_wlo + O_PWV, p_wlo + O_PWV,
        p_k, p_v, p_v, nullptr, HID, 0);
    qpool_kernel<<<1, HID>>>(seed, p_Wq, p_qpool);
    pool_attn_kernel<<<B, 256>>>(p_qpool, p_k, p_v, p_pool);
    gemm_kernel<<<gSmall, 256>>>(p_pool, p_Wo, nullptr, p_pool2, HID, 0);

    // output MLP
    gemm_kernel<<<gSmall, 256>>>(p_pool2, out_W1, out_b1, p_pool, HID, 1);
    final_kernel<<<B, 32>>>(p_pool, out_W2, out_b2, (float*)d_out);
    #undef GEMM1
}

// round 12
// speedup vs baseline: 1.9203x; 1.0001x over previous
#include <cuda_runtime.h>
#include <cuda_bf16.h>

// R12 = R11 resubmission: R11 bench failed at the GPU-broker layer
// ("GB300 container failed twice") before compile/run — same transient
// signature as R5/R6 which succeeded on retry. Source unchanged.

// ---------------- problem constants ----------------
#define B 64
#define EPG 512
#define E_TOT (B * EPG)        // 32768
#define NODE_DIM 64
#define EDGE_DIM 32
#define HID 128
#define HEADS 8
#define DH 16
#define FEAT_DIM 160           // 2*64 + 32

// GEMM smem strides (words). 40 ≡ 8 (mod 32), 136 ≡ 8 (mod 32): conflict-free.
#define ASTRIDE 40
#define BSTRIDE 136
#define SMEM_GEMM_BYTES ((2 * 128 * ASTRIDE + 4 * 32 * BSTRIDE) * 4)   // 110592

// dense-attention smem strides (words) — bank-verified conflict-free.
#define KSTR 20
#define VSTR 24
#define PSTR 36
#define SMEM_DATTN ((512 * KSTR + 512 * VSTR + 8 * 64 * PSTR) * 4)     // 163840

// pre-split weight scratch offsets (floats)
#define O_INW1 0
#define O_INW2 20480
#define O_WQ   36864
#define O_WK   86016
#define O_WV   135168
#define O_WO   184320
#define O_FW1  233472
#define O_FW2  282624
#define O_PWK  331776
#define O_PWV  348160
#define W_TOTAL 364544

// ---------------- scratch (device globals; no allocs allowed) ----------------
__device__ float g_h[E_TOT * HID];
__device__ float g_q[E_TOT * HID];
__device__ float g_k[E_TOT * HID];
__device__ float g_v[E_TOT * HID];
__device__ float g_a[E_TOT * HID];
__device__ float g_t[E_TOT * HID];
__device__ float g_feat[E_TOT * FEAT_DIM];
__device__ unsigned g_mask[B * EPG * 16];   // 512 bits per (graph,row)
__device__ float g_whi[W_TOTAL];
__device__ float g_wlo[W_TOTAL];
__device__ float g_qpool[HID];
__device__ float g_pool[B * HID];
__device__ float g_pool2[B * HID];

// ---------------- tf32 / cp.async helpers ----------------
__device__ __forceinline__ unsigned f2tf32u(float f) {
    unsigned u;
    asm("cvt.rna.tf32.f32 %0, %1;" : "=r"(u) : "f"(f));
    return u;
}

__device__ __forceinline__ void split_tf32(float x, unsigned& hi, unsigned& lo) {
    hi = f2tf32u(x);
    lo = f2tf32u(x - __uint_as_float(hi));
}

__device__ __forceinline__ void cp_async16(unsigned smem_addr, const void* gptr) {
    asm volatile("cp.async.cg.shared.global [%0], [%1], 16;\n"
                 :: "r"(smem_addr), "l"(gptr));
}

__device__ __forceinline__ void mma_tf32(float* c,
                                         unsigned a0, unsigned a1, unsigned a2, unsigned a3,
                                         unsigned b0, unsigned b1) {
    asm volatile("mma.sync.aligned.m16n8k8.row.col.f32.tf32.tf32.f32 "
                 "{%0,%1,%2,%3}, {%4,%5,%6,%7}, {%8,%9}, {%0,%1,%2,%3};"
                 : "+f"(c[0]), "+f"(c[1]), "+f"(c[2]), "+f"(c[3])
                 : "r"(a0), "r"(a1), "r"(a2), "r"(a3), "r"(b0), "r"(b1));
}

// ---------------- one-shot weight pre-split: w -> (tf32 hi, tf32 lo) ----------------
__global__ void split_w_kernel(const float* __restrict__ w0, const float* __restrict__ w1,
                               const float* __restrict__ w2, const float* __restrict__ w3,
                               const float* __restrict__ w4, const float* __restrict__ w5,
                               const float* __restrict__ w6, const float* __restrict__ w7,
                               const float* __restrict__ w8, const float* __restrict__ w9,
                               float* __restrict__ hi, float* __restrict__ lo) {
    int idx = blockIdx.x * 256 + threadIdx.x;
    float v;
    if      (idx < O_INW2) v = w0[idx - O_INW1];
    else if (idx < O_WQ)   v = w1[idx - O_INW2];
    else if (idx < O_WK)   v = w2[idx - O_WQ];
    else if (idx < O_WV)   v = w3[idx - O_WK];
    else if (idx < O_WO)   v = w4[idx - O_WV];
    else if (idx < O_FW1)  v = w5[idx - O_WO];
    else if (idx < O_FW2)  v = w6[idx - O_FW1];
    else if (idx < O_PWK)  v = w7[idx - O_FW2];
    else if (idx < O_PWV)  v = w8[idx - O_PWK];
    else                   v = w9[idx - O_PWV];
    unsigned h = f2tf32u(v);
    hi[idx] = __uint_as_float(h);
    lo[idx] = __uint_as_float(f2tf32u(v - __uint_as_float(h)));
}

// ---------------- gather edge features ----------------
__global__ void gather_feat_kernel(const float* __restrict__ x,
                                   const float* __restrict__ ea,
                                   const int* __restrict__ ei,
                                   float* __restrict__ feat) {
    int e = blockIdx.x;
    int c = threadIdx.x;            // 160 threads
    int s = ei[e];
    int d = ei[E_TOT + e];
    float val;
    if (c < 64)       val = x[(size_t)s * NODE_DIM + c];
    else if (c < 128) val = x[(size_t)d * NODE_DIM + (c - 64)];
    else              val = ea[(size_t)e * EDGE_DIM + (c - 128)];
    feat[(size_t)e * FEAT_DIM + c] = val;
}

// ---------------- adjacency bitmask (edges sharing a node) ----------------
__global__ void build_mask_kernel(const int* __restrict__ ei,
                                  unsigned* __restrict__ mask) {
    int b = blockIdx.x;
    __shared__ int ss[EPG];
    __shared__ int dd[EPG];
    for (int i = threadIdx.x; i < EPG; i += blockDim.x) {
        ss[i] = ei[b * EPG + i];
        dd[i] = ei[E_TOT + b * EPG + i];
    }
    __syncthreads();
    for (int i = threadIdx.x; i < EPG; i += blockDim.x) {
        int si = ss[i], di = dd[i];
        for (int w = 0; w < 16; w++) {
            unsigned bits = 0;
            #pragma unroll
            for (int jj = 0; jj < 32; jj++) {
                int j = (w << 5) + jj;
                int sj = ss[j], dj = dd[j];
                bool adj = (si == sj) | (si == dj) | (di == sj) | (di == dj) | (i == j);
                bits |= (unsigned)adj << jj;
            }
            mask[((size_t)b * EPG + i) * 16 + w] = bits;
        }
    }
}

// ---------------- 3xTF32 tensor-core GEMM, optional fused residual+LayerNorm ----
// res == nullptr: C = act(A@W + bias)  (grid.y selects W/C for fused launches)
// res != nullptr: res = LN(res + A@W + bias) * ln_g + ln_b   (in place, full row
//                 per CTA since N == HID == 128; cross-warp smem reduction)
__global__ void __launch_bounds__(256, 2)
gemm_tf32_kernel(const float* __restrict__ A,
                 const float* __restrict__ Whi0, const float* __restrict__ Whi1,
                 const float* __restrict__ Whi2,
                 const float* __restrict__ Wlo0, const float* __restrict__ Wlo1,
                 const float* __restrict__ Wlo2,
                 float* __restrict__ C0, float* __restrict__ C1, float* __restrict__ C2,
                 const float* __restrict__ bias, int K, int relu,
                 const float* __restrict__ ln_g, const float* __restrict__ ln_b,
                 float* __restrict__ res) {
    const float* WH = (blockIdx.y == 0) ? Whi0 : (blockIdx.y == 1 ? Whi1 : Whi2);
    const float* WL = (blockIdx.y == 0) ? Wlo0 : (blockIdx.y == 1 ? Wlo1 : Wlo2);
    float* C        = (blockIdx.y == 0) ? C0   : (blockIdx.y == 1 ? C1   : C2);

    extern __shared__ float sm[];
    float* Abuf[2]  = { sm, sm + 128 * ASTRIDE };
    float* BHbuf[2] = { sm + 2 * 128 * ASTRIDE,
                        sm + 2 * 128 * ASTRIDE + 32 * BSTRIDE };
    float* BLbuf[2] = { sm + 2 * 128 * ASTRIDE + 2 * 32 * BSTRIDE,
                        sm + 2 * 128 * ASTRIDE + 3 * 32 * BSTRIDE };

    const int tid = threadIdx.x;
    const int lane = tid & 31;
    const int wid = tid >> 5;
    const int wm = wid >> 1;
    const int wn = wid & 1;
    const int g = lane >> 2;
    const int t = lane & 3;
    const int bm = blockIdx.x * 128;

    float acc[2][8][4];
    #pragma unroll
    for (int i = 0; i < 2; i++)
        #pragma unroll
        for (int j = 0; j < 8; j++)
            #pragma unroll
            for (int r = 0; r < 4; r++) acc[i][j][r] = 0.f;

    const int nst = K >> 5;

    const int a_c4 = tid & 7;
    const int b_n4 = tid & 31;
    const unsigned sA[2]  = { (unsigned)__cvta_generic_to_shared(Abuf[0]),
                              (unsigned)__cvta_generic_to_shared(Abuf[1]) };
    const unsigned sBH[2] = { (unsigned)__cvta_generic_to_shared(BHbuf[0]),
                              (unsigned)__cvta_generic_to_shared(BHbuf[1]) };
    const unsigned sBL[2] = { (unsigned)__cvta_generic_to_shared(BLbuf[0]),
                              (unsigned)__cvta_generic_to_shared(BLbuf[1]) };

    auto load_stage = [&](int buf, int s) {
        const int k0 = s * 32;
        #pragma unroll
        for (int u = 0; u < 4; u++) {
            int rA = (tid >> 3) + 32 * u;
            cp_async16(sA[buf] + (unsigned)((rA * ASTRIDE + a_c4 * 4) << 2),
                       A + (size_t)(bm + rA) * K + k0 + a_c4 * 4);
            int rB = (tid >> 5) + 8 * u;
            unsigned boff = (unsigned)((rB * BSTRIDE + b_n4 * 4) << 2);
            const size_t gw = (size_t)(k0 + rB) * 128 + b_n4 * 4;
            cp_async16(sBH[buf] + boff, WH + gw);
            cp_async16(sBL[buf] + boff, WL + gw);
        }
        asm volatile("cp.async.commit_group;\n" ::: "memory");
    };

    load_stage(0, 0);
    if (nst > 1) load_stage(1, 1);

    for (int s = 0; s < nst; s++) {
        if (s + 1 < nst)
            asm volatile("cp.async.wait_group 1;\n" ::: "memory");
        else
            asm volatile("cp.async.wait_group 0;\n" ::: "memory");
        __syncthreads();

        const float* As = Abuf[s & 1];
        const float* BsH = BHbuf[s & 1];
        const float* BsL = BLbuf[s & 1];

        #pragma unroll
        for (int kq = 0; kq < 4; kq++) {
            const int koff = kq * 8;
            unsigned ah[2][4], al[2][4];
            #pragma unroll
            for (int i = 0; i < 2; i++) {
                int m0 = wm * 32 + i * 16;
                const float* p0 = As + (m0 + g) * ASTRIDE + koff + t;
                const float* p1 = As + (m0 + g + 8) * ASTRIDE + koff + t;
                split_tf32(p0[0], ah[i][0], al[i][0]);
                split_tf32(p1[0], ah[i][1], al[i][1]);
                split_tf32(p0[4], ah[i][2], al[i][2]);
                split_tf32(p1[4], ah[i][3], al[i][3]);
            }
            #pragma unroll
            for (int j = 0; j < 8; j++) {
                int n0 = wn * 64 + j * 8;
                unsigned bh0 = __float_as_uint(BsH[(koff + t) * BSTRIDE + n0 + g]);
                unsigned bh1 = __float_as_uint(BsH[(koff + t + 4) * BSTRIDE + n0 + g]);
                unsigned bl0 = __float_as_uint(BsL[(koff + t) * BSTRIDE + n0 + g]);
                unsigned bl1 = __float_as_uint(BsL[(koff + t + 4) * BSTRIDE + n0 + g]);
                #pragma unroll
                for (int i = 0; i < 2; i++) {
                    float* cc = acc[i][j];
                    mma_tf32(cc, ah[i][0], ah[i][1], ah[i][2], ah[i][3], bl0, bl1);
                    mma_tf32(cc, al[i][0], al[i][1], al[i][2], al[i][3], bh0, bh1);
                    mma_tf32(cc, ah[i][0], ah[i][1], ah[i][2], ah[i][3], bh0, bh1);
                }
            }
        }
        __syncthreads();
        if (s + 2 < nst) load_stage(s & 1, s + 2);
    }

    if (res != nullptr) {
        // -------- fused residual + LayerNorm epilogue (writes res in place) ------
        float* sb = sm;   // safe: all warps passed final __syncthreads() above
        float rs[2][2], rq[2][2];
        #pragma unroll
        for (int i = 0; i < 2; i++) {
            int row0 = bm + wm * 32 + i * 16 + g;
            float s0 = 0.f, s1 = 0.f, q0 = 0.f, q1 = 0.f;
            #pragma unroll
            for (int j = 0; j < 8; j++) {
                int col = wn * 64 + j * 8 + t * 2;
                float bv0 = bias ? bias[col] : 0.f;
                float bv1 = bias ? bias[col + 1] : 0.f;
                float2 r0 = *(const float2*)&res[(size_t)row0 * 128 + col];
                float2 r1 = *(const float2*)&res[(size_t)(row0 + 8) * 128 + col];
                float v0 = acc[i][j][0] + bv0 + r0.x;
                float v1 = acc[i][j][1] + bv1 + r0.y;
                float v2 = acc[i][j][2] + bv0 + r1.x;
                float v3 = acc[i][j][3] + bv1 + r1.y;
                acc[i][j][0] = v0; acc[i][j][1] = v1;
                acc[i][j][2] = v2; acc[i][j][3] = v3;
                s0 += v0 + v1; q0 += v0 * v0 + v1 * v1;
                s1 += v2 + v3; q1 += v2 * v2 + v3 * v3;
            }
            #pragma unroll
            for (int off = 1; off < 4; off <<= 1) {
                s0 += __shfl_xor_sync(0xFFFFFFFFu, s0, off);
                q0 += __shfl_xor_sync(0xFFFFFFFFu, q0, off);
                s1 += __shfl_xor_sync(0xFFFFFFFFu, s1, off);
                q1 += __shfl_xor_sync(0xFFFFFFFFu, q1, off);
            }
            rs[i][0] = s0; rq[i][0] = q0; rs[i][1] = s1; rq[i][1] = q1;
        }
        if (t == 0) {
            #pragma unroll
            for (int i = 0; i < 2; i++) {
                int rl = wm * 32 + i * 16 + g;
                *(float2*)&sb[(wn * 128 + rl) * 2] = make_float2(rs[i][0], rq[i][0]);
                *(float2*)&sb[(wn * 128 + rl + 8) * 2] = make_float2(rs[i][1], rq[i][1]);
            }
        }
        __syncthreads();
        #pragma unroll
        for (int i = 0; i < 2; i++) {
            int rl = wm * 32 + i * 16 + g;
            #pragma unroll
            for (int rh = 0; rh < 2; rh++) {
                float2 p0 = *(float2*)&sb[(rl + rh * 8) * 2];
                float2 p1 = *(float2*)&sb[(128 + rl + rh * 8) * 2];
                float S = p0.x + p1.x, Q = p0.y + p1.y;
                float mean = S * (1.f / 128.f);
                float var = Q * (1.f / 128.f) - mean * mean;
                float inv = rsqrtf(var + 1e-5f);
                int row = bm + rl + rh * 8;
                #pragma unroll
                for (int j = 0; j < 8; j++) {
                    int col = wn * 64 + j * 8 + t * 2;
                    float v0 = acc[i][j][rh * 2 + 0];
                    float v1 = acc[i][j][rh * 2 + 1];
                    *(float2*)&res[(size_t)row * 128 + col] = make_float2(
                        (v0 - mean) * inv * ln_g[col] + ln_b[col],
                        (v1 - mean) * inv * ln_g[col + 1] + ln_b[col + 1]);
                }
            }
        }
        return;
    }

    // -------- plain epilogue --------
    #pragma unroll
    for (int i = 0; i < 2; i++) {
        int row0 = bm + wm * 32 + i * 16 + g;
        #pragma unroll
        for (int j = 0; j < 8; j++) {
            int col = wn * 64 + j * 8 + t * 2;
            float bv0 = bias ? bias[col] : 0.f;
            float bv1 = bias ? bias[col + 1] : 0.f;
            float v0 = acc[i][j][0] + bv0, v1 = acc[i][j][1] + bv1;
            float v2 = acc[i][j][2] + bv0, v3 = acc[i][j][3] + bv1;
            if (relu) {
                v0 = fmaxf(v0, 0.f); v1 = fmaxf(v1, 0.f);
                v2 = fmaxf(v2, 0.f); v3 = fmaxf(v3, 0.f);
            }
            *(float2*)&C[(size_t)row0 * 128 + col] = make_float2(v0, v1);
            *(float2*)&C[(size_t)(row0 + 8) * 128 + col] = make_float2(v2, v3);
        }
    }
}

// ---------------- dense (S-layer) attention on tensor cores ----------------
__global__ void __launch_bounds__(256, 1)
dense_attn_tc_kernel(const float* __restrict__ q, const float* __restrict__ k,
                     const float* __restrict__ v, float* __restrict__ o) {
    extern __shared__ float sm[];
    float* Ks = sm;                      // [512][KSTR]
    float* Vs = Ks + 512 * KSTR;         // [512][VSTR]
    float* Ps = Vs + 512 * VSTR;         // [8][64][PSTR]
    const int b = blockIdx.x >> 3, h = blockIdx.x & 7;
    const int base = b * EPG;
    const int tid = threadIdx.x, lane = tid & 31, wid = tid >> 5;
    const int g = lane >> 2, t = lane & 3;
    float* Pw = Ps + wid * 64 * PSTR;

    for (int i = tid; i < 2048; i += 256) {
        int r = i >> 2, c4 = (i & 3) * 4;
        float4 kv = *(const float4*)(k + (size_t)(base + r) * HID + h * DH + c4);
        float4 vv = *(const float4*)(v + (size_t)(base + r) * HID + h * DH + c4);
        Ks[r * KSTR + c4 + 0] = kv.x; Ks[r * KSTR + c4 + 1] = kv.y;
        Ks[r * KSTR + c4 + 2] = kv.z; Ks[r * KSTR + c4 + 3] = kv.w;
        Vs[r * VSTR + c4 + 0] = vv.x; Vs[r * VSTR + c4 + 1] = vv.y;
        Vs[r * VSTR + c4 + 2] = vv.z; Vs[r * VSTR + c4 + 3] = vv.w;
    }

    unsigned qh[4][2][4], ql[4][2][4];
    #pragma unroll
    for (int mi = 0; mi < 4; mi++) {
        const size_t r0 = (size_t)(base + wid * 64 + mi * 16 + g) * HID + h * DH;
        const size_t r1 = r0 + (size_t)8 * HID;
        #pragma unroll
        for (int ko = 0; ko < 2; ko++) {
            split_tf32(q[r0 + ko * 8 + t],     qh[mi][ko][0], ql[mi][ko][0]);
            split_tf32(q[r1 + ko * 8 + t],     qh[mi][ko][1], ql[mi][ko][1]);
            split_tf32(q[r0 + ko * 8 + t + 4], qh[mi][ko][2], ql[mi][ko][2]);
            split_tf32(q[r1 + ko * 8 + t + 4], qh[mi][ko][3], ql[mi][ko][3]);
        }
    }
    __syncthreads();

    float oacc[4][2][4] = {};
    float lrow[8] = {};

    for (int kc = 0; kc < 16; kc++) {
        const int j0 = kc * 32;
        float sacc[4][4][4] = {};
        #pragma unroll
        for (int ko = 0; ko < 2; ko++) {
            #pragma unroll
            for (int nj = 0; nj < 4; nj++) {
                const float* kp = Ks + (j0 + nj * 8 + g) * KSTR + ko * 8 + t;
                unsigned bh0, bl0, bh1, bl1;
                split_tf32(kp[0], bh0, bl0);
                split_tf32(kp[4], bh1, bl1);
                #pragma unroll
                for (int mi = 0; mi < 4; mi++) {
                    float* cc = sacc[mi][nj];
                    mma_tf32(cc, qh[mi][ko][0], qh[mi][ko][1], qh[mi][ko][2], qh[mi][ko][3], bl0, bl1);
                    mma_tf32(cc, ql[mi][ko][0], ql[mi][ko][1], ql[mi][ko][2], ql[mi][ko][3], bh0, bh1);
                    mma_tf32(cc, qh[mi][ko][0], qh[mi][ko][1], qh[mi][ko][2], qh[mi][ko][3], bh0, bh1);
                }
            }
        }
        #pragma unroll
        for (int mi = 0; mi < 4; mi++) {
            #pragma unroll
            for (int nj = 0; nj < 4; nj++) {
                float p0 = __uint_as_float(f2tf32u(__expf(sacc[mi][nj][0] * 0.25f)));
                float p1 = __uint_as_float(f2tf32u(__expf(sacc[mi][nj][1] * 0.25f)));
                float p2 = __uint_as_float(f2tf32u(__expf(sacc[mi][nj][2] * 0.25f)));
                float p3 = __uint_as_float(f2tf32u(__expf(sacc[mi][nj][3] * 0.25f)));
                lrow[mi * 2 + 0] += p0 + p1;
                lrow[mi * 2 + 1] += p2 + p3;
                *(float2*)(Pw + (mi * 16 + g) * PSTR + nj * 8 + 2 * t) = make_float2(p0, p1);
                *(float2*)(Pw + (mi * 16 + g + 8) * PSTR + nj * 8 + 2 * t) = make_float2(p2, p3);
            }
        }
        __syncwarp();
        #pragma unroll
        for (int k2 = 0; k2 < 4; k2++) {
            unsigned pa[4][4];
            #pragma unroll
            for (int mi = 0; mi < 4; mi++) {
                const float* p0 = Pw + (mi * 16 + g) * PSTR + k2 * 8 + t;
                const float* p1 = Pw + (mi * 16 + g + 8) * PSTR + k2 * 8 + t;
                pa[mi][0] = __float_as_uint(p0[0]);
                pa[mi][1] = __float_as_uint(p1[0]);
                pa[mi][2] = __float_as_uint(p0[4]);
                pa[mi][3] = __float_as_uint(p1[4]);
            }
            #pragma unroll
            for (int nd = 0; nd < 2; nd++) {
                unsigned vb0 = f2tf32u(Vs[(j0 + k2 * 8 + t) * VSTR + nd * 8 + g]);
                unsigned vb1 = f2tf32u(Vs[(j0 + k2 * 8 + t + 4) * VSTR + nd * 8 + g]);
                #pragma unroll
                for (int mi = 0; mi < 4; mi++)
                    mma_tf32(oacc[mi][nd], pa[mi][0], pa[mi][1], pa[mi][2], pa[mi][3], vb0, vb1);
            }
        }
        __syncwarp();
    }

    #pragma unroll
    for (int i = 0; i < 8; i++) {
        lrow[i] += __shfl_xor_sync(0xFFFFFFFFu, lrow[i], 1);
        lrow[i] += __shfl_xor_sync(0xFFFFFFFFu, lrow[i], 2);
    }
    #pragma unroll
    for (int mi = 0; mi < 4; mi++) {
        float inv0 = 1.f / lrow[mi * 2 + 0];
        float inv1 = 1.f / lrow[mi * 2 + 1];
        size_t r0 = (size_t)(base + wid * 64 + mi * 16 + g) * HID + h * DH;
        size_t r1 = r0 + (size_t)8 * HID;
        #pragma unroll
        for (int nd = 0; nd < 2; nd++) {
            *(float2*)(o + r0 + nd * 8 + 2 * t) =
                make_float2(oacc[mi][nd][0] * inv0, oacc[mi][nd][1] * inv0);
            *(float2*)(o + r1 + nd * 8 + 2 * t) =
                make_float2(oacc[mi][nd][2] * inv1, oacc[mi][nd][3] * inv1);
        }
    }
}

// ---------------- small SGEMM (M=64 pool path) ----------------
__global__ void gemm_kernel(const float* __restrict__ A,
                            const float* __restrict__ W,
                            const float* __restrict__ bias,
                            float* __restrict__ C,
                            int K, int relu) {
    __shared__ __align__(16) float As[16][68];
    __shared__ __align__(16) float Ws[16][68];
    int bm = blockIdx.y * 64;
    int bn = blockIdx.x * 64;
    int tid = threadIdx.x;
    int tx = tid & 15;
    int ty = tid >> 4;
    float acc[4][4] = {};

    for (int k0 = 0; k0 < K; k0 += 16) {
        #pragma unroll
        for (int i = tid; i < 1024; i += 256) {
            int r = i >> 4, c = i & 15;
            As[c][r] = A[(size_t)(bm + r) * K + k0 + c];
        }
        #pragma unroll
        for (int i = tid; i < 1024; i += 256) {
            int r = i >> 6, c = i & 63;
            Ws[r][c] = W[(size_t)(k0 + r) * 128 + bn + c];
        }
        __syncthreads();
        #pragma unroll
        for (int kk = 0; kk < 16; kk++) {
            float4 av = *(const float4*)&As[kk][ty * 4];
            float4 wv = *(const float4*)&Ws[kk][tx * 4];
            float a[4] = {av.x, av.y, av.z, av.w};
            float w[4] = {wv.x, wv.y, wv.z, wv.w};
            #pragma unroll
            for (int i = 0; i < 4; i++)
                #pragma unroll
                for (int j = 0; j < 4; j++)
                    acc[i][j] += a[i] * w[j];
        }
        __syncthreads();
    }
    #pragma unroll
    for (int i = 0; i < 4; i++) {
        int row = bm + ty * 4 + i;
        float4 out;
        float* po = (float*)&out;
        #pragma unroll
        for (int j = 0; j < 4; j++) {
            int col = bn + tx * 4 + j;
            float vv = acc[i][j] + (bias ? bias[col] : 0.f);
            if (relu) vv = fmaxf(vv, 0.f);
            po[j] = vv;
        }
        *(float4*)&C[(size_t)row * 128 + bn + tx * 4] = out;
    }
}

// ---------------- masked multi-head attention (M layers) ----------------
__global__ void attn_kernel(const float* __restrict__ q, const float* __restrict__ k,
                            const float* __restrict__ v, float* __restrict__ o,
                            const unsigned* __restrict__ mask) {
    extern __shared__ float4 sm4[];
    float4* kd = sm4;           // 2048 float4
    float4* vd = sm4 + 2048;
    int b = blockIdx.x >> 3;
    int h = blockIdx.x & 7;
    int base = b * EPG;
    const float* kp = k + (size_t)base * HID + h * DH;
    const float* vp = v + (size_t)base * HID + h * DH;
    for (int i = threadIdx.x; i < 2048; i += 256) {
        int r = i >> 2, c = i & 3;
        kd[i] = *(const float4*)(kp + (size_t)r * HID + c * 4);
        vd[i] = *(const float4*)(vp + (size_t)r * HID + c * 4);
    }
    __syncthreads();

    #pragma unroll
    for (int rr = 0; rr < 2; rr++) {
        int i = threadIdx.x + rr * 256;
        const float* qp = q + (size_t)(base + i) * HID + h * DH;
        float4 q0 = *(const float4*)(qp + 0);
        float4 q1 = *(const float4*)(qp + 4);
        float4 q2 = *(const float4*)(qp + 8);
        float4 q3 = *(const float4*)(qp + 12);

        float l = 0.f;
        float4 a0 = {0,0,0,0}, a1 = {0,0,0,0}, a2 = {0,0,0,0}, a3 = {0,0,0,0};

        const unsigned* mp = mask + (size_t)(base + i) * 16;
        #pragma unroll
        for (int w = 0; w < 16; w++) {
            unsigned bits = mp[w];
            while (bits) {
                int jj = __ffs(bits) - 1;
                bits &= bits - 1;
                int j = (w << 5) + jj;
                const float4 k0 = kd[4*j+0], k1 = kd[4*j+1], k2 = kd[4*j+2], k3 = kd[4*j+3];
                float s = q0.x*k0.x + q0.y*k0.y + q0.z*k0.z + q0.w*k0.w
                        + q1.x*k1.x + q1.y*k1.y + q1.z*k1.z + q1.w*k1.w
                        + q2.x*k2.x + q2.y*k2.y + q2.z*k2.z + q2.w*k2.w
                        + q3.x*k3.x + q3.y*k3.y + q3.z*k3.z + q3.w*k3.w;
                float p = __expf(s * 0.25f);   // 1/sqrt(16)
                l += p;
                const float4 v0 = vd[4*j+0], v1 = vd[4*j+1], v2 = vd[4*j+2], v3 = vd[4*j+3];
                a0.x += p*v0.x; a0.y += p*v0.y; a0.z += p*v0.z; a0.w += p*v0.w;
                a1.x += p*v1.x; a1.y += p*v1.y; a1.z += p*v1.z; a1.w += p*v1.w;
                a2.x += p*v2.x; a2.y += p*v2.y; a2.z += p*v2.z; a2.w += p*v2.w;
                a3.x += p*v3.x; a3.y += p*v3.y; a3.z += p*v3.z; a3.w += p*v3.w;
            }
        }

        float inv = 1.f / l;
        float* op = o + (size_t)(base + i) * HID + h * DH;
        *(float4*)(op + 0)  = make_float4(a0.x*inv, a0.y*inv, a0.z*inv, a0.w*inv);
        *(float4*)(op + 4)  = make_float4(a1.x*inv, a1.y*inv, a1.z*inv, a1.w*inv);
        *(float4*)(op + 8)  = make_float4(a2.x*inv, a2.y*inv, a2.z*inv, a2.w*inv);
        *(float4*)(op + 12) = make_float4(a3.x*inv, a3.y*inv, a3.z*inv, a3.w*inv);
    }
}

// ---------------- pooling: qpool = seed @ p_Wq ----------------
__global__ void qpool_kernel(const float* __restrict__ seed, const float* __restrict__ Wq,
                             float* __restrict__ qpool) {
    int c = threadIdx.x;   // 128
    float s = 0.f;
    for (int kk = 0; kk < HID; kk++) s += seed[kk] * Wq[(size_t)kk * HID + c];
    qpool[c] = s;
}

// ---------------- PMA attention: 1 query per graph, full mask ----------------
__global__ void pool_attn_kernel(const float* __restrict__ qpool, const float* __restrict__ k,
                                 const float* __restrict__ v, float* __restrict__ pool) {
    int b = blockIdx.x;
    int w = threadIdx.x >> 5;     // head
    int lane = threadIdx.x & 31;
    float qr[DH];
    #pragma unroll
    for (int d = 0; d < DH; d++) qr[d] = qpool[w * DH + d];

    float s[16];
    float mloc = -1e30f;
    #pragma unroll
    for (int t = 0; t < 16; t++) {
        int j = lane + t * 32;
        const float* kp = k + (size_t)(b * EPG + j) * HID + w * DH;
        float acc = 0.f;
        #pragma unroll
        for (int d = 0; d < DH; d++) acc += qr[d] * kp[d];
        s[t] = acc * 0.25f;
        mloc = fmaxf(mloc, s[t]);
    }
    #pragma unroll
    for (int off = 16; off > 0; off >>= 1)
        mloc = fmaxf(mloc, __shfl_xor_sync(0xFFFFFFFFu, mloc, off));

    float l = 0.f;
    float acc[DH];
    #pragma unroll
    for (int d = 0; d < DH; d++) acc[d] = 0.f;
    #pragma unroll
    for (int t = 0; t < 16; t++) {
        int j = lane + t * 32;
        float p = __expf(s[t] - mloc);
        l += p;
        const float* vp = v + (size_t)(b * EPG + j) * HID + w * DH;
        #pragma unroll
        for (int d = 0; d < DH; d++) acc[d] += p * vp[d];
    }
    #pragma unroll
    for (int off = 16; off > 0; off >>= 1) {
        l += __shfl_xor_sync(0xFFFFFFFFu, l, off);
        #pragma unroll
        for (int d = 0; d < DH; d++)
            acc[d] += __shfl_xor_sync(0xFFFFFFFFu, acc[d], off);
    }
    if (lane == 0) {
        float inv = 1.f / l;
        #pragma unroll
        for (int d = 0; d < DH; d++)
            pool[(size_t)b * HID + w * DH + d] = acc[d] * inv;
    }
}

// ---------------- final: out[b] = o1[b] . out_W2 + out_b2 ----------------
__global__ void final_kernel(const float* __restrict__ o1, const float* __restrict__ W2,
                             const float* __restrict__ b2, float* __restrict__ out) {
    int b = blockIdx.x;
    int lane = threadIdx.x;
    float s = 0.f;
    #pragma unroll
    for (int i = 0; i < 4; i++) {
        int c = lane + 32 * i;
        s += o1[(size_t)b * HID + c] * W2[c];
    }
    #pragma unroll
    for (int off = 16; off > 0; off >>= 1)
        s += __shfl_xor_sync(0xFFFFFFFFu, s, off);
    if (lane == 0) out[b] = s + b2[0];
}

// ---------------- host launch ----------------
extern "C" void kernel_launch(void* const* d_in, const int* in_sizes, int n_in,
                              void* d_out, int out_size) {
    const float* x       = (const float*)d_in[0];
    const float* ea      = (const float*)d_in[1];
    const float* in_W1   = (const float*)d_in[2];
    const float* in_b1   = (const float*)d_in[3];
    const float* in_W2   = (const float*)d_in[4];
    const float* in_b2   = (const float*)d_in[5];
    const float* Wq      = (const float*)d_in[6];
    const float* Wk      = (const float*)d_in[7];
    const float* Wv      = (const float*)d_in[8];
    const float* Wo      = (const float*)d_in[9];
    const float* ln1_g   = (const float*)d_in[10];
    const float* ln1_b   = (const float*)d_in[11];
    const float* ln2_g   = (const float*)d_in[12];
    const float* ln2_b   = (const float*)d_in[13];
    const float* f_W1    = (const float*)d_in[14];
    const float* f_b1    = (const float*)d_in[15];
    const float* f_W2    = (const float*)d_in[16];
    const float* f_b2    = (const float*)d_in[17];
    const float* seed    = (const float*)d_in[18];
    const float* p_Wq    = (const float*)d_in[19];
    const float* p_Wk    = (const float*)d_in[20];
    const float* p_Wv    = (const float*)d_in[21];
    const float* p_Wo    = (const float*)d_in[22];
    const float* out_W1  = (const float*)d_in[23];
    const float* out_b1  = (const float*)d_in[24];
    const float* out_W2  = (const float*)d_in[25];
    const float* out_b2  = (const float*)d_in[26];
    const int*   ei      = (const int*)d_in[27];

    float *p_h, *p_q, *p_k, *p_v, *p_a, *p_t, *p_feat, *p_qpool, *p_pool, *p_pool2;
    float *p_whi, *p_wlo;
    unsigned* p_mask;
    cudaGetSymbolAddress((void**)&p_h, g_h);
    cudaGetSymbolAddress((void**)&p_q, g_q);
    cudaGetSymbolAddress((void**)&p_k, g_k);
    cudaGetSymbolAddress((void**)&p_v, g_v);
    cudaGetSymbolAddress((void**)&p_a, g_a);
    cudaGetSymbolAddress((void**)&p_t, g_t);
    cudaGetSymbolAddress((void**)&p_feat, g_feat);
    cudaGetSymbolAddress((void**)&p_mask, g_mask);
    cudaGetSymbolAddress((void**)&p_whi, g_whi);
    cudaGetSymbolAddress((void**)&p_wlo, g_wlo);
    cudaGetSymbolAddress((void**)&p_qpool, g_qpool);
    cudaGetSymbolAddress((void**)&p_pool, g_pool);
    cudaGetSymbolAddress((void**)&p_pool2, g_pool2);

    cudaFuncSetAttribute(attn_kernel, cudaFuncAttributeMaxDynamicSharedMemorySize, 65536);
    cudaFuncSetAttribute(gemm_tf32_kernel, cudaFuncAttributeMaxDynamicSharedMemorySize,
                         SMEM_GEMM_BYTES);
    cudaFuncSetAttribute(dense_attn_tc_kernel, cudaFuncAttributeMaxDynamicSharedMemorySize,
                         SMEM_DATTN);

    const dim3 g1(E_TOT / 128, 1);
    const dim3 g2(E_TOT / 128, 2);
    const dim3 g3(E_TOT / 128, 3);
    dim3 gSmall(2, 1);

    // weight pre-split + inputs
    split_w_kernel<<<W_TOTAL / 256, 256>>>(in_W1, in_W2, Wq, Wk, Wv, Wo,
                                           f_W1, f_W2, p_Wk, p_Wv, p_whi, p_wlo);
    gather_feat_kernel<<<E_TOT, FEAT_DIM>>>(x, ea, ei, p_feat);
    build_mask_kernel<<<B, 256>>>(ei, p_mask);

    #define GEMM1(Ap, OFF, Cp, bias, K, relu) \
        gemm_tf32_kernel<<<g1, 256, SMEM_GEMM_BYTES>>>(Ap, \
            p_whi + (OFF), p_whi + (OFF), p_whi + (OFF), \
            p_wlo + (OFF), p_wlo + (OFF), p_wlo + (OFF), \
            Cp, Cp, Cp, bias, K, relu, nullptr, nullptr, nullptr)

    #define GEMM1_LN(Ap, OFF, bias, lng, lnb, resp) \
        gemm_tf32_kernel<<<g1, 256, SMEM_GEMM_BYTES>>>(Ap, \
            p_whi + (OFF), p_whi + (OFF), p_whi + (OFF), \
            p_wlo + (OFF), p_wlo + (OFF), p_wlo + (OFF), \
            nullptr, nullptr, nullptr, bias, HID, 0, lng, lnb, resp)

    // input MLP
    GEMM1(p_feat, O_INW1, p_t, in_b1, FEAT_DIM, 1);
    GEMM1(p_t, O_INW2, p_h, in_b2, HID, 0);

    // transformer layers: M, M, S
    for (int L = 0; L < 3; L++) {
        const size_t wo = (size_t)L * HID * HID;
        gemm_tf32_kernel<<<g3, 256, SMEM_GEMM_BYTES>>>(p_h,
            p_whi + O_WQ + wo, p_whi + O_WK + wo, p_whi + O_WV + wo,
            p_wlo + O_WQ + wo, p_wlo + O_WK + wo, p_wlo + O_WV + wo,
            p_q, p_k, p_v, nullptr, HID, 0, nullptr, nullptr, nullptr);
        if (L < 2)
            attn_kernel<<<B * HEADS, 256, 65536>>>(p_q, p_k, p_v, p_a, p_mask);
        else
            dense_attn_tc_kernel<<<B * HEADS, 256, SMEM_DATTN>>>(p_q, p_k, p_v, p_a);
        // h = LN(h + a@Wo) fused
        GEMM1_LN(p_a, O_WO + wo, nullptr, ln1_g + L * HID, ln1_b + L * HID, p_h);
        // t = relu(h@W1 + b1)
        GEMM1(p_h, O_FW1 + wo, p_t, f_b1 + L * HID, HID, 1);
        // h = LN(h + t@W2 + b2) fused
        GEMM1_LN(p_t, O_FW2 + wo, f_b2 + L * HID, ln2_g + L * HID, ln2_b + L * HID, p_h);
    }

    // PMA pooling (fused K/V projection)
    gemm_tf32_kernel<<<g2, 256, SMEM_GEMM_BYTES>>>(p_h,
        p_whi + O_PWK, p_whi + O_PWV, p_whi + O_PWV,
        p_wlo + O_PWK, p_wlo + O_PWV, p_wlo + O_PWV,
        p_k, p_v, p_v, nullptr, HID, 0, nullptr, nullptr, nullptr);
    qpool_kernel<<<1, HID>>>(seed, p_Wq, p_qpool);
    pool_attn_kernel<<<B, 256>>>(p_qpool, p_k, p_v, p_pool);
    gemm_kernel<<<gSmall, 256>>>(p_pool, p_Wo, nullptr, p_pool2, HID, 0);

    // output MLP
    gemm_kernel<<<gSmall, 256>>>(p_pool2, out_W1, out_b1, p_pool, HID, 1);
    final_kernel<<<B, 32>>>(p_pool, out_W2, out_b2, (float*)d_out);
    #undef GEMM1
    #undef GEMM1_LN
}

// round 14
// speedup vs baseline: 2.3826x; 1.2408x over previous
#include <cuda_runtime.h>
#include <cuda_bf16.h>

// R14 = R13 resubmission: R13 failed at the GPU-broker layer (container
// acquisition) before compile/run — same transient signature as R5/R6/R11,
// each of which succeeded on identical-source retry. Source unchanged.

// ---------------- problem constants ----------------
#define B 64
#define EPG 512
#define E_TOT (B * EPG)        // 32768
#define NODE_DIM 64
#define EDGE_DIM 32
#define HID 128
#define HEADS 8
#define DH 16
#define FEAT_DIM 160           // 2*64 + 32

// GEMM smem strides. A: fp32 words, 40 ≡ 8 (mod 32); float2 frag loads use
// 8B banks: (20g+t) mod 32 bijective -> conflict-free. B: packed bf16x2
// unsigned, stride 136 ≡ 8 (mod 32): (8t+g) bijective -> conflict-free.
#define ASTRIDE 40
#define BSTRIDE 136
// A raw fp32 double-buffered + B packed hi/lo double-buffered
// = (2*128*40 + 4*16*136) * 4 bytes = 75776
#define SMEM_GEMM_BYTES ((2 * 128 * ASTRIDE + 4 * 16 * BSTRIDE) * 4)

// dense-attention smem strides (words) — bank-verified conflict-free.
#define KSTR 20
#define VSTR 24
#define PSTR 36
#define SMEM_DATTN ((512 * KSTR + 512 * VSTR + 8 * 64 * PSTR) * 4)     // 163840

// pre-split packed-bf16 weight offsets (in k-PAIR units: [k/2][128])
#define P_INW1 0
#define P_INW2 10240
#define P_WQ   18432
#define P_WK   43008
#define P_WV   67584
#define P_WO   92160
#define P_FW1  116736
#define P_FW2  141312
#define P_PWK  165888
#define P_PWV  174080
#define W_PAIRS 182272
#define LAYER_PSTRIDE 8192

// ---------------- scratch (device globals; no allocs allowed) ----------------
__device__ float g_h[E_TOT * HID];
__device__ float g_q[E_TOT * HID];
__device__ float g_k[E_TOT * HID];
__device__ float g_v[E_TOT * HID];
__device__ float g_a[E_TOT * HID];
__device__ float g_t[E_TOT * HID];
__device__ float g_feat[E_TOT * FEAT_DIM];
__device__ unsigned g_mask[B * EPG * 16];   // 512 bits per (graph,row)
__device__ unsigned g_wphi[W_PAIRS];
__device__ unsigned g_wplo[W_PAIRS];
__device__ float g_qpool[HID];
__device__ float g_pool[B * HID];
__device__ float g_pool2[B * HID];

// ---------------- helpers ----------------
__device__ __forceinline__ unsigned f2tf32u(float f) {
    unsigned u;
    asm("cvt.rna.tf32.f32 %0, %1;" : "=r"(u) : "f"(f));
    return u;
}

__device__ __forceinline__ void split_tf32(float x, unsigned& hi, unsigned& lo) {
    hi = f2tf32u(x);
    lo = f2tf32u(x - __uint_as_float(hi));
}

// bf16 truncation split of a k-adjacent float pair (v.x = even k, v.y = odd k):
// hi = packed top-16-bit truncations (low half = even k), lo = packed bf16 of
// the exact residuals.
__device__ __forceinline__ void bf16pair(float2 v, unsigned& hi, unsigned& lo) {
    unsigned u0 = __float_as_uint(v.x), u1 = __float_as_uint(v.y);
    hi = __byte_perm(u0, u1, 0x7632);
    float l0 = v.x - __uint_as_float(u0 & 0xFFFF0000u);
    float l1 = v.y - __uint_as_float(u1 & 0xFFFF0000u);
    asm("cvt.rn.bf16x2.f32 %0, %1, %2;" : "=r"(lo) : "f"(l1), "f"(l0));
}

__device__ __forceinline__ void cp_async16(unsigned smem_addr, const void* gptr) {
    asm volatile("cp.async.cg.shared.global [%0], [%1], 16;\n"
                 :: "r"(smem_addr), "l"(gptr));
}

__device__ __forceinline__ void mma_tf32(float* c,
                                         unsigned a0, unsigned a1, unsigned a2, unsigned a3,
                                         unsigned b0, unsigned b1) {
    asm volatile("mma.sync.aligned.m16n8k8.row.col.f32.tf32.tf32.f32 "
                 "{%0,%1,%2,%3}, {%4,%5,%6,%7}, {%8,%9}, {%0,%1,%2,%3};"
                 : "+f"(c[0]), "+f"(c[1]), "+f"(c[2]), "+f"(c[3])
                 : "r"(a0), "r"(a1), "r"(a2), "r"(a3), "r"(b0), "r"(b1));
}

__device__ __forceinline__ void mma_bf16(float* c, const unsigned* a,
                                         unsigned b0, unsigned b1) {
    asm volatile("mma.sync.aligned.m16n8k16.row.col.f32.bf16.bf16.f32 "
                 "{%0,%1,%2,%3}, {%4,%5,%6,%7}, {%8,%9}, {%0,%1,%2,%3};"
                 : "+f"(c[0]), "+f"(c[1]), "+f"(c[2]), "+f"(c[3])
                 : "r"(a[0]), "r"(a[1]), "r"(a[2]), "r"(a[3]), "r"(b0), "r"(b1));
}

// ---------------- one-shot weight pre-split into packed bf16 hi/lo pairs -------
// Pair p = [kpair][n] within each weight; src elements (2*kpair)*128+n and +128.
__global__ void split_wp_kernel(const float* __restrict__ w0, const float* __restrict__ w1,
                                const float* __restrict__ w2, const float* __restrict__ w3,
                                const float* __restrict__ w4, const float* __restrict__ w5,
                                const float* __restrict__ w6, const float* __restrict__ w7,
                                const float* __restrict__ w8, const float* __restrict__ w9,
                                unsigned* __restrict__ hi, unsigned* __restrict__ lo) {
    int p = blockIdx.x * 256 + threadIdx.x;
    const float* w;
    int q;
    if      (p < P_INW2) { w = w0; q = p; }
    else if (p < P_WQ)   { w = w1; q = p - P_INW2; }
    else if (p < P_WK)   { w = w2; q = p - P_WQ; }
    else if (p < P_WV)   { w = w3; q = p - P_WK; }
    else if (p < P_WO)   { w = w4; q = p - P_WV; }
    else if (p < P_FW1)  { w = w5; q = p - P_WO; }
    else if (p < P_FW2)  { w = w6; q = p - P_FW1; }
    else if (p < P_PWK)  { w = w7; q = p - P_FW2; }
    else if (p < P_PWV)  { w = w8; q = p - P_PWK; }
    else                 { w = w9; q = p - P_PWV; }
    int e0 = (q >> 7) * 256 + (q & 127);
    float2 v = make_float2(w[e0], w[e0 + 128]);
    unsigned h, l;
    bf16pair(v, h, l);
    hi[p] = h;
    lo[p] = l;
}

// ---------------- gather edge features ----------------
__global__ void gather_feat_kernel(const float* __restrict__ x,
                                   const float* __restrict__ ea,
                                   const int* __restrict__ ei,
                                   float* __restrict__ feat) {
    int e = blockIdx.x;
    int c = threadIdx.x;            // 160 threads
    int s = ei[e];
    int d = ei[E_TOT + e];
    float val;
    if (c < 64)       val = x[(size_t)s * NODE_DIM + c];
    else if (c < 128) val = x[(size_t)d * NODE_DIM + (c - 64)];
    else              val = ea[(size_t)e * EDGE_DIM + (c - 128)];
    feat[(size_t)e * FEAT_DIM + c] = val;
}

// ---------------- adjacency bitmask (edges sharing a node) ----------------
__global__ void build_mask_kernel(const int* __restrict__ ei,
                                  unsigned* __restrict__ mask) {
    int b = blockIdx.x;
    __shared__ int ss[EPG];
    __shared__ int dd[EPG];
    for (int i = threadIdx.x; i < EPG; i += blockDim.x) {
        ss[i] = ei[b * EPG + i];
        dd[i] = ei[E_TOT + b * EPG + i];
    }
    __syncthreads();
    for (int i = threadIdx.x; i < EPG; i += blockDim.x) {
        int si = ss[i], di = dd[i];
        for (int w = 0; w < 16; w++) {
            unsigned bits = 0;
            #pragma unroll
            for (int jj = 0; jj < 32; jj++) {
                int j = (w << 5) + jj;
                int sj = ss[j], dj = dd[j];
                bool adj = (si == sj) | (si == dj) | (di == sj) | (di == dj) | (i == j);
                bits |= (unsigned)adj << jj;
            }
            mask[((size_t)b * EPG + i) * 16 + w] = bits;
        }
    }
}

// ---------------- 3-term bf16 tensor-core GEMM, optional fused res+LN ----------
// C = Ah*Bh + Ah*Bl + Al*Bh with truncation splits (~16-17 effective mantissa
// bits). W pre-split+packed in global (bf16x2 k-pairs). A staged raw fp32 via
// cp.async, split+packed in registers. 128x128 tile, BK=32 (2 k16 chunks/stage),
// 256 threads (4m x 2n warps), double-buffered. grid.y selects W/C.
// res != nullptr: res = LN(res + A@W + bias) in place (full row per CTA).
__global__ void __launch_bounds__(256, 2)
gemm_bf16_kernel(const float* __restrict__ A,
                 const unsigned* __restrict__ Whi0, const unsigned* __restrict__ Whi1,
                 const unsigned* __restrict__ Whi2,
                 const unsigned* __restrict__ Wlo0, const unsigned* __restrict__ Wlo1,
                 const unsigned* __restrict__ Wlo2,
                 float* __restrict__ C0, float* __restrict__ C1, float* __restrict__ C2,
                 const float* __restrict__ bias, int K, int relu,
                 const float* __restrict__ ln_g, const float* __restrict__ ln_b,
                 float* __restrict__ res) {
    const unsigned* WH = (blockIdx.y == 0) ? Whi0 : (blockIdx.y == 1 ? Whi1 : Whi2);
    const unsigned* WL = (blockIdx.y == 0) ? Wlo0 : (blockIdx.y == 1 ? Wlo1 : Wlo2);
    float* C           = (blockIdx.y == 0) ? C0   : (blockIdx.y == 1 ? C1   : C2);

    extern __shared__ float sm[];
    float* Abuf[2] = { sm, sm + 128 * ASTRIDE };
    unsigned* BHbuf[2] = { (unsigned*)(sm + 2 * 128 * ASTRIDE),
                           (unsigned*)(sm + 2 * 128 * ASTRIDE) + 16 * BSTRIDE };
    unsigned* BLbuf[2] = { (unsigned*)(sm + 2 * 128 * ASTRIDE) + 2 * 16 * BSTRIDE,
                           (unsigned*)(sm + 2 * 128 * ASTRIDE) + 3 * 16 * BSTRIDE };

    const int tid = threadIdx.x;
    const int lane = tid & 31;
    const int wid = tid >> 5;
    const int wm = wid >> 1;
    const int wn = wid & 1;
    const int g = lane >> 2;
    const int t = lane & 3;
    const int bm = blockIdx.x * 128;

    float acc[2][8][4];
    #pragma unroll
    for (int i = 0; i < 2; i++)
        #pragma unroll
        for (int j = 0; j < 8; j++)
            #pragma unroll
            for (int r = 0; r < 4; r++) acc[i][j][r] = 0.f;

    const int nst = K >> 5;   // BK = 32 (K = 128 or 160)

    const int a_c4 = tid & 7;
    const int b_n4 = tid & 31;
    const unsigned sA[2]  = { (unsigned)__cvta_generic_to_shared(Abuf[0]),
                              (unsigned)__cvta_generic_to_shared(Abuf[1]) };
    const unsigned sBH[2] = { (unsigned)__cvta_generic_to_shared(BHbuf[0]),
                              (unsigned)__cvta_generic_to_shared(BHbuf[1]) };
    const unsigned sBL[2] = { (unsigned)__cvta_generic_to_shared(BLbuf[0]),
                              (unsigned)__cvta_generic_to_shared(BLbuf[1]) };

    auto load_stage = [&](int buf, int s) {
        const int k0 = s * 32;
        #pragma unroll
        for (int u = 0; u < 4; u++) {
            int rA = (tid >> 3) + 32 * u;
            cp_async16(sA[buf] + (unsigned)((rA * ASTRIDE + a_c4 * 4) << 2),
                       A + (size_t)(bm + rA) * K + k0 + a_c4 * 4);
        }
        // B: 16 k-pairs x 128 cols packed; 512 uint4 per half -> 2 per thread
        #pragma unroll
        for (int u = 0; u < 2; u++) {
            int id = tid + 256 * u;
            int rp = id >> 5, n4 = id & 31;
            unsigned boff = (unsigned)((rp * BSTRIDE + n4 * 4) << 2);
            const size_t gw = (size_t)(s * 16 + rp) * 128 + n4 * 4;
            cp_async16(sBH[buf] + boff, WH + gw);
            cp_async16(sBL[buf] + boff, WL + gw);
        }
        asm volatile("cp.async.commit_group;\n" ::: "memory");
    };

    load_stage(0, 0);
    if (nst > 1) load_stage(1, 1);

    for (int s = 0; s < nst; s++) {
        if (s + 1 < nst)
            asm volatile("cp.async.wait_group 1;\n" ::: "memory");
        else
            asm volatile("cp.async.wait_group 0;\n" ::: "memory");
        __syncthreads();

        const float* As = Abuf[s & 1];
        const unsigned* BsH = BHbuf[s & 1];
        const unsigned* BsL = BLbuf[s & 1];

        #pragma unroll
        for (int c = 0; c < 2; c++) {        // two k16 chunks per stage
            const int koff = c * 16;
            unsigned ah[2][4], al[2][4];
            #pragma unroll
            for (int mi = 0; mi < 2; mi++) {
                int m0 = wm * 32 + mi * 16;
                const float* p0 = As + (m0 + g) * ASTRIDE + koff + 2 * t;
                const float* p1 = As + (m0 + g + 8) * ASTRIDE + koff + 2 * t;
                bf16pair(*(const float2*)(p0),     ah[mi][0], al[mi][0]);
                bf16pair(*(const float2*)(p1),     ah[mi][1], al[mi][1]);
                bf16pair(*(const float2*)(p0 + 8), ah[mi][2], al[mi][2]);
                bf16pair(*(const float2*)(p1 + 8), ah[mi][3], al[mi][3]);
            }
            #pragma unroll
            for (int nj = 0; nj < 8; nj++) {
                int n0 = wn * 64 + nj * 8;
                unsigned bh0 = BsH[(c * 8 + t) * BSTRIDE + n0 + g];
                unsigned bh1 = BsH[(c * 8 + t + 4) * BSTRIDE + n0 + g];
                unsigned bl0 = BsL[(c * 8 + t) * BSTRIDE + n0 + g];
                unsigned bl1 = BsL[(c * 8 + t + 4) * BSTRIDE + n0 + g];
                #pragma unroll
                for (int mi = 0; mi < 2; mi++) {
                    float* cc = acc[mi][nj];
                    mma_bf16(cc, ah[mi], bl0, bl1);
                    mma_bf16(cc, al[mi], bh0, bh1);
                    mma_bf16(cc, ah[mi], bh0, bh1);
                }
            }
        }
        __syncthreads();
        if (s + 2 < nst) load_stage(s & 1, s + 2);
    }

    if (res != nullptr) {
        // -------- fused residual + LayerNorm epilogue (writes res in place) ------
        float* sb = sm;   // safe: all warps passed final __syncthreads() above
        float rs[2][2], rq[2][2];
        #pragma unroll
        for (int i = 0; i < 2; i++) {
            int row0 = bm + wm * 32 + i * 16 + g;
            float s0 = 0.f, s1 = 0.f, q0 = 0.f, q1 = 0.f;
            #pragma unroll
            for (int j = 0; j < 8; j++) {
                int col = wn * 64 + j * 8 + t * 2;
                float bv0 = bias ? bias[col] : 0.f;
                float bv1 = bias ? bias[col + 1] : 0.f;
                float2 r0 = *(const float2*)&res[(size_t)row0 * 128 + col];
                float2 r1 = *(const float2*)&res[(size_t)(row0 + 8) * 128 + col];
                float v0 = acc[i][j][0] + bv0 + r0.x;
                float v1 = acc[i][j][1] + bv1 + r0.y;
                float v2 = acc[i][j][2] + bv0 + r1.x;
                float v3 = acc[i][j][3] + bv1 + r1.y;
                acc[i][j][0] = v0; acc[i][j][1] = v1;
                acc[i][j][2] = v2; acc[i][j][3] = v3;
                s0 += v0 + v1; q0 += v0 * v0 + v1 * v1;
                s1 += v2 + v3; q1 += v2 * v2 + v3 * v3;
            }
            #pragma unroll
            for (int off = 1; off < 4; off <<= 1) {
                s0 += __shfl_xor_sync(0xFFFFFFFFu, s0, off);
                q0 += __shfl_xor_sync(0xFFFFFFFFu, q0, off);
                s1 += __shfl_xor_sync(0xFFFFFFFFu, s1, off);
                q1 += __shfl_xor_sync(0xFFFFFFFFu, q1, off);
            }
            rs[i][0] = s0; rq[i][0] = q0; rs[i][1] = s1; rq[i][1] = q1;
        }
        if (t == 0) {
            #pragma unroll
            for (int i = 0; i < 2; i++) {
                int rl = wm * 32 + i * 16 + g;
                *(float2*)&sb[(wn * 128 + rl) * 2] = make_float2(rs[i][0], rq[i][0]);
                *(float2*)&sb[(wn * 128 + rl + 8) * 2] = make_float2(rs[i][1], rq[i][1]);
            }
        }
        __syncthreads();
        #pragma unroll
        for (int i = 0; i < 2; i++) {
            int rl = wm * 32 + i * 16 + g;
            #pragma unroll
            for (int rh = 0; rh < 2; rh++) {
                float2 p0 = *(float2*)&sb[(rl + rh * 8) * 2];
                float2 p1 = *(float2*)&sb[(128 + rl + rh * 8) * 2];
                float S = p0.x + p1.x, Q = p0.y + p1.y;
                float mean = S * (1.f / 128.f);
                float var = Q * (1.f / 128.f) - mean * mean;
                float inv = rsqrtf(var + 1e-5f);
                int row = bm + rl + rh * 8;
                #pragma unroll
                for (int j = 0; j < 8; j++) {
                    int col = wn * 64 + j * 8 + t * 2;
                    float v0 = acc[i][j][rh * 2 + 0];
                    float v1 = acc[i][j][rh * 2 + 1];
                    *(float2*)&res[(size_t)row * 128 + col] = make_float2(
                        (v0 - mean) * inv * ln_g[col] + ln_b[col],
                        (v1 - mean) * inv * ln_g[col + 1] + ln_b[col + 1]);
                }
            }
        }
        return;
    }

    // -------- plain epilogue --------
    #pragma unroll
    for (int i = 0; i < 2; i++) {
        int row0 = bm + wm * 32 + i * 16 + g;
        #pragma unroll
        for (int j = 0; j < 8; j++) {
            int col = wn * 64 + j * 8 + t * 2;
            float bv0 = bias ? bias[col] : 0.f;
            float bv1 = bias ? bias[col + 1] : 0.f;
            float v0 = acc[i][j][0] + bv0, v1 = acc[i][j][1] + bv1;
            float v2 = acc[i][j][2] + bv0, v3 = acc[i][j][3] + bv1;
            if (relu) {
                v0 = fmaxf(v0, 0.f); v1 = fmaxf(v1, 0.f);
                v2 = fmaxf(v2, 0.f); v3 = fmaxf(v3, 0.f);
            }
            *(float2*)&C[(size_t)row0 * 128 + col] = make_float2(v0, v1);
            *(float2*)&C[(size_t)(row0 + 8) * 128 + col] = make_float2(v2, v3);
        }
    }
}

// ---------------- dense (S-layer) attention on tensor cores (tf32, unchanged) ----
__global__ void __launch_bounds__(256, 1)
dense_attn_tc_kernel(const float* __restrict__ q, const float* __restrict__ k,
                     const float* __restrict__ v, float* __restrict__ o) {
    extern __shared__ float sm[];
    float* Ks = sm;                      // [512][KSTR]
    float* Vs = Ks + 512 * KSTR;         // [512][VSTR]
    float* Ps = Vs + 512 * VSTR;         // [8][64][PSTR]
    const int b = blockIdx.x >> 3, h = blockIdx.x & 7;
    const int base = b * EPG;
    const int tid = threadIdx.x, lane = tid & 31, wid = tid >> 5;
    const int g = lane >> 2, t = lane & 3;
    float* Pw = Ps + wid * 64 * PSTR;

    for (int i = tid; i < 2048; i += 256) {
        int r = i >> 2, c4 = (i & 3) * 4;
        float4 kv = *(const float4*)(k + (size_t)(base + r) * HID + h * DH + c4);
        float4 vv = *(const float4*)(v + (size_t)(base + r) * HID + h * DH + c4);
        Ks[r * KSTR + c4 + 0] = kv.x; Ks[r * KSTR + c4 + 1] = kv.y;
        Ks[r * KSTR + c4 + 2] = kv.z; Ks[r * KSTR + c4 + 3] = kv.w;
        Vs[r * VSTR + c4 + 0] = vv.x; Vs[r * VSTR + c4 + 1] = vv.y;
        Vs[r * VSTR + c4 + 2] = vv.z; Vs[r * VSTR + c4 + 3] = vv.w;
    }

    unsigned qh[4][2][4], ql[4][2][4];
    #pragma unroll
    for (int mi = 0; mi < 4; mi++) {
        const size_t r0 = (size_t)(base + wid * 64 + mi * 16 + g) * HID + h * DH;
        const size_t r1 = r0 + (size_t)8 * HID;
        #pragma unroll
        for (int ko = 0; ko < 2; ko++) {
            split_tf32(q[r0 + ko * 8 + t],     qh[mi][ko][0], ql[mi][ko][0]);
            split_tf32(q[r1 + ko * 8 + t],     qh[mi][ko][1], ql[mi][ko][1]);
            split_tf32(q[r0 + ko * 8 + t + 4], qh[mi][ko][2], ql[mi][ko][2]);
            split_tf32(q[r1 + ko * 8 + t + 4], qh[mi][ko][3], ql[mi][ko][3]);
        }
    }
    __syncthreads();

    float oacc[4][2][4] = {};
    float lrow[8] = {};

    for (int kc = 0; kc < 16; kc++) {
        const int j0 = kc * 32;
        float sacc[4][4][4] = {};
        #pragma unroll
        for (int ko = 0; ko < 2; ko++) {
            #pragma unroll
            for (int nj = 0; nj < 4; nj++) {
                const float* kp = Ks + (j0 + nj * 8 + g) * KSTR + ko * 8 + t;
                unsigned bh0, bl0, bh1, bl1;
                split_tf32(kp[0], bh0, bl0);
                split_tf32(kp[4], bh1, bl1);
                #pragma unroll
                for (int mi = 0; mi < 4; mi++) {
                    float* cc = sacc[mi][nj];
                    mma_tf32(cc, qh[mi][ko][0], qh[mi][ko][1], qh[mi][ko][2], qh[mi][ko][3], bl0, bl1);
                    mma_tf32(cc, ql[mi][ko][0], ql[mi][ko][1], ql[mi][ko][2], ql[mi][ko][3], bh0, bh1);
                    mma_tf32(cc, qh[mi][ko][0], qh[mi][ko][1], qh[mi][ko][2], qh[mi][ko][3], bh0, bh1);
                }
            }
        }
        #pragma unroll
        for (int mi = 0; mi < 4; mi++) {
            #pragma unroll
            for (int nj = 0; nj < 4; nj++) {
                float p0 = __uint_as_float(f2tf32u(__expf(sacc[mi][nj][0] * 0.25f)));
                float p1 = __uint_as_float(f2tf32u(__expf(sacc[mi][nj][1] * 0.25f)));
                float p2 = __uint_as_float(f2tf32u(__expf(sacc[mi][nj][2] * 0.25f)));
                float p3 = __uint_as_float(f2tf32u(__expf(sacc[mi][nj][3] * 0.25f)));
                lrow[mi * 2 + 0] += p0 + p1;
                lrow[mi * 2 + 1] += p2 + p3;
                *(float2*)(Pw + (mi * 16 + g) * PSTR + nj * 8 + 2 * t) = make_float2(p0, p1);
                *(float2*)(Pw + (mi * 16 + g + 8) * PSTR + nj * 8 + 2 * t) = make_float2(p2, p3);
            }
        }
        __syncwarp();
        #pragma unroll
        for (int k2 = 0; k2 < 4; k2++) {
            unsigned pa[4][4];
            #pragma unroll
            for (int mi = 0; mi < 4; mi++) {
                const float* p0 = Pw + (mi * 16 + g) * PSTR + k2 * 8 + t;
                const float* p1 = Pw + (mi * 16 + g + 8) * PSTR + k2 * 8 + t;
                pa[mi][0] = __float_as_uint(p0[0]);
                pa[mi][1] = __float_as_uint(p1[0]);
                pa[mi][2] = __float_as_uint(p0[4]);
                pa[mi][3] = __float_as_uint(p1[4]);
            }
            #pragma unroll
            for (int nd = 0; nd < 2; nd++) {
                unsigned vb0 = f2tf32u(Vs[(j0 + k2 * 8 + t) * VSTR + nd * 8 + g]);
                unsigned vb1 = f2tf32u(Vs[(j0 + k2 * 8 + t + 4) * VSTR + nd * 8 + g]);
                #pragma unroll
                for (int mi = 0; mi < 4; mi++)
                    mma_tf32(oacc[mi][nd], pa[mi][0], pa[mi][1], pa[mi][2], pa[mi][3], vb0, vb1);
            }
        }
        __syncwarp();
    }

    #pragma unroll
    for (int i = 0; i < 8; i++) {
        lrow[i] += __shfl_xor_sync(0xFFFFFFFFu, lrow[i], 1);
        lrow[i] += __shfl_xor_sync(0xFFFFFFFFu, lrow[i], 2);
    }
    #pragma unroll
    for (int mi = 0; mi < 4; mi++) {
        float inv0 = 1.f / lrow[mi * 2 + 0];
        float inv1 = 1.f / lrow[mi * 2 + 1];
        size_t r0 = (size_t)(base + wid * 64 + mi * 16 + g) * HID + h * DH;
        size_t r1 = r0 + (size_t)8 * HID;
        #pragma unroll
        for (int nd = 0; nd < 2; nd++) {
            *(float2*)(o + r0 + nd * 8 + 2 * t) =
                make_float2(oacc[mi][nd][0] * inv0, oacc[mi][nd][1] * inv0);
            *(float2*)(o + r1 + nd * 8 + 2 * t) =
                make_float2(oacc[mi][nd][2] * inv1, oacc[mi][nd][3] * inv1);
        }
    }
}

// ---------------- small SGEMM (M=64 pool path) ----------------
__global__ void gemm_kernel(const float* __restrict__ A,
                            const float* __restrict__ W,
                            const float* __restrict__ bias,
                            float* __restrict__ C,
                            int K, int relu) {
    __shared__ __align__(16) float As[16][68];
    __shared__ __align__(16) float Ws[16][68];
    int bm = blockIdx.y * 64;
    int bn = blockIdx.x * 64;
    int tid = threadIdx.x;
    int tx = tid & 15;
    int ty = tid >> 4;
    float acc[4][4] = {};

    for (int k0 = 0; k0 < K; k0 += 16) {
        #pragma unroll
        for (int i = tid; i < 1024; i += 256) {
            int r = i >> 4, c = i & 15;
            As[c][r] = A[(size_t)(bm + r) * K + k0 + c];
        }
        #pragma unroll
        for (int i = tid; i < 1024; i += 256) {
            int r = i >> 6, c = i & 63;
            Ws[r][c] = W[(size_t)(k0 + r) * 128 + bn + c];
        }
        __syncthreads();
        #pragma unroll
        for (int kk = 0; kk < 16; kk++) {
            float4 av = *(const float4*)&As[kk][ty * 4];
            float4 wv = *(const float4*)&Ws[kk][tx * 4];
            float a[4] = {av.x, av.y, av.z, av.w};
            float w[4] = {wv.x, wv.y, wv.z, wv.w};
            #pragma unroll
            for (int i = 0; i < 4; i++)
                #pragma unroll
                for (int j = 0; j < 4; j++)
                    acc[i][j] += a[i] * w[j];
        }
        __syncthreads();
    }
    #pragma unroll
    for (int i = 0; i < 4; i++) {
        int row = bm + ty * 4 + i;
        float4 out;
        float* po = (float*)&out;
        #pragma unroll
        for (int j = 0; j < 4; j++) {
            int col = bn + tx * 4 + j;
            float vv = acc[i][j] + (bias ? bias[col] : 0.f);
            if (relu) vv = fmaxf(vv, 0.f);
            po[j] = vv;
        }
        *(float4*)&C[(size_t)row * 128 + bn + tx * 4] = out;
    }
}

// ---------------- masked multi-head attention (M layers) ----------------
__global__ void attn_kernel(const float* __restrict__ q, const float* __restrict__ k,
                            const float* __restrict__ v, float* __restrict__ o,
                            const unsigned* __restrict__ mask) {
    extern __shared__ float4 sm4[];
    float4* kd = sm4;           // 2048 float4
    float4* vd = sm4 + 2048;
    int b = blockIdx.x >> 3;
    int h = blockIdx.x & 7;
    int base = b * EPG;
    const float* kp = k + (size_t)base * HID + h * DH;
    const float* vp = v + (size_t)base * HID + h * DH;
    for (int i = threadIdx.x; i < 2048; i += 256) {
        int r = i >> 2, c = i & 3;
        kd[i] = *(const float4*)(kp + (size_t)r * HID + c * 4);
        vd[i] = *(const float4*)(vp + (size_t)r * HID + c * 4);
    }
    __syncthreads();

    #pragma unroll
    for (int rr = 0; rr < 2; rr++) {
        int i = threadIdx.x + rr * 256;
        const float* qp = q + (size_t)(base + i) * HID + h * DH;
        float4 q0 = *(const float4*)(qp + 0);
        float4 q1 = *(const float4*)(qp + 4);
        float4 q2 = *(const float4*)(qp + 8);
        float4 q3 = *(const float4*)(qp + 12);

        float l = 0.f;
        float4 a0 = {0,0,0,0}, a1 = {0,0,0,0}, a2 = {0,0,0,0}, a3 = {0,0,0,0};

        const unsigned* mp = mask + (size_t)(base + i) * 16;
        #pragma unroll
        for (int w = 0; w < 16; w++) {
            unsigned bits = mp[w];
            while (bits) {
                int jj = __ffs(bits) - 1;
                bits &= bits - 1;
                int j = (w << 5) + jj;
                const float4 k0 = kd[4*j+0], k1 = kd[4*j+1], k2 = kd[4*j+2], k3 = kd[4*j+3];
                float s = q0.x*k0.x + q0.y*k0.y + q0.z*k0.z + q0.w*k0.w
                        + q1.x*k1.x + q1.y*k1.y + q1.z*k1.z + q1.w*k1.w
                        + q2.x*k2.x + q2.y*k2.y + q2.z*k2.z + q2.w*k2.w
                        + q3.x*k3.x + q3.y*k3.y + q3.z*k3.z + q3.w*k3.w;
                float p = __expf(s * 0.25f);   // 1/sqrt(16)
                l += p;
                const float4 v0 = vd[4*j+0], v1 = vd[4*j+1], v2 = vd[4*j+2], v3 = vd[4*j+3];
                a0.x += p*v0.x; a0.y += p*v0.y; a0.z += p*v0.z; a0.w += p*v0.w;
                a1.x += p*v1.x; a1.y += p*v1.y; a1.z += p*v1.z; a1.w += p*v1.w;
                a2.x += p*v2.x; a2.y += p*v2.y; a2.z += p*v2.z; a2.w += p*v2.w;
                a3.x += p*v3.x; a3.y += p*v3.y; a3.z += p*v3.z; a3.w += p*v3.w;
            }
        }

        float inv = 1.f / l;
        float* op = o + (size_t)(base + i) * HID + h * DH;
        *(float4*)(op + 0)  = make_float4(a0.x*inv, a0.y*inv, a0.z*inv, a0.w*inv);
        *(float4*)(op + 4)  = make_float4(a1.x*inv, a1.y*inv, a1.z*inv, a1.w*inv);
        *(float4*)(op + 8)  = make_float4(a2.x*inv, a2.y*inv, a2.z*inv, a2.w*inv);
        *(float4*)(op + 12) = make_float4(a3.x*inv, a3.y*inv, a3.z*inv, a3.w*inv);
    }
}

// ---------------- pooling: qpool = seed @ p_Wq ----------------
__global__ void qpool_kernel(const float* __restrict__ seed, const float* __restrict__ Wq,
                             float* __restrict__ qpool) {
    int c = threadIdx.x;   // 128
    float s = 0.f;
    for (int kk = 0; kk < HID; kk++) s += seed[kk] * Wq[(size_t)kk * HID + c];
    qpool[c] = s;
}

// ---------------- PMA attention: 1 query per graph, full mask ----------------
__global__ void pool_attn_kernel(const float* __restrict__ qpool, const float* __restrict__ k,
                                 const float* __restrict__ v, float* __restrict__ pool) {
    int b = blockIdx.x;
    int w = threadIdx.x >> 5;     // head
    int lane = threadIdx.x & 31;
    float qr[DH];
    #pragma unroll
    for (int d = 0; d < DH; d++) qr[d] = qpool[w * DH + d];

    float s[16];
    float mloc = -1e30f;
    #pragma unroll
    for (int t = 0; t < 16; t++) {
        int j = lane + t * 32;
        const float* kp = k + (size_t)(b * EPG + j) * HID + w * DH;
        float acc = 0.f;
        #pragma unroll
        for (int d = 0; d < DH; d++) acc += qr[d] * kp[d];
        s[t] = acc * 0.25f;
        mloc = fmaxf(mloc, s[t]);
    }
    #pragma unroll
    for (int off = 16; off > 0; off >>= 1)
        mloc = fmaxf(mloc, __shfl_xor_sync(0xFFFFFFFFu, mloc, off));

    float l = 0.f;
    float acc[DH];
    #pragma unroll
    for (int d = 0; d < DH; d++) acc[d] = 0.f;
    #pragma unroll
    for (int t = 0; t < 16; t++) {
        int j = lane + t * 32;
        float p = __expf(s[t] - mloc);
        l += p;
        const float* vp = v + (size_t)(b * EPG + j) * HID + w * DH;
        #pragma unroll
        for (int d = 0; d < DH; d++) acc[d] += p * vp[d];
    }
    #pragma unroll
    for (int off = 16; off > 0; off >>= 1) {
        l += __shfl_xor_sync(0xFFFFFFFFu, l, off);
        #pragma unroll
        for (int d = 0; d < DH; d++)
            acc[d] += __shfl_xor_sync(0xFFFFFFFFu, acc[d], off);
    }
    if (lane == 0) {
        float inv = 1.f / l;
        #pragma unroll
        for (int d = 0; d < DH; d++)
            pool[(size_t)b * HID + w * DH + d] = acc[d] * inv;
    }
}

// ---------------- final: out[b] = o1[b] . out_W2 + out_b2 ----------------
__global__ void final_kernel(const float* __restrict__ o1, const float* __restrict__ W2,
                             const float* __restrict__ b2, float* __restrict__ out) {
    int b = blockIdx.x;
    int lane = threadIdx.x;
    float s = 0.f;
    #pragma unroll
    for (int i = 0; i < 4; i++) {
        int c = lane + 32 * i;
        s += o1[(size_t)b * HID + c] * W2[c];
    }
    #pragma unroll
    for (int off = 16; off > 0; off >>= 1)
        s += __shfl_xor_sync(0xFFFFFFFFu, s, off);
    if (lane == 0) out[b] = s + b2[0];
}

// ---------------- host launch ----------------
extern "C" void kernel_launch(void* const* d_in, const int* in_sizes, int n_in,
                              void* d_out, int out_size) {
    const float* x       = (const float*)d_in[0];
    const float* ea      = (const float*)d_in[1];
    const float* in_W1   = (const float*)d_in[2];
    const float* in_b1   = (const float*)d_in[3];
    const float* in_W2   = (const float*)d_in[4];
    const float* in_b2   = (const float*)d_in[5];
    const float* Wq      = (const float*)d_in[6];
    const float* Wk      = (const float*)d_in[7];
    const float* Wv      = (const float*)d_in[8];
    const float* Wo      = (const float*)d_in[9];
    const float* ln1_g   = (const float*)d_in[10];
    const float* ln1_b   = (const float*)d_in[11];
    const float* ln2_g   = (const float*)d_in[12];
    const float* ln2_b   = (const float*)d_in[13];
    const float* f_W1    = (const float*)d_in[14];
    const float* f_b1    = (const float*)d_in[15];
    const float* f_W2    = (const float*)d_in[16];
    const float* f_b2    = (const float*)d_in[17];
    const float* seed    = (const float*)d_in[18];
    const float* p_Wq    = (const float*)d_in[19];
    const float* p_Wk    = (const float*)d_in[20];
    const float* p_Wv    = (const float*)d_in[21];
    const float* p_Wo    = (const float*)d_in[22];
    const float* out_W1  = (const float*)d_in[23];
    const float* out_b1  = (const float*)d_in[24];
    const float* out_W2  = (const float*)d_in[25];
    const float* out_b2  = (const float*)d_in[26];
    const int*   ei      = (const int*)d_in[27];

    float *p_h, *p_q, *p_k, *p_v, *p_a, *p_t, *p_feat, *p_qpool, *p_pool, *p_pool2;
    unsigned *p_wphi, *p_wplo;
    unsigned* p_mask;
    cudaGetSymbolAddress((void**)&p_h, g_h);
    cudaGetSymbolAddress((void**)&p_q, g_q);
    cudaGetSymbolAddress((void**)&p_k, g_k);
    cudaGetSymbolAddress((void**)&p_v, g_v);
    cudaGetSymbolAddress((void**)&p_a, g_a);
    cudaGetSymbolAddress((void**)&p_t, g_t);
    cudaGetSymbolAddress((void**)&p_feat, g_feat);
    cudaGetSymbolAddress((void**)&p_mask, g_mask);
    cudaGetSymbolAddress((void**)&p_wphi, g_wphi);
    cudaGetSymbolAddress((void**)&p_wplo, g_wplo);
    cudaGetSymbolAddress((void**)&p_qpool, g_qpool);
    cudaGetSymbolAddress((void**)&p_pool, g_pool);
    cudaGetSymbolAddress((void**)&p_pool2, g_pool2);

    cudaFuncSetAttribute(attn_kernel, cudaFuncAttributeMaxDynamicSharedMemorySize, 65536);
    cudaFuncSetAttribute(gemm_bf16_kernel, cudaFuncAttributeMaxDynamicSharedMemorySize,
                         SMEM_GEMM_BYTES);
    cudaFuncSetAttribute(dense_attn_tc_kernel, cudaFuncAttributeMaxDynamicSharedMemorySize,
                         SMEM_DATTN);

    const dim3 g1(E_TOT / 128, 1);
    const dim3 g2(E_TOT / 128, 2);
    const dim3 g3(E_TOT / 128, 3);
    dim3 gSmall(2, 1);

    // weight pre-split + inputs
    split_wp_kernel<<<W_PAIRS / 256, 256>>>(in_W1, in_W2, Wq, Wk, Wv, Wo,
                                            f_W1, f_W2, p_Wk, p_Wv, p_wphi, p_wplo);
    gather_feat_kernel<<<E_TOT, FEAT_DIM>>>(x, ea, ei, p_feat);
    build_mask_kernel<<<B, 256>>>(ei, p_mask);

    #define GEMM1(Ap, OFF, Cp, bias, K, relu) \
        gemm_bf16_kernel<<<g1, 256, SMEM_GEMM_BYTES>>>(Ap, \
            p_wphi + (OFF), p_wphi + (OFF), p_wphi + (OFF), \
            p_wplo + (OFF), p_wplo + (OFF), p_wplo + (OFF), \
            Cp, Cp, Cp, bias, K, relu, nullptr, nullptr, nullptr)

    #define GEMM1_LN(Ap, OFF, bias, lng, lnb, resp) \
        gemm_bf16_kernel<<<g1, 256, SMEM_GEMM_BYTES>>>(Ap, \
            p_wphi + (OFF), p_wphi + (OFF), p_wphi + (OFF), \
            p_wplo + (OFF), p_wplo + (OFF), p_wplo + (OFF), \
            nullptr, nullptr, nullptr, bias, HID, 0, lng, lnb, resp)

    // input MLP
    GEMM1(p_feat, P_INW1, p_t, in_b1, FEAT_DIM, 1);
    GEMM1(p_t, P_INW2, p_h, in_b2, HID, 0);

    // transformer layers: M, M, S
    for (int L = 0; L < 3; L++) {
        const size_t wo = (size_t)L * LAYER_PSTRIDE;
        gemm_bf16_kernel<<<g3, 256, SMEM_GEMM_BYTES>>>(p_h,
            p_wphi + P_WQ + wo, p_wphi + P_WK + wo, p_wphi + P_WV + wo,
            p_wplo + P_WQ + wo, p_wplo + P_WK + wo, p_wplo + P_WV + wo,
            p_q, p_k, p_v, nullptr, HID, 0, nullptr, nullptr, nullptr);
        if (L < 2)
            attn_kernel<<<B * HEADS, 256, 65536>>>(p_q, p_k, p_v, p_a, p_mask);
        else
            dense_attn_tc_kernel<<<B * HEADS, 256, SMEM_DATTN>>>(p_q, p_k, p_v, p_a);
        // h = LN(h + a@Wo) fused
        GEMM1_LN(p_a, P_WO + wo, nullptr, ln1_g + L * HID, ln1_b + L * HID, p_h);
        // t = relu(h@W1 + b1)
        GEMM1(p_h, P_FW1 + wo, p_t, f_b1 + L * HID, HID, 1);
        // h = LN(h + t@W2 + b2) fused
        GEMM1_LN(p_t, P_FW2 + wo, f_b2 + L * HID, ln2_g + L * HID, ln2_b + L * HID, p_h);
    }

    // PMA pooling (fused K/V projection)
    gemm_bf16_kernel<<<g2, 256, SMEM_GEMM_BYTES>>>(p_h,
        p_wphi + P_PWK, p_wphi + P_PWV, p_wphi + P_PWV,
        p_wplo + P_PWK, p_wplo + P_PWV, p_wplo + P_PWV,
        p_k, p_v, p_v, nullptr, HID, 0, nullptr, nullptr, nullptr);
    qpool_kernel<<<1, HID>>>(seed, p_Wq, p_qpool);
    pool_attn_kernel<<<B, 256>>>(p_qpool, p_k, p_v, p_pool);
    gemm_kernel<<<gSmall, 256>>>(p_pool, p_Wo, nullptr, p_pool2, HID, 0);

    // output MLP
    gemm_kernel<<<gSmall, 256>>>(p_pool2, out_W1, out_b1, p_pool, HID, 1);
    final_kernel<<<B, 32>>>(p_pool, out_W2, out_b2, (float*)d_out);
    #undef GEMM1
    #undef GEMM1_LN
}